// round 10
// baseline (speedup 1.0000x reference)
#include <cuda_runtime.h>
#include <cuda_bf16.h>
#include <cstdint>

#define BATCH 128
#define NN    512
#define KNB   16
#define BN    (BATCH*NN)
#define NEGS  0.01f

// ---------------- scratch (device globals; no allocation allowed) -------------
__device__ float g_xx[BN*5];
__device__ float g_x1[BN*64];
__device__ float g_x2[BN*64];
__device__ int   g_idx[BN*KNB];
__device__ float g_A[(size_t)BN*128];
__device__ float g_C[(size_t)BN*128];
__device__ float g_pool[BATCH*256];
__device__ float g_sq[BN];
__device__ float g_sq5[BN];
__device__ float g_hs[(size_t)BN*512];  // lin1 -> lin2 buffer

// W^T A-operand fragment tables for edge kernels (indexed (mt*8+kb)*32+lane)
__device__ uint4 g_w1Ah[1024], g_w1Al[1024];   // conv1 W2 (64x64), tf32 split
__device__ uint4 g_w2Ah[1024], g_w2Al[1024];   // conv2 W2 (128x64), bf16 split
// bf16 split fragment-packed B-operand weights for lin kernels
__device__ uint4  g_wl1pb[9*64*32];      // 144x512 (rows >=133 zero)
__device__ uint4  g_wl2pb[32*32*32];     // 512x256

__device__ __forceinline__ float leaky(float v){ return v > 0.f ? v : NEGS*v; }

__device__ __forceinline__ void atomicMaxFloat(float* addr, float value){
    if (value >= 0.f) atomicMax((int*)addr, __float_as_int(value));
    else              atomicMin((unsigned int*)addr, __float_as_uint(value));
}

__device__ __forceinline__ unsigned f2tf(float x){
    unsigned u; asm("cvt.rna.tf32.f32 %0, %1;" : "=r"(u) : "f"(x)); return u;
}
__device__ __forceinline__ void splt(float x, unsigned &h, unsigned &l){
    h = f2tf(x);
    l = f2tf(x - __uint_as_float(h));
}
__device__ __forceinline__ void mma8(float* c, const unsigned* a, const unsigned* b){
    asm("mma.sync.aligned.m16n8k8.row.col.f32.tf32.tf32.f32 "
        "{%0,%1,%2,%3}, {%4,%5,%6,%7}, {%8,%9}, {%0,%1,%2,%3};"
        : "+f"(c[0]), "+f"(c[1]), "+f"(c[2]), "+f"(c[3])
        : "r"(a[0]), "r"(a[1]), "r"(a[2]), "r"(a[3]), "r"(b[0]), "r"(b[1]));
}
__device__ __forceinline__ void mma16(float* c, const unsigned* a, const unsigned* b){
    asm("mma.sync.aligned.m16n8k16.row.col.f32.bf16.bf16.f32 "
        "{%0,%1,%2,%3}, {%4,%5,%6,%7}, {%8,%9}, {%0,%1,%2,%3};"
        : "+f"(c[0]), "+f"(c[1]), "+f"(c[2]), "+f"(c[3])
        : "r"(a[0]), "r"(a[1]), "r"(a[2]), "r"(a[3]), "r"(b[0]), "r"(b[1]));
}
__device__ __forceinline__ unsigned packbf(float v0, float v1){
    unsigned d; asm("cvt.rn.bf16x2.f32 %0, %1, %2;" : "=r"(d) : "f"(v1), "f"(v0)); return d;
}
__device__ __forceinline__ float bflo(unsigned p){ return __uint_as_float(p << 16); }
__device__ __forceinline__ float bfhi(unsigned p){ return __uint_as_float(p & 0xffff0000u); }
__device__ __forceinline__ void split2(float v0, float v1, unsigned &h, unsigned &l){
    h = packbf(v0, v1);
    l = packbf(v0 - bflo(h), v1 - bfhi(h));
}

// sortable-u32 transform
__device__ __forceinline__ unsigned fsort(float f){
    unsigned b = __float_as_uint(f);
    return b ^ (((int)b >> 31) | 0x80000000u);
}

// index mappings for sel16 slot u on lane:
// MODE 0: j = u*32 + lane        (knn5)
// MODE 2: j = (u>>2)*128 + lane*4 + (u&3)   (fused d2+select chunks)
template<int MODE>
__device__ __forceinline__ int sel_j(int lane, int u){
    if (MODE == 0) return u*32 + lane;
    return (u >> 2)*128 + lane*4 + (u & 3);
}
template<int MODE>
__device__ __forceinline__ int sel_u(int j){
    if (MODE == 0) return j >> 5;
    return ((j >> 7) << 2) + (j & 3);
}

// warp-cooperative exact top-16-of-512 with lower-index tiebreak.
template<int MODE>
__device__ __forceinline__ void sel16(const float* v, int lane, int* out){
    const unsigned long long INF = ~0ull;
    unsigned long long s0 = INF, s1 = INF, s2 = INF, s3 = INF;
    #pragma unroll
    for (int u = 0; u < 16; u++){
        int j = sel_j<MODE>(lane, u);
        unsigned long long k = ((unsigned long long)fsort(v[u]) << 32) | (unsigned)j;
        if (k < s3){
            s3 = k;
            if (s3 < s2){ unsigned long long t = s2; s2 = s3; s3 = t; }
            if (s2 < s1){ unsigned long long t = s1; s1 = s2; s2 = t; }
            if (s1 < s0){ unsigned long long t = s0; s0 = s1; s1 = t; }
        }
    }
    unsigned mask = 0;
    int mine = 0;
    #pragma unroll 1
    for (int r = 0; r < KNB; r++){
        unsigned long long m = s0;
        #pragma unroll
        for (int off = 16; off; off >>= 1){
            unsigned long long o = __shfl_xor_sync(0xffffffffu, m, off);
            if (o < m) m = o;
        }
        if (lane == r) mine = (int)(unsigned)(m & 0xffffffffu);
        if (s0 == m){
            int j = (int)(unsigned)(m & 0xffffffffu);
            mask |= 1u << sel_u<MODE>(j);
            s0 = s1; s1 = s2; s2 = s3; s3 = INF;
            if (s0 == INF && mask != 0xffffu){
                #pragma unroll
                for (int u2 = 0; u2 < 16; u2++){
                    if (!((mask >> u2) & 1u)){
                        int j2 = sel_j<MODE>(lane, u2);
                        unsigned long long k = ((unsigned long long)fsort(v[u2]) << 32) | (unsigned)j2;
                        if (k < s3){
                            s3 = k;
                            if (s3 < s2){ unsigned long long t = s2; s2 = s3; s3 = t; }
                            if (s2 < s1){ unsigned long long t = s1; s1 = s2; s2 = t; }
                            if (s1 < s0){ unsigned long long t = s0; s0 = s1; s1 = t; }
                        }
                    }
                }
            }
        }
    }
    if (lane < KNB) out[lane] = mine;
}

// ---------------- prep: pool init + pack all weight fragment tables ----------
__global__ void k_prep(const float* __restrict__ w1b, const float* __restrict__ w2b,
                       const float* __restrict__ wl1, const float* __restrict__ wl2){
    int i = blockIdx.x*256 + threadIdx.x;
    if (i < BATCH*256) g_pool[i] = __int_as_float(0xff800000); // -inf

    if (i < 1024){
        int lane = i & 31, tmp = i >> 5;
        int kb = tmp & 7, mt = tmp >> 3;
        int r = lane >> 2, q = lane & 3;
        int R = mt*16 + r, k0 = kb*8 + q;
        uint4 H, L;
        splt(w1b[k0*64 + R],       H.x, L.x);
        splt(w1b[k0*64 + R + 8],   H.y, L.y);
        splt(w1b[(k0+4)*64 + R],   H.z, L.z);
        splt(w1b[(k0+4)*64 + R+8], H.w, L.w);
        g_w1Ah[i] = H; g_w1Al[i] = L;
    } else if (i < 2048){
        int rel = i - 1024;
        int lane = rel & 31, tmp = rel >> 5;
        int kb = tmp & 7, mt = tmp >> 3;
        int r = lane >> 2, q = lane & 3;
        int R = mt*16 + r, c0 = kb*16 + 2*q;
        uint4 H, L;
        split2(w2b[c0*64 + R],       w2b[(c0+1)*64 + R],     H.x, L.x);
        split2(w2b[c0*64 + R + 8],   w2b[(c0+1)*64 + R + 8], H.y, L.y);
        split2(w2b[(c0+8)*64 + R],   w2b[(c0+9)*64 + R],     H.z, L.z);
        split2(w2b[(c0+8)*64 + R+8], w2b[(c0+9)*64 + R + 8], H.w, L.w);
        g_w2Ah[rel] = H; g_w2Al[rel] = L;
    } else if (i < 53248){
        const float* W; uint4* dst; int ncb, ncols, nrows, rel;
        if (i < 20480){ rel = i - 2048;  W = wl1; dst = g_wl1pb; ncb = 64; ncols = 512; nrows = 133; }
        else          { rel = i - 20480; W = wl2; dst = g_wl2pb; ncb = 32; ncols = 256; nrows = 512; }
        int lane = rel & 31, tmp = rel >> 5;
        int cb = tmp % ncb, kb = tmp / ncb;
        int r = lane >> 2, q = lane & 3, col = cb*8 + r;
        int k0 = kb*16 + 2*q;
        float v00 = (k0     < nrows) ? W[(k0    )*ncols + col] : 0.f;
        float v01 = (k0 + 1 < nrows) ? W[(k0 + 1)*ncols + col] : 0.f;
        float v10 = (k0 + 8 < nrows) ? W[(k0 + 8)*ncols + col] : 0.f;
        float v11 = (k0 + 9 < nrows) ? W[(k0 + 9)*ncols + col] : 0.f;
        unsigned h0, l0, h1, l1;
        split2(v00, v01, h0, l0);
        split2(v10, v11, h1, l1);
        dst[rel] = make_uint4(h0, h1, l0, l1);
    }
}

// ---------------- 0) build xx = [tq, x, pos] + 5d norms ----------------------
__global__ void k_build(const float* __restrict__ x, const float* __restrict__ pos,
                        const float* __restrict__ tq){
    int i = blockIdx.x*blockDim.x + threadIdx.x;
    if (i < BN){
        float tv = tq[i], xv = x[i];
        float p0 = pos[i*3+0], p1 = pos[i*3+1], p2 = pos[i*3+2];
        g_xx[i*5+0] = tv;
        g_xx[i*5+1] = xv;
        g_xx[i*5+2] = p0;
        g_xx[i*5+3] = p1;
        g_xx[i*5+4] = p2;
        g_sq5[i] = tv*tv + xv*xv + p0*p0 + p1*p1 + p2*p2;
    }
}

// ---------------- 1a) kNN d=5 ------------------------------------------------
__global__ void k_knn5(){
    __shared__ float tile[128*8];    // c0..4 = feat, c5 = sq, c6..7 pad
    int b  = blockIdx.x >> 6;
    int q0 = (blockIdx.x & 63) * 8;
    int warp = threadIdx.x >> 5, lane = threadIdx.x & 31;
    int qi = q0 + warp;
    int node = b*NN + qi;
    const float* Fb = g_xx + (size_t)b*NN*5;

    float f0, f1, f2, f3, f4;
    { const float* fq = Fb + qi*5; f0=fq[0]; f1=fq[1]; f2=fq[2]; f3=fq[3]; f4=fq[4]; }
    float sqi = g_sq5[node];

    float d2loc[16];
    for (int t4 = 0; t4 < 4; t4++){
        __syncthreads();
        for (int idx = threadIdx.x; idx < 1024; idx += 256){
            int rrow = idx >> 3, c = idx & 7;
            int grow = t4*128 + rrow;
            float v = 0.f;
            if (c < 5)       v = Fb[grow*5 + c];
            else if (c == 5) v = g_sq5[b*NN + grow];
            tile[idx] = v;
        }
        __syncthreads();
        #pragma unroll
        for (int u = 0; u < 4; u++){
            int jj = u*32 + lane;
            const float* tr = &tile[jj*8];
            float4 p  = *(const float4*)tr;
            float2 p2 = *(const float2*)(tr + 4);
            float dot = f0*p.x + f1*p.y + f2*p.z + f3*p.w + f4*p2.x;
            d2loc[t4*4 + u] = sqi + p2.y - 2.f*dot;
        }
    }
    sel16<0>(d2loc, lane, g_idx + (size_t)node*KNB);
}

// ---------------- 1c) kNN d=64: fused d2-GEMM + top-16 select ----------------
// Block = 32-row strip x all 512 cols, 4 chunks of 128. d2 never hits global.
__global__ void k_d2sel(){
    __shared__ float As[32*68];
    __shared__ float Bs[128*68];     // aliased per-chunk by d2 staging (32*132)
    float* d2s = Bs;

    int blk = blockIdx.x;
    int b = blk >> 4;
    int i0 = (blk & 15) * 32;
    const float* Fb = g_x1 + (size_t)b*NN*64;
    int t = threadIdx.x, lane = t & 31, w = t >> 5;
    int wy = w >> 2, wx = w & 3;
    int r = lane >> 2, q = lane & 3;

    for (int i = t; i < 32*16; i += 256){
        int m = i >> 4, kq = (i & 15)*4;
        *(float4*)&As[m*68 + kq] = *(const float4*)(Fb + (i0+m)*64 + kq);
    }

    float v[4][16];
    for (int jc = 0; jc < 4; jc++){
        __syncthreads();
        for (int i = t; i < 128*16; i += 256){
            int m = i >> 4, kq = (i & 15)*4;
            *(float4*)&Bs[m*68 + kq] = *(const float4*)(Fb + (jc*128+m)*64 + kq);
        }
        __syncthreads();

        float acc[4][4];
        #pragma unroll
        for (int nt = 0; nt < 4; nt++)
            #pragma unroll
            for (int i = 0; i < 4; i++) acc[nt][i] = 0.f;

        #pragma unroll
        for (int k0 = 0; k0 < 64; k0 += 8){
            int row = wy*16;
            unsigned ah[4], al[4];
            splt(As[(row+r)*68 + k0 + q],       ah[0], al[0]);
            splt(As[(row+r+8)*68 + k0 + q],     ah[1], al[1]);
            splt(As[(row+r)*68 + k0 + q + 4],   ah[2], al[2]);
            splt(As[(row+r+8)*68 + k0 + q + 4], ah[3], al[3]);
            #pragma unroll
            for (int nt = 0; nt < 4; nt++){
                int col = wx*32 + nt*8;
                unsigned bh[2], bl[2];
                splt(Bs[(col+r)*68 + k0 + q],     bh[0], bl[0]);
                splt(Bs[(col+r)*68 + k0 + q + 4], bh[1], bl[1]);
                mma8(acc[nt], ah, bh);
                mma8(acc[nt], ah, bl);
                mma8(acc[nt], al, bh);
            }
        }
        __syncthreads();   // all Bs reads done before aliasing write

        {
            int rowb = i0 + wy*16;
            float si0 = g_sq[b*NN + rowb + r];
            float si1 = g_sq[b*NN + rowb + r + 8];
            #pragma unroll
            for (int nt = 0; nt < 4; nt++){
                int cl = wx*32 + nt*8 + 2*q;
                int colg = b*NN + jc*128 + cl;
                float sj0 = g_sq[colg], sj1 = g_sq[colg + 1];
                float2 o0, o1;
                o0.x = si0 + sj0 - 2.f*acc[nt][0];
                o0.y = si0 + sj1 - 2.f*acc[nt][1];
                o1.x = si1 + sj0 - 2.f*acc[nt][2];
                o1.y = si1 + sj1 - 2.f*acc[nt][3];
                *(float2*)&d2s[(wy*16 + r)*132 + cl]     = o0;
                *(float2*)&d2s[(wy*16 + r + 8)*132 + cl] = o1;
            }
        }
        __syncthreads();
        // selection harvest: warp w owns rows w*4..w*4+3; lane cols lane*4..+3
        #pragma unroll
        for (int ri = 0; ri < 4; ri++){
            float4 x = *(const float4*)&d2s[(w*4 + ri)*132 + lane*4];
            v[ri][jc*4+0] = x.x; v[ri][jc*4+1] = x.y;
            v[ri][jc*4+2] = x.z; v[ri][jc*4+3] = x.w;
        }
    }

    #pragma unroll
    for (int ri = 0; ri < 4; ri++){
        int node = b*NN + i0 + w*4 + ri;
        sel16<2>(v[ri], lane, g_idx + (size_t)node*KNB);
    }
}

// ---------------- 2a) conv1 layer-1 factorization (d=5, H=64) ----------------
__global__ void k_convA1(const float* __restrict__ W, const float* __restrict__ bias){
    int t = blockIdx.x*blockDim.x + threadIdx.x;
    if (t >= BN*64) return;
    int i = t >> 6, c = t & 63;
    const float* f = g_xx + (size_t)i*5;
    float a = bias[c], cc = 0.f;
    #pragma unroll
    for (int d = 0; d < 5; d++){
        float v  = f[d];
        float wt = W[d*64 + c];
        float wb = W[(5 + d)*64 + c];
        a  += v*(wt - wb);
        cc += v*wb;
    }
    g_A[(size_t)i*64 + c] = a;
    g_C[(size_t)i*64 + c] = cc;
}

// ---------------- 2b) conv2 layer-1 (d=64, H=128) ----------------------------
__global__ void k_convA2(const float* __restrict__ W, const float* __restrict__ bias){
    __shared__ float Wd[32*128];
    __shared__ float Wb[32*128];
    __shared__ float Fs[16*64];
    int t = threadIdx.x;
    int base = blockIdx.x*16;

    for (int idx = t; idx < 1024; idx += 256)
        Fs[idx] = g_x1[(size_t)base*64 + idx];

    int m  = t >> 4;
    int cg = (t & 15)*8;
    float a[8], cc[8];
    float4 bb0 = *(const float4*)(bias + cg);
    float4 bb1 = *(const float4*)(bias + cg + 4);
    a[0]=bb0.x; a[1]=bb0.y; a[2]=bb0.z; a[3]=bb0.w;
    a[4]=bb1.x; a[5]=bb1.y; a[6]=bb1.z; a[7]=bb1.w;
    #pragma unroll
    for (int q = 0; q < 8; q++) cc[q] = 0.f;

    for (int db = 0; db < 64; db += 32){
        __syncthreads();
        for (int idx = t; idx < 4096; idx += 256){
            int d = idx >> 7, c = idx & 127;
            float wt = W[(db + d)*128 + c];
            float wb = W[(64 + db + d)*128 + c];
            Wd[idx] = wt - wb;
            Wb[idx] = wb;
        }
        __syncthreads();
        #pragma unroll 4
        for (int d = 0; d < 32; d++){
            float v = Fs[m*64 + db + d];
            float4 w0 = *(const float4*)&Wd[d*128 + cg];
            float4 w1 = *(const float4*)&Wd[d*128 + cg + 4];
            float4 u0 = *(const float4*)&Wb[d*128 + cg];
            float4 u1 = *(const float4*)&Wb[d*128 + cg + 4];
            a[0] += v*w0.x; a[1] += v*w0.y; a[2] += v*w0.z; a[3] += v*w0.w;
            a[4] += v*w1.x; a[5] += v*w1.y; a[6] += v*w1.z; a[7] += v*w1.w;
            cc[0] += v*u0.x; cc[1] += v*u0.y; cc[2] += v*u0.z; cc[3] += v*u0.w;
            cc[4] += v*u1.x; cc[5] += v*u1.y; cc[6] += v*u1.z; cc[7] += v*u1.w;
        }
    }
    int node = base + m;
    float4* pa = (float4*)(g_A + (size_t)node*128 + cg);
    float4* pc = (float4*)(g_C + (size_t)node*128 + cg);
    pa[0] = make_float4(a[0],a[1],a[2],a[3]);
    pa[1] = make_float4(a[4],a[5],a[6],a[7]);
    pc[0] = make_float4(cc[0],cc[1],cc[2],cc[3]);
    pc[1] = make_float4(cc[4],cc[5],cc[6],cc[7]);
}

// ---------------- 3a) conv1 edge layer-2: D^T = W^T @ h^T (tf32, no smem) ----
__global__ void k_edge64(const float* __restrict__ bias){
    int t = threadIdx.x, warp = t >> 5, lane = t & 31;
    int node = blockIdx.x*8 + warp;
    int b = node / NN;
    int r = lane >> 2, q = lane & 3;

    int j0 = b*NN + __ldg(g_idx + (size_t)node*KNB + r);
    int j1 = b*NN + __ldg(g_idx + (size_t)node*KNB + 8 + r);
    const float* Ai = g_A + (size_t)node*64;
    const float* C0 = g_C + (size_t)j0*64;
    const float* C1 = g_C + (size_t)j1*64;

    float acc[4][2][4];
    #pragma unroll
    for (int mt = 0; mt < 4; mt++)
        #pragma unroll
        for (int n = 0; n < 2; n++)
            #pragma unroll
            for (int i = 0; i < 4; i++) acc[mt][n][i] = 0.f;

    #pragma unroll
    for (int kb = 0; kb < 8; kb++){
        int c0 = kb*8 + q;
        float ai0 = __ldg(Ai + c0), ai1 = __ldg(Ai + c0 + 4);
        unsigned b0h[2], b0l[2], b1h[2], b1l[2];
        splt(leaky(ai0 + __ldg(C0 + c0)),     b0h[0], b0l[0]);
        splt(leaky(ai1 + __ldg(C0 + c0 + 4)), b0h[1], b0l[1]);
        splt(leaky(ai0 + __ldg(C1 + c0)),     b1h[0], b1l[0]);
        splt(leaky(ai1 + __ldg(C1 + c0 + 4)), b1h[1], b1l[1]);
        #pragma unroll
        for (int mt = 0; mt < 4; mt++){
            uint4 H = __ldg(&g_w1Ah[(mt*8 + kb)*32 + lane]);
            uint4 L = __ldg(&g_w1Al[(mt*8 + kb)*32 + lane]);
            mma8(acc[mt][0], (const unsigned*)&H, b0h);
            mma8(acc[mt][0], (const unsigned*)&H, b0l);
            mma8(acc[mt][0], (const unsigned*)&L, b0h);
            mma8(acc[mt][1], (const unsigned*)&H, b1h);
            mma8(acc[mt][1], (const unsigned*)&H, b1l);
            mma8(acc[mt][1], (const unsigned*)&L, b1h);
        }
    }

    float ssum = 0.f;
    #pragma unroll
    for (int mt = 0; mt < 4; mt++){
        float m0 = fmaxf(fmaxf(acc[mt][0][0], acc[mt][0][1]),
                         fmaxf(acc[mt][1][0], acc[mt][1][1]));
        float m1 = fmaxf(fmaxf(acc[mt][0][2], acc[mt][0][3]),
                         fmaxf(acc[mt][1][2], acc[mt][1][3]));
        m0 = fmaxf(m0, __shfl_xor_sync(0xffffffffu, m0, 1));
        m0 = fmaxf(m0, __shfl_xor_sync(0xffffffffu, m0, 2));
        m1 = fmaxf(m1, __shfl_xor_sync(0xffffffffu, m1, 1));
        m1 = fmaxf(m1, __shfl_xor_sync(0xffffffffu, m1, 2));
        if (q == 0){
            int ch = mt*16 + r;
            float v0 = leaky(m0 + __ldg(bias + ch));
            float v1 = leaky(m1 + __ldg(bias + ch + 8));
            g_x1[(size_t)node*64 + ch]     = v0;
            g_x1[(size_t)node*64 + ch + 8] = v1;
            ssum += v0*v0 + v1*v1;
        }
    }
    ssum += __shfl_xor_sync(0xffffffffu, ssum, 4);
    ssum += __shfl_xor_sync(0xffffffffu, ssum, 8);
    ssum += __shfl_xor_sync(0xffffffffu, ssum, 16);
    if (lane == 0) g_sq[node] = ssum;
}

// ---------------- 3b) conv2 edge layer-2: D^T = W^T @ h^T (bf16, no smem) ----
__global__ void k_edge128(const float* __restrict__ bias){
    int t = threadIdx.x, warp = t >> 5, lane = t & 31;
    int node = blockIdx.x*8 + warp;
    int b = node / NN;
    int r = lane >> 2, q = lane & 3;

    int j0 = b*NN + __ldg(g_idx + (size_t)node*KNB + r);
    int j1 = b*NN + __ldg(g_idx + (size_t)node*KNB + 8 + r);
    const float* Ai = g_A + (size_t)node*128;
    const float* C0 = g_C + (size_t)j0*128;
    const float* C1 = g_C + (size_t)j1*128;

    float acc[4][2][4];
    #pragma unroll
    for (int mt = 0; mt < 4; mt++)
        #pragma unroll
        for (int n = 0; n < 2; n++)
            #pragma unroll
            for (int i = 0; i < 4; i++) acc[mt][n][i] = 0.f;

    #pragma unroll
    for (int kb = 0; kb < 8; kb++){
        int c0 = kb*16 + 2*q;
        float2 ai0 = *(const float2*)(Ai + c0);
        float2 ai1 = *(const float2*)(Ai + c0 + 8);
        float2 ca0 = *(const float2*)(C0 + c0);
        float2 ca1 = *(const float2*)(C0 + c0 + 8);
        float2 cb0 = *(const float2*)(C1 + c0);
        float2 cb1 = *(const float2*)(C1 + c0 + 8);
        unsigned b0h[2], b0l[2], b1h[2], b1l[2];
        split2(leaky(ai0.x + ca0.x), leaky(ai0.y + ca0.y), b0h[0], b0l[0]);
        split2(leaky(ai1.x + ca1.x), leaky(ai1.y + ca1.y), b0h[1], b0l[1]);
        split2(leaky(ai0.x + cb0.x), leaky(ai0.y + cb0.y), b1h[0], b1l[0]);
        split2(leaky(ai1.x + cb1.x), leaky(ai1.y + cb1.y), b1h[1], b1l[1]);
        #pragma unroll
        for (int mt = 0; mt < 4; mt++){
            uint4 H = __ldg(&g_w2Ah[(mt*8 + kb)*32 + lane]);
            uint4 L = __ldg(&g_w2Al[(mt*8 + kb)*32 + lane]);
            mma16(acc[mt][0], (const unsigned*)&H, b0h);
            mma16(acc[mt][0], (const unsigned*)&H, b0l);
            mma16(acc[mt][0], (const unsigned*)&L, b0h);
            mma16(acc[mt][1], (const unsigned*)&H, b1h);
            mma16(acc[mt][1], (const unsigned*)&H, b1l);
            mma16(acc[mt][1], (const unsigned*)&L, b1h);
        }
    }

    #pragma unroll
    for (int mt = 0; mt < 4; mt++){
        float m0 = fmaxf(fmaxf(acc[mt][0][0], acc[mt][0][1]),
                         fmaxf(acc[mt][1][0], acc[mt][1][1]));
        float m1 = fmaxf(fmaxf(acc[mt][0][2], acc[mt][0][3]),
                         fmaxf(acc[mt][1][2], acc[mt][1][3]));
        m0 = fmaxf(m0, __shfl_xor_sync(0xffffffffu, m0, 1));
        m0 = fmaxf(m0, __shfl_xor_sync(0xffffffffu, m0, 2));
        m1 = fmaxf(m1, __shfl_xor_sync(0xffffffffu, m1, 1));
        m1 = fmaxf(m1, __shfl_xor_sync(0xffffffffu, m1, 2));
        if (q == 0){
            int ch = mt*16 + r;
            g_x2[(size_t)node*64 + ch]     = leaky(m0 + __ldg(bias + ch));
            g_x2[(size_t)node*64 + ch + 8] = leaky(m1 + __ldg(bias + ch + 8));
        }
    }
}

__device__ __forceinline__ float featval(int node, int d){
    if (d < 5)   return g_xx[node*5 + d];
    if (d < 69)  return g_x1[(size_t)node*64 + d - 5];
    if (d < 133) return g_x2[(size_t)node*64 + d - 69];
    return 0.f;
}

// ---------------- 4a) lin1: [BN x 144] @ [144 x 512] + leaky (bf16) ----------
__global__ void k_lin1(const float* __restrict__ bl1){
    __shared__ unsigned CSh[64*76];
    __shared__ unsigned CSl[64*76];
    int t = threadIdx.x, lane = t & 31, w = t >> 5;
    int base = blockIdx.x*64;
    for (int i = t; i < 64*72; i += 256){
        int m = i / 72, p = i - m*72;
        int node = base + m;
        float v0 = featval(node, 2*p);
        float v1 = featval(node, 2*p + 1);
        unsigned h, l;
        split2(v0, v1, h, l);
        CSh[m*76 + p] = h;
        CSl[m*76 + p] = l;
    }
    __syncthreads();

    int r = lane >> 2, q = lane & 3;
    int n0 = w*64;
    for (int np = 0; np < 2; np++){
        float acc[4][4][4];
        #pragma unroll
        for (int mt = 0; mt < 4; mt++)
            #pragma unroll
            for (int nt = 0; nt < 4; nt++)
                #pragma unroll
                for (int i = 0; i < 4; i++) acc[mt][nt][i] = 0.f;

        for (int kb = 0; kb < 9; kb++){
            unsigned ah[4][4], al[4][4];
            #pragma unroll
            for (int mt = 0; mt < 4; mt++){
                int rb = mt*16;
                ah[mt][0] = CSh[(rb+r)*76 + kb*8 + q];       al[mt][0] = CSl[(rb+r)*76 + kb*8 + q];
                ah[mt][1] = CSh[(rb+r+8)*76 + kb*8 + q];     al[mt][1] = CSl[(rb+r+8)*76 + kb*8 + q];
                ah[mt][2] = CSh[(rb+r)*76 + kb*8 + 4 + q];   al[mt][2] = CSl[(rb+r)*76 + kb*8 + 4 + q];
                ah[mt][3] = CSh[(rb+r+8)*76 + kb*8 + 4 + q]; al[mt][3] = CSl[(rb+r+8)*76 + kb*8 + 4 + q];
            }
            #pragma unroll
            for (int nt = 0; nt < 4; nt++){
                uint4 wv = __ldg(&g_wl1pb[(kb*64 + w*8 + np*4 + nt)*32 + lane]);
                unsigned bh[2] = {wv.x, wv.y};
                unsigned bl[2] = {wv.z, wv.w};
                #pragma unroll
                for (int mt = 0; mt < 4; mt++){
                    mma16(acc[mt][nt], ah[mt], bh);
                    mma16(acc[mt][nt], ah[mt], bl);
                    mma16(acc[mt][nt], al[mt], bh);
                }
            }
        }
        #pragma unroll
        for (int mt = 0; mt < 4; mt++){
            #pragma unroll
            for (int nt = 0; nt < 4; nt++){
                int node = base + mt*16 + r;
                int col = n0 + (np*4 + nt)*8 + q*2;
                float b0 = __ldg(bl1 + col), b1 = __ldg(bl1 + col + 1);
                float2 u0, u1;
                u0.x = leaky(acc[mt][nt][0] + b0); u0.y = leaky(acc[mt][nt][1] + b1);
                u1.x = leaky(acc[mt][nt][2] + b0); u1.y = leaky(acc[mt][nt][3] + b1);
                *(float2*)(g_hs + (size_t)node*512 + col)     = u0;
                *(float2*)(g_hs + (size_t)(node+8)*512 + col) = u1;
            }
        }
    }
}

// ---------------- 4b) lin2: [BN x 512] @ [512 x 256] + max-pool (bf16) -------
__global__ void k_lin2(const float* __restrict__ bl2){
    __shared__ unsigned Ash[64*36];
    __shared__ unsigned Asl[64*36];
    int t = threadIdx.x, lane = t & 31, w = t >> 5;
    int base = blockIdx.x*64;
    int g = base / NN;
    int r = lane >> 2, q = lane & 3;
    int n0 = w*32;

    float acc[4][4][4];
    #pragma unroll
    for (int mt = 0; mt < 4; mt++)
        #pragma unroll
        for (int nt = 0; nt < 4; nt++)
            #pragma unroll
            for (int i = 0; i < 4; i++) acc[mt][nt][i] = 0.f;

    for (int kc = 0; kc < 512; kc += 64){
        __syncthreads();
        for (int i = t; i < 1024; i += 256){
            int m = i >> 4, sub = i & 15;
            float4 v = *(const float4*)(g_hs + (size_t)(base + m)*512 + kc + sub*4);
            unsigned h0, l0, h1, l1;
            split2(v.x, v.y, h0, l0);
            split2(v.z, v.w, h1, l1);
            Ash[m*36 + sub*2]     = h0;
            Ash[m*36 + sub*2 + 1] = h1;
            Asl[m*36 + sub*2]     = l0;
            Asl[m*36 + sub*2 + 1] = l1;
        }
        __syncthreads();
        #pragma unroll
        for (int kb = 0; kb < 4; kb++){
            unsigned ah[4][4], al[4][4];
            #pragma unroll
            for (int mt = 0; mt < 4; mt++){
                int rb = mt*16;
                ah[mt][0] = Ash[(rb+r)*36 + kb*8 + q];       al[mt][0] = Asl[(rb+r)*36 + kb*8 + q];
                ah[mt][1] = Ash[(rb+r+8)*36 + kb*8 + q];     al[mt][1] = Asl[(rb+r+8)*36 + kb*8 + q];
                ah[mt][2] = Ash[(rb+r)*36 + kb*8 + 4 + q];   al[mt][2] = Asl[(rb+r)*36 + kb*8 + 4 + q];
                ah[mt][3] = Ash[(rb+r+8)*36 + kb*8 + 4 + q]; al[mt][3] = Asl[(rb+r+8)*36 + kb*8 + 4 + q];
            }
            int kbg = (kc >> 4) + kb;
            #pragma unroll
            for (int nt = 0; nt < 4; nt++){
                uint4 wv = __ldg(&g_wl2pb[(kbg*32 + w*4 + nt)*32 + lane]);
                unsigned bh[2] = {wv.x, wv.y};
                unsigned bl[2] = {wv.z, wv.w};
                #pragma unroll
                for (int mt = 0; mt < 4; mt++){
                    mma16(acc[mt][nt], ah[mt], bh);
                    mma16(acc[mt][nt], ah[mt], bl);
                    mma16(acc[mt][nt], al[mt], bh);
                }
            }
        }
    }

    #pragma unroll
    for (int nt = 0; nt < 4; nt++){
        float m0 = -3.4e38f, m1 = -3.4e38f;
        #pragma unroll
        for (int mt = 0; mt < 4; mt++){
            m0 = fmaxf(m0, fmaxf(acc[mt][nt][0], acc[mt][nt][2]));
            m1 = fmaxf(m1, fmaxf(acc[mt][nt][1], acc[mt][nt][3]));
        }
        #pragma unroll
        for (int off = 4; off < 32; off <<= 1){
            m0 = fmaxf(m0, __shfl_xor_sync(0xffffffffu, m0, off));
            m1 = fmaxf(m1, __shfl_xor_sync(0xffffffffu, m1, off));
        }
        if (lane < 4){
            int col = n0 + nt*8 + lane*2;
            atomicMaxFloat(&g_pool[g*256 + col],     m0 + __ldg(bl2 + col));
            atomicMaxFloat(&g_pool[g*256 + col + 1], m1 + __ldg(bl2 + col + 1));
        }
    }
}

// ---------------- 5) head: leaky -> 256x128 -> leaky -> 128x3 ----------------
__global__ void k_head(const float* __restrict__ wm1, const float* __restrict__ bm1,
                       const float* __restrict__ wm2, const float* __restrict__ bm2,
                       float* __restrict__ out){
    __shared__ float gs[256];
    __shared__ float ms[128];
    int b = blockIdx.x, t = threadIdx.x;
    for (int c = t; c < 256; c += 128) gs[c] = leaky(g_pool[b*256 + c]);
    __syncthreads();
    float acc = bm1[t];
    #pragma unroll 8
    for (int d = 0; d < 256; d++) acc += gs[d]*wm1[d*128 + t];
    ms[t] = leaky(acc);
    __syncthreads();
    if (t < 3){
        float o = bm2[t];
        #pragma unroll 8
        for (int d = 0; d < 128; d++) o += ms[d]*wm2[d*3 + t];
        out[b*3 + t] = o;
    }
}

// -----------------------------------------------------------------------------
extern "C" void kernel_launch(void* const* d_in, const int* in_sizes, int n_in,
                              void* d_out, int out_size){
    const float* x   = (const float*)d_in[0];
    const float* pos = (const float*)d_in[1];
    const float* tq  = (const float*)d_in[2];
    const float* w1a = (const float*)d_in[4];
    const float* b1a = (const float*)d_in[5];
    const float* w1b = (const float*)d_in[6];
    const float* b1b = (const float*)d_in[7];
    const float* w2a = (const float*)d_in[8];
    const float* b2a = (const float*)d_in[9];
    const float* w2b = (const float*)d_in[10];
    const float* b2b = (const float*)d_in[11];
    const float* wl1 = (const float*)d_in[12];
    const float* bl1 = (const float*)d_in[13];
    const float* wl2 = (const float*)d_in[14];
    const float* bl2 = (const float*)d_in[15];
    const float* wm1 = (const float*)d_in[16];
    const float* bm1 = (const float*)d_in[17];
    const float* wm2 = (const float*)d_in[18];
    const float* bm2 = (const float*)d_in[19];
    float* out = (float*)d_out;

    k_prep<<<208, 256>>>(w1b, w2b, wl1, wl2);
    k_build<<<BN/256, 256>>>(x, pos, tq);

    // conv1
    k_knn5<<<BATCH*(NN/8), 256>>>();
    k_convA1<<<(BN*64)/256, 256>>>(w1a, b1a);
    k_edge64<<<BN/8, 256>>>(b1b);        // also emits g_sq

    // conv2: fused d2-GEMM + select, then layer-1 and edge layer-2
    k_d2sel<<<BN/32, 256>>>();
    k_convA2<<<BN/16, 256>>>(w2a, b2a);
    k_edge128<<<BN/8, 256>>>(b2b);

    // lin1 -> g_hs, lin2 + fused pool, head
    k_lin1<<<BN/64, 256>>>(bl1);
    k_lin2<<<BN/64, 256>>>(bl2);
    k_head<<<BATCH, 128>>>(wm1, bm1, wm2, bm2, out);
}

// round 11
// speedup vs baseline: 1.0069x; 1.0069x over previous
#include <cuda_runtime.h>
#include <cuda_bf16.h>
#include <cstdint>

#define BATCH 128
#define NN    512
#define KNB   16
#define BN    (BATCH*NN)
#define NEGS  0.01f

// ---------------- scratch (device globals; no allocation allowed) -------------
__device__ float g_xx[BN*5];
__device__ float g_x1[BN*64];
__device__ float g_x2[BN*64];
__device__ int   g_idx[BN*KNB];
__device__ float g_A[(size_t)BN*128];
__device__ float g_C[(size_t)BN*128];
__device__ float g_pool[BATCH*256];
__device__ float g_sq[BN];
__device__ float g_sq5[BN];
__device__ float g_d2[(size_t)BN*NN];   // pairwise distances (conv2 kNN)
__device__ float g_hs[(size_t)BN*512];  // lin1 -> lin2 buffer

// W^T A-operand fragment tables for edge kernels (indexed (mt*8+kb)*32+lane)
__device__ uint4 g_w1Ah[1024], g_w1Al[1024];   // conv1 W2 (64x64), tf32 split
__device__ uint4 g_w2Ah[1024], g_w2Al[1024];   // conv2 W2 (128x64), bf16 split
// bf16 split fragment-packed B-operand weights for lin kernels
__device__ uint4  g_wl1pb[9*64*32];      // 144x512 (rows >=133 zero)
__device__ uint4  g_wl2pb[32*32*32];     // 512x256

__device__ __forceinline__ float leaky(float v){ return v > 0.f ? v : NEGS*v; }

__device__ __forceinline__ void atomicMaxFloat(float* addr, float value){
    if (value >= 0.f) atomicMax((int*)addr, __float_as_int(value));
    else              atomicMin((unsigned int*)addr, __float_as_uint(value));
}

__device__ __forceinline__ unsigned f2tf(float x){
    unsigned u; asm("cvt.rna.tf32.f32 %0, %1;" : "=r"(u) : "f"(x)); return u;
}
__device__ __forceinline__ void splt(float x, unsigned &h, unsigned &l){
    h = f2tf(x);
    l = f2tf(x - __uint_as_float(h));
}
__device__ __forceinline__ void mma8(float* c, const unsigned* a, const unsigned* b){
    asm("mma.sync.aligned.m16n8k8.row.col.f32.tf32.tf32.f32 "
        "{%0,%1,%2,%3}, {%4,%5,%6,%7}, {%8,%9}, {%0,%1,%2,%3};"
        : "+f"(c[0]), "+f"(c[1]), "+f"(c[2]), "+f"(c[3])
        : "r"(a[0]), "r"(a[1]), "r"(a[2]), "r"(a[3]), "r"(b[0]), "r"(b[1]));
}
__device__ __forceinline__ void mma16(float* c, const unsigned* a, const unsigned* b){
    asm("mma.sync.aligned.m16n8k16.row.col.f32.bf16.bf16.f32 "
        "{%0,%1,%2,%3}, {%4,%5,%6,%7}, {%8,%9}, {%0,%1,%2,%3};"
        : "+f"(c[0]), "+f"(c[1]), "+f"(c[2]), "+f"(c[3])
        : "r"(a[0]), "r"(a[1]), "r"(a[2]), "r"(a[3]), "r"(b[0]), "r"(b[1]));
}
__device__ __forceinline__ unsigned packbf(float v0, float v1){
    unsigned d; asm("cvt.rn.bf16x2.f32 %0, %1, %2;" : "=r"(d) : "f"(v1), "f"(v0)); return d;
}
__device__ __forceinline__ float bflo(unsigned p){ return __uint_as_float(p << 16); }
__device__ __forceinline__ float bfhi(unsigned p){ return __uint_as_float(p & 0xffff0000u); }
__device__ __forceinline__ void split2(float v0, float v1, unsigned &h, unsigned &l){
    h = packbf(v0, v1);
    l = packbf(v0 - bflo(h), v1 - bfhi(h));
}

// sortable-u32 transform
__device__ __forceinline__ unsigned fsort(float f){
    unsigned b = __float_as_uint(f);
    return b ^ (((int)b >> 31) | 0x80000000u);
}

// index mappings for sel16 slot u on lane:
// MODE 0: j = u*32 + lane   (knn5)
// MODE 1: j = lane*16 + u   (select from contiguous row)
template<int MODE>
__device__ __forceinline__ int sel_j(int lane, int u){
    if (MODE == 0) return u*32 + lane;
    return lane*16 + u;
}
template<int MODE>
__device__ __forceinline__ int sel_u(int j){
    if (MODE == 0) return j >> 5;
    return j & 15;
}

// warp-cooperative exact top-16-of-512 with lower-index tiebreak.
template<int MODE>
__device__ __forceinline__ void sel16(const float* v, int lane, int* out){
    const unsigned long long INF = ~0ull;
    unsigned long long s0 = INF, s1 = INF, s2 = INF, s3 = INF;
    #pragma unroll
    for (int u = 0; u < 16; u++){
        int j = sel_j<MODE>(lane, u);
        unsigned long long k = ((unsigned long long)fsort(v[u]) << 32) | (unsigned)j;
        if (k < s3){
            s3 = k;
            if (s3 < s2){ unsigned long long t = s2; s2 = s3; s3 = t; }
            if (s2 < s1){ unsigned long long t = s1; s1 = s2; s2 = t; }
            if (s1 < s0){ unsigned long long t = s0; s0 = s1; s1 = t; }
        }
    }
    unsigned mask = 0;
    int mine = 0;
    #pragma unroll 1
    for (int r = 0; r < KNB; r++){
        unsigned long long m = s0;
        #pragma unroll
        for (int off = 16; off; off >>= 1){
            unsigned long long o = __shfl_xor_sync(0xffffffffu, m, off);
            if (o < m) m = o;
        }
        if (lane == r) mine = (int)(unsigned)(m & 0xffffffffu);
        if (s0 == m){
            int j = (int)(unsigned)(m & 0xffffffffu);
            mask |= 1u << sel_u<MODE>(j);
            s0 = s1; s1 = s2; s2 = s3; s3 = INF;
            if (s0 == INF && mask != 0xffffu){
                #pragma unroll
                for (int u2 = 0; u2 < 16; u2++){
                    if (!((mask >> u2) & 1u)){
                        int j2 = sel_j<MODE>(lane, u2);
                        unsigned long long k = ((unsigned long long)fsort(v[u2]) << 32) | (unsigned)j2;
                        if (k < s3){
                            s3 = k;
                            if (s3 < s2){ unsigned long long t = s2; s2 = s3; s3 = t; }
                            if (s2 < s1){ unsigned long long t = s1; s1 = s2; s2 = t; }
                            if (s1 < s0){ unsigned long long t = s0; s0 = s1; s1 = t; }
                        }
                    }
                }
            }
        }
    }
    if (lane < KNB) out[lane] = mine;
}

// ---------------- fused prep (weight packing + pool init) + build ------------
__global__ void k_prepbuild(const float* __restrict__ w1b, const float* __restrict__ w2b,
                            const float* __restrict__ wl1, const float* __restrict__ wl2,
                            const float* __restrict__ x, const float* __restrict__ pos,
                            const float* __restrict__ tq){
    if (blockIdx.x < 208){
        int i = blockIdx.x*256 + threadIdx.x;
        if (i < BATCH*256) g_pool[i] = __int_as_float(0xff800000); // -inf
        if (i < 1024){
            int lane = i & 31, tmp = i >> 5;
            int kb = tmp & 7, mt = tmp >> 3;
            int r = lane >> 2, q = lane & 3;
            int R = mt*16 + r, k0 = kb*8 + q;
            uint4 H, L;
            splt(w1b[k0*64 + R],       H.x, L.x);
            splt(w1b[k0*64 + R + 8],   H.y, L.y);
            splt(w1b[(k0+4)*64 + R],   H.z, L.z);
            splt(w1b[(k0+4)*64 + R+8], H.w, L.w);
            g_w1Ah[i] = H; g_w1Al[i] = L;
        } else if (i < 2048){
            int rel = i - 1024;
            int lane = rel & 31, tmp = rel >> 5;
            int kb = tmp & 7, mt = tmp >> 3;
            int r = lane >> 2, q = lane & 3;
            int R = mt*16 + r, c0 = kb*16 + 2*q;
            uint4 H, L;
            split2(w2b[c0*64 + R],       w2b[(c0+1)*64 + R],     H.x, L.x);
            split2(w2b[c0*64 + R + 8],   w2b[(c0+1)*64 + R + 8], H.y, L.y);
            split2(w2b[(c0+8)*64 + R],   w2b[(c0+9)*64 + R],     H.z, L.z);
            split2(w2b[(c0+8)*64 + R+8], w2b[(c0+9)*64 + R + 8], H.w, L.w);
            g_w2Ah[rel] = H; g_w2Al[rel] = L;
        } else if (i < 53248){
            const float* W; uint4* dst; int ncb, ncols, nrows, rel;
            if (i < 20480){ rel = i - 2048;  W = wl1; dst = g_wl1pb; ncb = 64; ncols = 512; nrows = 133; }
            else          { rel = i - 20480; W = wl2; dst = g_wl2pb; ncb = 32; ncols = 256; nrows = 512; }
            int lane = rel & 31, tmp = rel >> 5;
            int cb = tmp % ncb, kb = tmp / ncb;
            int r = lane >> 2, q = lane & 3, col = cb*8 + r;
            int k0 = kb*16 + 2*q;
            float v00 = (k0     < nrows) ? W[(k0    )*ncols + col] : 0.f;
            float v01 = (k0 + 1 < nrows) ? W[(k0 + 1)*ncols + col] : 0.f;
            float v10 = (k0 + 8 < nrows) ? W[(k0 + 8)*ncols + col] : 0.f;
            float v11 = (k0 + 9 < nrows) ? W[(k0 + 9)*ncols + col] : 0.f;
            unsigned h0, l0, h1, l1;
            split2(v00, v01, h0, l0);
            split2(v10, v11, h1, l1);
            dst[rel] = make_uint4(h0, h1, l0, l1);
        }
    } else {
        int i = (blockIdx.x - 208)*256 + threadIdx.x;
        if (i < BN){
            float tv = tq[i], xv = x[i];
            float p0 = pos[i*3+0], p1 = pos[i*3+1], p2 = pos[i*3+2];
            g_xx[i*5+0] = tv;
            g_xx[i*5+1] = xv;
            g_xx[i*5+2] = p0;
            g_xx[i*5+3] = p1;
            g_xx[i*5+4] = p2;
            g_sq5[i] = tv*tv + xv*xv + p0*p0 + p1*p1 + p2*p2;
        }
    }
}

// ---------------- fused kNN d=5 + conv1 layer-1 ------------------------------
// blocks [0, 8192): knn5 ; blocks [8192, 24576): convA1
__global__ void k_knn5A1(const float* __restrict__ W, const float* __restrict__ bias){
    __shared__ float tile[128*8];
    if (blockIdx.x < 8192){
        int b  = blockIdx.x >> 6;
        int q0 = (blockIdx.x & 63) * 8;
        int warp = threadIdx.x >> 5, lane = threadIdx.x & 31;
        int qi = q0 + warp;
        int node = b*NN + qi;
        const float* Fb = g_xx + (size_t)b*NN*5;

        float f0, f1, f2, f3, f4;
        { const float* fq = Fb + qi*5; f0=fq[0]; f1=fq[1]; f2=fq[2]; f3=fq[3]; f4=fq[4]; }
        float sqi = g_sq5[node];

        float d2loc[16];
        for (int t4 = 0; t4 < 4; t4++){
            __syncthreads();
            for (int idx = threadIdx.x; idx < 1024; idx += 256){
                int rrow = idx >> 3, c = idx & 7;
                int grow = t4*128 + rrow;
                float v = 0.f;
                if (c < 5)       v = Fb[grow*5 + c];
                else if (c == 5) v = g_sq5[b*NN + grow];
                tile[idx] = v;
            }
            __syncthreads();
            #pragma unroll
            for (int u = 0; u < 4; u++){
                int jj = u*32 + lane;
                const float* tr = &tile[jj*8];
                float4 p  = *(const float4*)tr;
                float2 p2 = *(const float2*)(tr + 4);
                float dot = f0*p.x + f1*p.y + f2*p.z + f3*p.w + f4*p2.x;
                d2loc[t4*4 + u] = sqi + p2.y - 2.f*dot;
            }
        }
        sel16<0>(d2loc, lane, g_idx + (size_t)node*KNB);
    } else {
        int t = (blockIdx.x - 8192)*256 + threadIdx.x;
        if (t >= BN*64) return;
        int i = t >> 6, c = t & 63;
        const float* f = g_xx + (size_t)i*5;
        float a = bias[c], cc = 0.f;
        #pragma unroll
        for (int d = 0; d < 5; d++){
            float v  = f[d];
            float wt = W[d*64 + c];
            float wb = W[(5 + d)*64 + c];
            a  += v*(wt - wb);
            cc += v*wb;
        }
        g_A[(size_t)i*64 + c] = a;
        g_C[(size_t)i*64 + c] = cc;
    }
}

// ---------------- fused d2-GEMM (split-tf32) + conv2 layer-1 -----------------
// blocks [0, 2048): d2t tiles ; blocks [2048, 6144): convA2
__global__ void k_d2A2(const float* __restrict__ W, const float* __restrict__ bias){
    __shared__ float SU[9216];     // union: d2t As/Bs | convA2 Wd/Wb/Fs
    int t = threadIdx.x;
    if (blockIdx.x < 2048){
        float* As = SU;            // [128*36]
        float* Bs = SU + 4608;     // [128*36]
        int blk = blockIdx.x;
        int b = blk >> 4;
        int i0 = ((blk >> 2) & 3) * 128;
        int j0 = (blk & 3) * 128;
        const float* Fb = g_x1 + (size_t)b*NN*64;
        int lane = t & 31, w = t >> 5;
        int wx = w & 1, wy = w >> 1;
        int r = lane >> 2, q = lane & 3;

        float acc[2][8][4];
        #pragma unroll
        for (int mt = 0; mt < 2; mt++)
            #pragma unroll
            for (int nt = 0; nt < 8; nt++)
                #pragma unroll
                for (int i = 0; i < 4; i++) acc[mt][nt][i] = 0.f;

        for (int kc = 0; kc < 64; kc += 32){
            __syncthreads();
            for (int i = t; i < 128*8; i += 256){
                int m = i >> 3, kq = (i & 7)*4;
                *(float4*)&As[m*36 + kq] = *(const float4*)(Fb + (i0+m)*64 + kc + kq);
                *(float4*)&Bs[m*36 + kq] = *(const float4*)(Fb + (j0+m)*64 + kc + kq);
            }
            __syncthreads();
            #pragma unroll
            for (int k0 = 0; k0 < 32; k0 += 8){
                unsigned ah[2][4], al[2][4];
                #pragma unroll
                for (int mt = 0; mt < 2; mt++){
                    int row = wy*32 + mt*16;
                    splt(As[(row+r)*36 + k0 + q],       ah[mt][0], al[mt][0]);
                    splt(As[(row+r+8)*36 + k0 + q],     ah[mt][1], al[mt][1]);
                    splt(As[(row+r)*36 + k0 + q + 4],   ah[mt][2], al[mt][2]);
                    splt(As[(row+r+8)*36 + k0 + q + 4], ah[mt][3], al[mt][3]);
                }
                #pragma unroll
                for (int nt = 0; nt < 8; nt++){
                    int col = wx*64 + nt*8;
                    unsigned bh[2], bl[2];
                    splt(Bs[(col+r)*36 + k0 + q],     bh[0], bl[0]);
                    splt(Bs[(col+r)*36 + k0 + q + 4], bh[1], bl[1]);
                    #pragma unroll
                    for (int mt = 0; mt < 2; mt++){
                        mma8(acc[mt][nt], ah[mt], bh);
                        mma8(acc[mt][nt], ah[mt], bl);
                        mma8(acc[mt][nt], al[mt], bh);
                    }
                }
            }
        }

        #pragma unroll
        for (int mt = 0; mt < 2; mt++){
            int rowb = i0 + wy*32 + mt*16;
            float si0 = g_sq[b*NN + rowb + r];
            float si1 = g_sq[b*NN + rowb + r + 8];
            #pragma unroll
            for (int nt = 0; nt < 8; nt++){
                int colb = j0 + wx*64 + nt*8 + 2*q;
                float sj0 = g_sq[b*NN + colb], sj1 = g_sq[b*NN + colb + 1];
                float2 v0, v1;
                v0.x = si0 + sj0 - 2.f*acc[mt][nt][0];
                v0.y = si0 + sj1 - 2.f*acc[mt][nt][1];
                v1.x = si1 + sj0 - 2.f*acc[mt][nt][2];
                v1.y = si1 + sj1 - 2.f*acc[mt][nt][3];
                *(float2*)(g_d2 + (size_t)(b*NN + rowb + r)*NN + colb)     = v0;
                *(float2*)(g_d2 + (size_t)(b*NN + rowb + r + 8)*NN + colb) = v1;
            }
        }
    } else {
        float* Wd = SU;            // [32*128]
        float* Wb = SU + 4096;     // [32*128]
        float* Fs = SU + 8192;     // [16*64]
        int base = (blockIdx.x - 2048)*16;

        for (int idx = t; idx < 1024; idx += 256)
            Fs[idx] = g_x1[(size_t)base*64 + idx];

        int m  = t >> 4;
        int cg = (t & 15)*8;
        float a[8], cc[8];
        float4 bb0 = *(const float4*)(bias + cg);
        float4 bb1 = *(const float4*)(bias + cg + 4);
        a[0]=bb0.x; a[1]=bb0.y; a[2]=bb0.z; a[3]=bb0.w;
        a[4]=bb1.x; a[5]=bb1.y; a[6]=bb1.z; a[7]=bb1.w;
        #pragma unroll
        for (int q = 0; q < 8; q++) cc[q] = 0.f;

        for (int db = 0; db < 64; db += 32){
            __syncthreads();
            for (int idx = t; idx < 4096; idx += 256){
                int d = idx >> 7, c = idx & 127;
                float wt = W[(db + d)*128 + c];
                float wb = W[(64 + db + d)*128 + c];
                Wd[idx] = wt - wb;
                Wb[idx] = wb;
            }
            __syncthreads();
            #pragma unroll 4
            for (int d = 0; d < 32; d++){
                float v = Fs[m*64 + db + d];
                float4 w0 = *(const float4*)&Wd[d*128 + cg];
                float4 w1 = *(const float4*)&Wd[d*128 + cg + 4];
                float4 u0 = *(const float4*)&Wb[d*128 + cg];
                float4 u1 = *(const float4*)&Wb[d*128 + cg + 4];
                a[0] += v*w0.x; a[1] += v*w0.y; a[2] += v*w0.z; a[3] += v*w0.w;
                a[4] += v*w1.x; a[5] += v*w1.y; a[6] += v*w1.z; a[7] += v*w1.w;
                cc[0] += v*u0.x; cc[1] += v*u0.y; cc[2] += v*u0.z; cc[3] += v*u0.w;
                cc[4] += v*u1.x; cc[5] += v*u1.y; cc[6] += v*u1.z; cc[7] += v*u1.w;
            }
        }
        int node = base + m;
        float4* pa = (float4*)(g_A + (size_t)node*128 + cg);
        float4* pc = (float4*)(g_C + (size_t)node*128 + cg);
        pa[0] = make_float4(a[0],a[1],a[2],a[3]);
        pa[1] = make_float4(a[4],a[5],a[6],a[7]);
        pc[0] = make_float4(cc[0],cc[1],cc[2],cc[3]);
        pc[1] = make_float4(cc[4],cc[5],cc[6],cc[7]);
    }
}

// ---------------- kNN d=64: cached-top4 select from g_d2 ---------------------
__global__ void k_select(){
    int warp = threadIdx.x >> 5, lane = threadIdx.x & 31;
    int node = blockIdx.x*8 + warp;
    const float* row = g_d2 + (size_t)node*NN;
    float v[16];
    #pragma unroll
    for (int u4 = 0; u4 < 4; u4++){
        float4 x = *(const float4*)(row + lane*16 + u4*4);
        v[u4*4+0] = x.x; v[u4*4+1] = x.y; v[u4*4+2] = x.z; v[u4*4+3] = x.w;
    }
    sel16<1>(v, lane, g_idx + (size_t)node*KNB);
}

// ---------------- conv1 edge layer-2: D^T = W^T @ h^T (tf32, no smem) --------
__global__ void k_edge64(const float* __restrict__ bias){
    int t = threadIdx.x, warp = t >> 5, lane = t & 31;
    int node = blockIdx.x*8 + warp;
    int b = node / NN;
    int r = lane >> 2, q = lane & 3;

    int j0 = b*NN + __ldg(g_idx + (size_t)node*KNB + r);
    int j1 = b*NN + __ldg(g_idx + (size_t)node*KNB + 8 + r);
    const float* Ai = g_A + (size_t)node*64;
    const float* C0 = g_C + (size_t)j0*64;
    const float* C1 = g_C + (size_t)j1*64;

    float acc[4][2][4];
    #pragma unroll
    for (int mt = 0; mt < 4; mt++)
        #pragma unroll
        for (int n = 0; n < 2; n++)
            #pragma unroll
            for (int i = 0; i < 4; i++) acc[mt][n][i] = 0.f;

    #pragma unroll
    for (int kb = 0; kb < 8; kb++){
        int c0 = kb*8 + q;
        float ai0 = __ldg(Ai + c0), ai1 = __ldg(Ai + c0 + 4);
        unsigned b0h[2], b0l[2], b1h[2], b1l[2];
        splt(leaky(ai0 + __ldg(C0 + c0)),     b0h[0], b0l[0]);
        splt(leaky(ai1 + __ldg(C0 + c0 + 4)), b0h[1], b0l[1]);
        splt(leaky(ai0 + __ldg(C1 + c0)),     b1h[0], b1l[0]);
        splt(leaky(ai1 + __ldg(C1 + c0 + 4)), b1h[1], b1l[1]);
        #pragma unroll
        for (int mt = 0; mt < 4; mt++){
            uint4 H = __ldg(&g_w1Ah[(mt*8 + kb)*32 + lane]);
            uint4 L = __ldg(&g_w1Al[(mt*8 + kb)*32 + lane]);
            mma8(acc[mt][0], (const unsigned*)&H, b0h);
            mma8(acc[mt][0], (const unsigned*)&H, b0l);
            mma8(acc[mt][0], (const unsigned*)&L, b0h);
            mma8(acc[mt][1], (const unsigned*)&H, b1h);
            mma8(acc[mt][1], (const unsigned*)&H, b1l);
            mma8(acc[mt][1], (const unsigned*)&L, b1h);
        }
    }

    float ssum = 0.f;
    #pragma unroll
    for (int mt = 0; mt < 4; mt++){
        float m0 = fmaxf(fmaxf(acc[mt][0][0], acc[mt][0][1]),
                         fmaxf(acc[mt][1][0], acc[mt][1][1]));
        float m1 = fmaxf(fmaxf(acc[mt][0][2], acc[mt][0][3]),
                         fmaxf(acc[mt][1][2], acc[mt][1][3]));
        m0 = fmaxf(m0, __shfl_xor_sync(0xffffffffu, m0, 1));
        m0 = fmaxf(m0, __shfl_xor_sync(0xffffffffu, m0, 2));
        m1 = fmaxf(m1, __shfl_xor_sync(0xffffffffu, m1, 1));
        m1 = fmaxf(m1, __shfl_xor_sync(0xffffffffu, m1, 2));
        if (q == 0){
            int ch = mt*16 + r;
            float v0 = leaky(m0 + __ldg(bias + ch));
            float v1 = leaky(m1 + __ldg(bias + ch + 8));
            g_x1[(size_t)node*64 + ch]     = v0;
            g_x1[(size_t)node*64 + ch + 8] = v1;
            ssum += v0*v0 + v1*v1;
        }
    }
    ssum += __shfl_xor_sync(0xffffffffu, ssum, 4);
    ssum += __shfl_xor_sync(0xffffffffu, ssum, 8);
    ssum += __shfl_xor_sync(0xffffffffu, ssum, 16);
    if (lane == 0) g_sq[node] = ssum;
}

// ---------------- conv2 edge layer-2: D^T = W^T @ h^T (bf16, no smem) --------
__global__ void k_edge128(const float* __restrict__ bias){
    int t = threadIdx.x, warp = t >> 5, lane = t & 31;
    int node = blockIdx.x*8 + warp;
    int b = node / NN;
    int r = lane >> 2, q = lane & 3;

    int j0 = b*NN + __ldg(g_idx + (size_t)node*KNB + r);
    int j1 = b*NN + __ldg(g_idx + (size_t)node*KNB + 8 + r);
    const float* Ai = g_A + (size_t)node*128;
    const float* C0 = g_C + (size_t)j0*128;
    const float* C1 = g_C + (size_t)j1*128;

    float acc[4][2][4];
    #pragma unroll
    for (int mt = 0; mt < 4; mt++)
        #pragma unroll
        for (int n = 0; n < 2; n++)
            #pragma unroll
            for (int i = 0; i < 4; i++) acc[mt][n][i] = 0.f;

    #pragma unroll
    for (int kb = 0; kb < 8; kb++){
        int c0 = kb*16 + 2*q;
        float2 ai0 = *(const float2*)(Ai + c0);
        float2 ai1 = *(const float2*)(Ai + c0 + 8);
        float2 ca0 = *(const float2*)(C0 + c0);
        float2 ca1 = *(const float2*)(C0 + c0 + 8);
        float2 cb0 = *(const float2*)(C1 + c0);
        float2 cb1 = *(const float2*)(C1 + c0 + 8);
        unsigned b0h[2], b0l[2], b1h[2], b1l[2];
        split2(leaky(ai0.x + ca0.x), leaky(ai0.y + ca0.y), b0h[0], b0l[0]);
        split2(leaky(ai1.x + ca1.x), leaky(ai1.y + ca1.y), b0h[1], b0l[1]);
        split2(leaky(ai0.x + cb0.x), leaky(ai0.y + cb0.y), b1h[0], b1l[0]);
        split2(leaky(ai1.x + cb1.x), leaky(ai1.y + cb1.y), b1h[1], b1l[1]);
        #pragma unroll
        for (int mt = 0; mt < 4; mt++){
            uint4 H = __ldg(&g_w2Ah[(mt*8 + kb)*32 + lane]);
            uint4 L = __ldg(&g_w2Al[(mt*8 + kb)*32 + lane]);
            mma16(acc[mt][0], (const unsigned*)&H, b0h);
            mma16(acc[mt][0], (const unsigned*)&H, b0l);
            mma16(acc[mt][0], (const unsigned*)&L, b0h);
            mma16(acc[mt][1], (const unsigned*)&H, b1h);
            mma16(acc[mt][1], (const unsigned*)&H, b1l);
            mma16(acc[mt][1], (const unsigned*)&L, b1h);
        }
    }

    #pragma unroll
    for (int mt = 0; mt < 4; mt++){
        float m0 = fmaxf(fmaxf(acc[mt][0][0], acc[mt][0][1]),
                         fmaxf(acc[mt][1][0], acc[mt][1][1]));
        float m1 = fmaxf(fmaxf(acc[mt][0][2], acc[mt][0][3]),
                         fmaxf(acc[mt][1][2], acc[mt][1][3]));
        m0 = fmaxf(m0, __shfl_xor_sync(0xffffffffu, m0, 1));
        m0 = fmaxf(m0, __shfl_xor_sync(0xffffffffu, m0, 2));
        m1 = fmaxf(m1, __shfl_xor_sync(0xffffffffu, m1, 1));
        m1 = fmaxf(m1, __shfl_xor_sync(0xffffffffu, m1, 2));
        if (q == 0){
            int ch = mt*16 + r;
            g_x2[(size_t)node*64 + ch]     = leaky(m0 + __ldg(bias + ch));
            g_x2[(size_t)node*64 + ch + 8] = leaky(m1 + __ldg(bias + ch + 8));
        }
    }
}

__device__ __forceinline__ float featval(int node, int d){
    if (d < 5)   return g_xx[node*5 + d];
    if (d < 69)  return g_x1[(size_t)node*64 + d - 5];
    if (d < 133) return g_x2[(size_t)node*64 + d - 69];
    return 0.f;
}

// ---------------- lin1: [BN x 144] @ [144 x 512] + leaky (bf16) --------------
__global__ void k_lin1(const float* __restrict__ bl1){
    __shared__ unsigned CSh[64*76];
    __shared__ unsigned CSl[64*76];
    int t = threadIdx.x, lane = t & 31, w = t >> 5;
    int base = blockIdx.x*64;
    for (int i = t; i < 64*72; i += 256){
        int m = i / 72, p = i - m*72;
        int node = base + m;
        float v0 = featval(node, 2*p);
        float v1 = featval(node, 2*p + 1);
        unsigned h, l;
        split2(v0, v1, h, l);
        CSh[m*76 + p] = h;
        CSl[m*76 + p] = l;
    }
    __syncthreads();

    int r = lane >> 2, q = lane & 3;
    int n0 = w*64;
    for (int np = 0; np < 2; np++){
        float acc[4][4][4];
        #pragma unroll
        for (int mt = 0; mt < 4; mt++)
            #pragma unroll
            for (int nt = 0; nt < 4; nt++)
                #pragma unroll
                for (int i = 0; i < 4; i++) acc[mt][nt][i] = 0.f;

        for (int kb = 0; kb < 9; kb++){
            unsigned ah[4][4], al[4][4];
            #pragma unroll
            for (int mt = 0; mt < 4; mt++){
                int rb = mt*16;
                ah[mt][0] = CSh[(rb+r)*76 + kb*8 + q];       al[mt][0] = CSl[(rb+r)*76 + kb*8 + q];
                ah[mt][1] = CSh[(rb+r+8)*76 + kb*8 + q];     al[mt][1] = CSl[(rb+r+8)*76 + kb*8 + q];
                ah[mt][2] = CSh[(rb+r)*76 + kb*8 + 4 + q];   al[mt][2] = CSl[(rb+r)*76 + kb*8 + 4 + q];
                ah[mt][3] = CSh[(rb+r+8)*76 + kb*8 + 4 + q]; al[mt][3] = CSl[(rb+r+8)*76 + kb*8 + 4 + q];
            }
            #pragma unroll
            for (int nt = 0; nt < 4; nt++){
                uint4 wv = __ldg(&g_wl1pb[(kb*64 + w*8 + np*4 + nt)*32 + lane]);
                unsigned bh[2] = {wv.x, wv.y};
                unsigned bl[2] = {wv.z, wv.w};
                #pragma unroll
                for (int mt = 0; mt < 4; mt++){
                    mma16(acc[mt][nt], ah[mt], bh);
                    mma16(acc[mt][nt], ah[mt], bl);
                    mma16(acc[mt][nt], al[mt], bh);
                }
            }
        }
        #pragma unroll
        for (int mt = 0; mt < 4; mt++){
            #pragma unroll
            for (int nt = 0; nt < 4; nt++){
                int node = base + mt*16 + r;
                int col = n0 + (np*4 + nt)*8 + q*2;
                float b0 = __ldg(bl1 + col), b1 = __ldg(bl1 + col + 1);
                float2 u0, u1;
                u0.x = leaky(acc[mt][nt][0] + b0); u0.y = leaky(acc[mt][nt][1] + b1);
                u1.x = leaky(acc[mt][nt][2] + b0); u1.y = leaky(acc[mt][nt][3] + b1);
                *(float2*)(g_hs + (size_t)node*512 + col)     = u0;
                *(float2*)(g_hs + (size_t)(node+8)*512 + col) = u1;
            }
        }
    }
}

// ---------------- lin2: [BN x 512] @ [512 x 256] + max-pool (bf16) -----------
__global__ void k_lin2(const float* __restrict__ bl2){
    __shared__ unsigned Ash[64*36];
    __shared__ unsigned Asl[64*36];
    int t = threadIdx.x, lane = t & 31, w = t >> 5;
    int base = blockIdx.x*64;
    int g = base / NN;
    int r = lane >> 2, q = lane & 3;
    int n0 = w*32;

    float acc[4][4][4];
    #pragma unroll
    for (int mt = 0; mt < 4; mt++)
        #pragma unroll
        for (int nt = 0; nt < 4; nt++)
            #pragma unroll
            for (int i = 0; i < 4; i++) acc[mt][nt][i] = 0.f;

    for (int kc = 0; kc < 512; kc += 64){
        __syncthreads();
        for (int i = t; i < 1024; i += 256){
            int m = i >> 4, sub = i & 15;
            float4 v = *(const float4*)(g_hs + (size_t)(base + m)*512 + kc + sub*4);
            unsigned h0, l0, h1, l1;
            split2(v.x, v.y, h0, l0);
            split2(v.z, v.w, h1, l1);
            Ash[m*36 + sub*2]     = h0;
            Ash[m*36 + sub*2 + 1] = h1;
            Asl[m*36 + sub*2]     = l0;
            Asl[m*36 + sub*2 + 1] = l1;
        }
        __syncthreads();
        #pragma unroll
        for (int kb = 0; kb < 4; kb++){
            unsigned ah[4][4], al[4][4];
            #pragma unroll
            for (int mt = 0; mt < 4; mt++){
                int rb = mt*16;
                ah[mt][0] = Ash[(rb+r)*36 + kb*8 + q];       al[mt][0] = Asl[(rb+r)*36 + kb*8 + q];
                ah[mt][1] = Ash[(rb+r+8)*36 + kb*8 + q];     al[mt][1] = Asl[(rb+r+8)*36 + kb*8 + q];
                ah[mt][2] = Ash[(rb+r)*36 + kb*8 + 4 + q];   al[mt][2] = Asl[(rb+r)*36 + kb*8 + 4 + q];
                ah[mt][3] = Ash[(rb+r+8)*36 + kb*8 + 4 + q]; al[mt][3] = Asl[(rb+r+8)*36 + kb*8 + 4 + q];
            }
            int kbg = (kc >> 4) + kb;
            #pragma unroll
            for (int nt = 0; nt < 4; nt++){
                uint4 wv = __ldg(&g_wl2pb[(kbg*32 + w*4 + nt)*32 + lane]);
                unsigned bh[2] = {wv.x, wv.y};
                unsigned bl[2] = {wv.z, wv.w};
                #pragma unroll
                for (int mt = 0; mt < 4; mt++){
                    mma16(acc[mt][nt], ah[mt], bh);
                    mma16(acc[mt][nt], ah[mt], bl);
                    mma16(acc[mt][nt], al[mt], bh);
                }
            }
        }
    }

    #pragma unroll
    for (int nt = 0; nt < 4; nt++){
        float m0 = -3.4e38f, m1 = -3.4e38f;
        #pragma unroll
        for (int mt = 0; mt < 4; mt++){
            m0 = fmaxf(m0, fmaxf(acc[mt][nt][0], acc[mt][nt][2]));
            m1 = fmaxf(m1, fmaxf(acc[mt][nt][1], acc[mt][nt][3]));
        }
        #pragma unroll
        for (int off = 4; off < 32; off <<= 1){
            m0 = fmaxf(m0, __shfl_xor_sync(0xffffffffu, m0, off));
            m1 = fmaxf(m1, __shfl_xor_sync(0xffffffffu, m1, off));
        }
        if (lane < 4){
            int col = n0 + nt*8 + lane*2;
            atomicMaxFloat(&g_pool[g*256 + col],     m0 + __ldg(bl2 + col));
            atomicMaxFloat(&g_pool[g*256 + col + 1], m1 + __ldg(bl2 + col + 1));
        }
    }
}

// ---------------- head: leaky -> 256x128 -> leaky -> 128x3 -------------------
__global__ void k_head(const float* __restrict__ wm1, const float* __restrict__ bm1,
                       const float* __restrict__ wm2, const float* __restrict__ bm2,
                       float* __restrict__ out){
    __shared__ float gs[256];
    __shared__ float ms[128];
    int b = blockIdx.x, t = threadIdx.x;
    for (int c = t; c < 256; c += 128) gs[c] = leaky(g_pool[b*256 + c]);
    __syncthreads();
    float acc = bm1[t];
    #pragma unroll 8
    for (int d = 0; d < 256; d++) acc += gs[d]*wm1[d*128 + t];
    ms[t] = leaky(acc);
    __syncthreads();
    if (t < 3){
        float o = bm2[t];
        #pragma unroll 8
        for (int d = 0; d < 128; d++) o += ms[d]*wm2[d*3 + t];
        out[b*3 + t] = o;
    }
}

// -----------------------------------------------------------------------------
extern "C" void kernel_launch(void* const* d_in, const int* in_sizes, int n_in,
                              void* d_out, int out_size){
    const float* x   = (const float*)d_in[0];
    const float* pos = (const float*)d_in[1];
    const float* tq  = (const float*)d_in[2];
    const float* w1a = (const float*)d_in[4];
    const float* b1a = (const float*)d_in[5];
    const float* w1b = (const float*)d_in[6];
    const float* b1b = (const float*)d_in[7];
    const float* w2a = (const float*)d_in[8];
    const float* b2a = (const float*)d_in[9];
    const float* w2b = (const float*)d_in[10];
    const float* b2b = (const float*)d_in[11];
    const float* wl1 = (const float*)d_in[12];
    const float* bl1 = (const float*)d_in[13];
    const float* wl2 = (const float*)d_in[14];
    const float* bl2 = (const float*)d_in[15];
    const float* wm1 = (const float*)d_in[16];
    const float* bm1 = (const float*)d_in[17];
    const float* wm2 = (const float*)d_in[18];
    const float* bm2 = (const float*)d_in[19];
    float* out = (float*)d_out;

    // prep (weights, pool) + build (xx, sq5) — independent, one launch
    k_prepbuild<<<208 + BN/256, 256>>>(w1b, w2b, wl1, wl2, x, pos, tq);

    // conv1: kNN5 || convA1 (independent given xx), then edge
    k_knn5A1<<<8192 + (BN*64)/256, 256>>>(w1a, b1a);
    k_edge64<<<BN/8, 256>>>(b1b);        // also emits g_sq

    // conv2: d2-GEMM || convA2 (both depend only on x1/g_sq), then select+edge
    k_d2A2<<<2048 + BN/16, 256>>>(w2a, b2a);
    k_select<<<BN/8, 256>>>();
    k_edge128<<<BN/8, 256>>>(b2b);

    // lin1 -> g_hs, lin2 + fused pool, head
    k_lin1<<<BN/64, 256>>>(bl1);
    k_lin2<<<BN/64, 256>>>(bl2);
    k_head<<<BATCH, 128>>>(wm1, bm1, wm2, bm2, out);
}

// round 14
// speedup vs baseline: 1.0284x; 1.0213x over previous
#include <cuda_runtime.h>
#include <cuda_bf16.h>
#include <cstdint>

#define BATCH 128
#define NN    512
#define KNB   16
#define BN    (BATCH*NN)
#define NEGS  0.01f

// ---------------- scratch (device globals; no allocation allowed) -------------
__device__ float g_xx[BN*5];
__device__ float g_x1[BN*64];
__device__ float g_x2[BN*64];
__device__ int   g_idx[BN*KNB];
__device__ float g_A[(size_t)BN*128];
__device__ float g_C[(size_t)BN*128];
__device__ float g_pool[BATCH*256];
__device__ float g_sq[BN];
__device__ float g_sq5[BN];
__device__ float g_d2[(size_t)BN*NN];   // pairwise distances (conv2 kNN)
__device__ float g_hs[(size_t)BN*512];  // lin1 -> lin2 buffer

// W^T A-operand fragment tables for edge kernels (indexed (mt*8+kb)*32+lane)
__device__ uint4 g_w1Ah[1024], g_w1Al[1024];   // conv1 W2 (64x64), tf32 split
__device__ uint4 g_w2Ah[1024], g_w2Al[1024];   // conv2 W2 (128x64), bf16 split
// bf16 split fragment-packed B-operand weights for lin kernels
__device__ uint4  g_wl1pb[9*64*32];      // 144x512 (rows >=133 zero)
__device__ uint4  g_wl2pb[32*32*32];     // 512x256

__device__ __forceinline__ float leaky(float v){ return v > 0.f ? v : NEGS*v; }

__device__ __forceinline__ void atomicMaxFloat(float* addr, float value){
    if (value >= 0.f) atomicMax((int*)addr, __float_as_int(value));
    else              atomicMin((unsigned int*)addr, __float_as_uint(value));
}

__device__ __forceinline__ unsigned f2tf(float x){
    unsigned u; asm("cvt.rna.tf32.f32 %0, %1;" : "=r"(u) : "f"(x)); return u;
}
__device__ __forceinline__ void splt(float x, unsigned &h, unsigned &l){
    h = f2tf(x);
    l = f2tf(x - __uint_as_float(h));
}
__device__ __forceinline__ void mma8(float* c, const unsigned* a, const unsigned* b){
    asm("mma.sync.aligned.m16n8k8.row.col.f32.tf32.tf32.f32 "
        "{%0,%1,%2,%3}, {%4,%5,%6,%7}, {%8,%9}, {%0,%1,%2,%3};"
        : "+f"(c[0]), "+f"(c[1]), "+f"(c[2]), "+f"(c[3])
        : "r"(a[0]), "r"(a[1]), "r"(a[2]), "r"(a[3]), "r"(b[0]), "r"(b[1]));
}
__device__ __forceinline__ void mma16(float* c, const unsigned* a, const unsigned* b){
    asm("mma.sync.aligned.m16n8k16.row.col.f32.bf16.bf16.f32 "
        "{%0,%1,%2,%3}, {%4,%5,%6,%7}, {%8,%9}, {%0,%1,%2,%3};"
        : "+f"(c[0]), "+f"(c[1]), "+f"(c[2]), "+f"(c[3])
        : "r"(a[0]), "r"(a[1]), "r"(a[2]), "r"(a[3]), "r"(b[0]), "r"(b[1]));
}
__device__ __forceinline__ unsigned packbf(float v0, float v1){
    unsigned d; asm("cvt.rn.bf16x2.f32 %0, %1, %2;" : "=r"(d) : "f"(v1), "f"(v0)); return d;
}
__device__ __forceinline__ float bflo(unsigned p){ return __uint_as_float(p << 16); }
__device__ __forceinline__ float bfhi(unsigned p){ return __uint_as_float(p & 0xffff0000u); }
__device__ __forceinline__ void split2(float v0, float v1, unsigned &h, unsigned &l){
    h = packbf(v0, v1);
    l = packbf(v0 - bflo(h), v1 - bfhi(h));
}

// sortable-u32 transform
__device__ __forceinline__ unsigned fsort(float f){
    unsigned b = __float_as_uint(f);
    return b ^ (((int)b >> 31) | 0x80000000u);
}

// index mappings for sel16 slot u on lane:
// MODE 0: j = u*32 + lane   (knn5)
// MODE 1: j = lane*16 + u   (select from contiguous row)
template<int MODE>
__device__ __forceinline__ int sel_j(int lane, int u){
    if (MODE == 0) return u*32 + lane;
    return lane*16 + u;
}
template<int MODE>
__device__ __forceinline__ int sel_u(int j){
    if (MODE == 0) return j >> 5;
    return j & 15;
}

// warp-cooperative exact top-16-of-512 with lower-index tiebreak.
template<int MODE>
__device__ __forceinline__ void sel16(const float* v, int lane, int* out){
    const unsigned long long INF = ~0ull;
    unsigned long long s0 = INF, s1 = INF, s2 = INF, s3 = INF;
    #pragma unroll
    for (int u = 0; u < 16; u++){
        int j = sel_j<MODE>(lane, u);
        unsigned long long k = ((unsigned long long)fsort(v[u]) << 32) | (unsigned)j;
        if (k < s3){
            s3 = k;
            if (s3 < s2){ unsigned long long t = s2; s2 = s3; s3 = t; }
            if (s2 < s1){ unsigned long long t = s1; s1 = s2; s2 = t; }
            if (s1 < s0){ unsigned long long t = s0; s0 = s1; s1 = t; }
        }
    }
    unsigned mask = 0;
    int mine = 0;
    #pragma unroll 1
    for (int r = 0; r < KNB; r++){
        unsigned long long m = s0;
        #pragma unroll
        for (int off = 16; off; off >>= 1){
            unsigned long long o = __shfl_xor_sync(0xffffffffu, m, off);
            if (o < m) m = o;
        }
        if (lane == r) mine = (int)(unsigned)(m & 0xffffffffu);
        if (s0 == m){
            int j = (int)(unsigned)(m & 0xffffffffu);
            mask |= 1u << sel_u<MODE>(j);
            s0 = s1; s1 = s2; s2 = s3; s3 = INF;
            if (s0 == INF && mask != 0xffffu){
                #pragma unroll
                for (int u2 = 0; u2 < 16; u2++){
                    if (!((mask >> u2) & 1u)){
                        int j2 = sel_j<MODE>(lane, u2);
                        unsigned long long k = ((unsigned long long)fsort(v[u2]) << 32) | (unsigned)j2;
                        if (k < s3){
                            s3 = k;
                            if (s3 < s2){ unsigned long long t = s2; s2 = s3; s3 = t; }
                            if (s2 < s1){ unsigned long long t = s1; s1 = s2; s2 = t; }
                            if (s1 < s0){ unsigned long long t = s0; s0 = s1; s1 = t; }
                        }
                    }
                }
            }
        }
    }
    if (lane < KNB) out[lane] = mine;
}

// ---------------- fused prep (weight packing + pool init) + build ------------
__global__ void k_prepbuild(const float* __restrict__ w1b, const float* __restrict__ w2b,
                            const float* __restrict__ wl1, const float* __restrict__ wl2,
                            const float* __restrict__ x, const float* __restrict__ pos,
                            const float* __restrict__ tq){
    if (blockIdx.x < 208){
        int i = blockIdx.x*256 + threadIdx.x;
        if (i < BATCH*256) g_pool[i] = __int_as_float(0xff800000); // -inf
        if (i < 1024){
            int lane = i & 31, tmp = i >> 5;
            int kb = tmp & 7, mt = tmp >> 3;
            int r = lane >> 2, q = lane & 3;
            int R = mt*16 + r, k0 = kb*8 + q;
            uint4 H, L;
            splt(w1b[k0*64 + R],       H.x, L.x);
            splt(w1b[k0*64 + R + 8],   H.y, L.y);
            splt(w1b[(k0+4)*64 + R],   H.z, L.z);
            splt(w1b[(k0+4)*64 + R+8], H.w, L.w);
            g_w1Ah[i] = H; g_w1Al[i] = L;
        } else if (i < 2048){
            int rel = i - 1024;
            int lane = rel & 31, tmp = rel >> 5;
            int kb = tmp & 7, mt = tmp >> 3;
            int r = lane >> 2, q = lane & 3;
            int R = mt*16 + r, c0 = kb*16 + 2*q;
            uint4 H, L;
            split2(w2b[c0*64 + R],       w2b[(c0+1)*64 + R],     H.x, L.x);
            split2(w2b[c0*64 + R + 8],   w2b[(c0+1)*64 + R + 8], H.y, L.y);
            split2(w2b[(c0+8)*64 + R],   w2b[(c0+9)*64 + R],     H.z, L.z);
            split2(w2b[(c0+8)*64 + R+8], w2b[(c0+9)*64 + R + 8], H.w, L.w);
            g_w2Ah[rel] = H; g_w2Al[rel] = L;
        } else if (i < 53248){
            const float* W; uint4* dst; int ncb, ncols, nrows, rel;
            if (i < 20480){ rel = i - 2048;  W = wl1; dst = g_wl1pb; ncb = 64; ncols = 512; nrows = 133; }
            else          { rel = i - 20480; W = wl2; dst = g_wl2pb; ncb = 32; ncols = 256; nrows = 512; }
            int lane = rel & 31, tmp = rel >> 5;
            int cb = tmp % ncb, kb = tmp / ncb;
            int r = lane >> 2, q = lane & 3, col = cb*8 + r;
            int k0 = kb*16 + 2*q;
            float v00 = (k0     < nrows) ? W[(k0    )*ncols + col] : 0.f;
            float v01 = (k0 + 1 < nrows) ? W[(k0 + 1)*ncols + col] : 0.f;
            float v10 = (k0 + 8 < nrows) ? W[(k0 + 8)*ncols + col] : 0.f;
            float v11 = (k0 + 9 < nrows) ? W[(k0 + 9)*ncols + col] : 0.f;
            unsigned h0, l0, h1, l1;
            split2(v00, v01, h0, l0);
            split2(v10, v11, h1, l1);
            dst[rel] = make_uint4(h0, h1, l0, l1);
        }
    } else {
        int i = (blockIdx.x - 208)*256 + threadIdx.x;
        if (i < BN){
            float tv = tq[i], xv = x[i];
            float p0 = pos[i*3+0], p1 = pos[i*3+1], p2 = pos[i*3+2];
            g_xx[i*5+0] = tv;
            g_xx[i*5+1] = xv;
            g_xx[i*5+2] = p0;
            g_xx[i*5+3] = p1;
            g_xx[i*5+4] = p2;
            g_sq5[i] = tv*tv + xv*xv + p0*p0 + p1*p1 + p2*p2;
        }
    }
}

// ---------------- fused kNN d=5 + conv1 layer-1 ------------------------------
__global__ void k_knn5A1(const float* __restrict__ W, const float* __restrict__ bias){
    __shared__ float tile[128*8];
    if (blockIdx.x < 8192){
        int b  = blockIdx.x >> 6;
        int q0 = (blockIdx.x & 63) * 8;
        int warp = threadIdx.x >> 5, lane = threadIdx.x & 31;
        int qi = q0 + warp;
        int node = b*NN + qi;
        const float* Fb = g_xx + (size_t)b*NN*5;

        float f0, f1, f2, f3, f4;
        { const float* fq = Fb + qi*5; f0=fq[0]; f1=fq[1]; f2=fq[2]; f3=fq[3]; f4=fq[4]; }
        float sqi = g_sq5[node];

        float d2loc[16];
        for (int t4 = 0; t4 < 4; t4++){
            __syncthreads();
            for (int idx = threadIdx.x; idx < 1024; idx += 256){
                int rrow = idx >> 3, c = idx & 7;
                int grow = t4*128 + rrow;
                float v = 0.f;
                if (c < 5)       v = Fb[grow*5 + c];
                else if (c == 5) v = g_sq5[b*NN + grow];
                tile[idx] = v;
            }
            __syncthreads();
            #pragma unroll
            for (int u = 0; u < 4; u++){
                int jj = u*32 + lane;
                const float* tr = &tile[jj*8];
                float4 p  = *(const float4*)tr;
                float2 p2 = *(const float2*)(tr + 4);
                float dot = f0*p.x + f1*p.y + f2*p.z + f3*p.w + f4*p2.x;
                d2loc[t4*4 + u] = sqi + p2.y - 2.f*dot;
            }
        }
        sel16<0>(d2loc, lane, g_idx + (size_t)node*KNB);
    } else {
        int t = (blockIdx.x - 8192)*256 + threadIdx.x;
        if (t >= BN*64) return;
        int i = t >> 6, c = t & 63;
        const float* f = g_xx + (size_t)i*5;
        float a = bias[c], cc = 0.f;
        #pragma unroll
        for (int d = 0; d < 5; d++){
            float v  = f[d];
            float wt = W[d*64 + c];
            float wb = W[(5 + d)*64 + c];
            a  += v*(wt - wb);
            cc += v*wb;
        }
        g_A[(size_t)i*64 + c] = a;
        g_C[(size_t)i*64 + c] = cc;
    }
}

// ------- fused SYMMETRIC d2-GEMM (split-tf32, upper triangle) + conv2 L1 -----
// blocks [0, 1280): 10 upper-triangle 128x128 tiles per graph:
//   tt: 0..3 -> (0, tt) ; 4..6 -> (1, tt-3) ; 7..8 -> (2, tt-5) ; 9 -> (3,3)
// Off-diagonal tiles also write the mirrored block via smem transpose.
__global__ void k_d2A2(const float* __restrict__ W, const float* __restrict__ bias){
    __shared__ float SU[9216];     // union: d2 As/Bs | transpose buf | convA2 Wd/Wb/Fs
    int t = threadIdx.x;
    if (blockIdx.x < 1280){
        float* As = SU;            // [128*36]
        float* Bs = SU + 4608;     // [128*36]
        int blk = blockIdx.x;
        int b = blk / 10;
        int tt = blk - b*10;
        int ti, tj;
        if (tt < 4)      { ti = 0; tj = tt; }
        else if (tt < 7) { ti = 1; tj = tt - 3; }
        else if (tt < 9) { ti = 2; tj = tt - 5; }
        else             { ti = 3; tj = 3; }
        int i0 = ti*128, j0 = tj*128;
        const float* Fb = g_x1 + (size_t)b*NN*64;
        int lane = t & 31, w = t >> 5;
        int wx = w & 1, wy = w >> 1;
        int r = lane >> 2, q = lane & 3;

        float acc[2][8][4];
        #pragma unroll
        for (int mt = 0; mt < 2; mt++)
            #pragma unroll
            for (int nt = 0; nt < 8; nt++)
                #pragma unroll
                for (int i = 0; i < 4; i++) acc[mt][nt][i] = 0.f;

        for (int kc = 0; kc < 64; kc += 32){
            __syncthreads();
            for (int i = t; i < 128*8; i += 256){
                int m = i >> 3, kq = (i & 7)*4;
                *(float4*)&As[m*36 + kq] = *(const float4*)(Fb + (i0+m)*64 + kc + kq);
                *(float4*)&Bs[m*36 + kq] = *(const float4*)(Fb + (j0+m)*64 + kc + kq);
            }
            __syncthreads();
            #pragma unroll
            for (int k0 = 0; k0 < 32; k0 += 8){
                unsigned ah[2][4], al[2][4];
                #pragma unroll
                for (int mt = 0; mt < 2; mt++){
                    int row = wy*32 + mt*16;
                    splt(As[(row+r)*36 + k0 + q],       ah[mt][0], al[mt][0]);
                    splt(As[(row+r+8)*36 + k0 + q],     ah[mt][1], al[mt][1]);
                    splt(As[(row+r)*36 + k0 + q + 4],   ah[mt][2], al[mt][2]);
                    splt(As[(row+r+8)*36 + k0 + q + 4], ah[mt][3], al[mt][3]);
                }
                #pragma unroll
                for (int nt = 0; nt < 8; nt++){
                    int col = wx*64 + nt*8;
                    unsigned bh[2], bl[2];
                    splt(Bs[(col+r)*36 + k0 + q],     bh[0], bl[0]);
                    splt(Bs[(col+r)*36 + k0 + q + 4], bh[1], bl[1]);
                    #pragma unroll
                    for (int mt = 0; mt < 2; mt++){
                        mma8(acc[mt][nt], ah[mt], bh);
                        mma8(acc[mt][nt], ah[mt], bl);
                        mma8(acc[mt][nt], al[mt], bh);
                    }
                }
            }
        }

        // direct write (rows i0-block, cols j0-block)
        float si0[2], si1[2];
        #pragma unroll
        for (int mt = 0; mt < 2; mt++){
            int rowb = i0 + wy*32 + mt*16;
            si0[mt] = g_sq[b*NN + rowb + r];
            si1[mt] = g_sq[b*NN + rowb + r + 8];
            #pragma unroll
            for (int nt = 0; nt < 8; nt++){
                int colb = j0 + wx*64 + nt*8 + 2*q;
                float sj0 = g_sq[b*NN + colb], sj1 = g_sq[b*NN + colb + 1];
                float2 v0, v1;
                v0.x = si0[mt] + sj0 - 2.f*acc[mt][nt][0];
                v0.y = si0[mt] + sj1 - 2.f*acc[mt][nt][1];
                v1.x = si1[mt] + sj0 - 2.f*acc[mt][nt][2];
                v1.y = si1[mt] + sj1 - 2.f*acc[mt][nt][3];
                *(float2*)(g_d2 + (size_t)(b*NN + i0 + wy*32 + mt*16 + r)*NN + colb)     = v0;
                *(float2*)(g_d2 + (size_t)(b*NN + i0 + wy*32 + mt*16 + r + 8)*NN + colb) = v1;
            }
        }

        // mirrored write for off-diagonal tiles: stage 64 cols x 128 rows, twice.
        // Tb stride 132 floats: 132 % 4 == 0 so float4 reads at row*132 + 4k are
        // 16B-aligned; 132 % 32 == 4 keeps the read phase conflict-free.
        if (i0 != j0){
            float* Tb = SU;        // [64][132] = 8448 floats < 9216
            for (int h = 0; h < 2; h++){
                __syncthreads();
                if (wx == h){
                    #pragma unroll
                    for (int mt = 0; mt < 2; mt++){
                        int rowl = wy*32 + mt*16;
                        #pragma unroll
                        for (int nt = 0; nt < 8; nt++){
                            int coll = nt*8 + 2*q;          // 0..63 within half
                            int colb = j0 + h*64 + coll;
                            float sj0 = g_sq[b*NN + colb], sj1 = g_sq[b*NN + colb + 1];
                            Tb[(coll    )*132 + rowl + r]     = si0[mt] + sj0 - 2.f*acc[mt][nt][0];
                            Tb[(coll + 1)*132 + rowl + r]     = si0[mt] + sj1 - 2.f*acc[mt][nt][1];
                            Tb[(coll    )*132 + rowl + r + 8] = si1[mt] + sj0 - 2.f*acc[mt][nt][2];
                            Tb[(coll + 1)*132 + rowl + r + 8] = si1[mt] + sj1 - 2.f*acc[mt][nt][3];
                        }
                    }
                }
                __syncthreads();
                for (int i = t; i < 64*32; i += 256){
                    int row = i >> 5, c4 = (i & 31)*4;
                    float4 v = *(const float4*)&Tb[row*132 + c4];
                    *(float4*)(g_d2 + (size_t)(b*NN + j0 + h*64 + row)*NN + i0 + c4) = v;
                }
            }
        }
    } else {
        float* Wd = SU;            // [32*128]
        float* Wb = SU + 4096;     // [32*128]
        float* Fs = SU + 8192;     // [16*64]
        int base = (blockIdx.x - 1280)*16;

        for (int idx = t; idx < 1024; idx += 256)
            Fs[idx] = g_x1[(size_t)base*64 + idx];

        int m  = t >> 4;
        int cg = (t & 15)*8;
        float a[8], cc[8];
        float4 bb0 = *(const float4*)(bias + cg);
        float4 bb1 = *(const float4*)(bias + cg + 4);
        a[0]=bb0.x; a[1]=bb0.y; a[2]=bb0.z; a[3]=bb0.w;
        a[4]=bb1.x; a[5]=bb1.y; a[6]=bb1.z; a[7]=bb1.w;
        #pragma unroll
        for (int q = 0; q < 8; q++) cc[q] = 0.f;

        for (int db = 0; db < 64; db += 32){
            __syncthreads();
            for (int idx = t; idx < 4096; idx += 256){
                int d = idx >> 7, c = idx & 127;
                float wt = W[(db + d)*128 + c];
                float wb = W[(64 + db + d)*128 + c];
                Wd[idx] = wt - wb;
                Wb[idx] = wb;
            }
            __syncthreads();
            #pragma unroll 4
            for (int d = 0; d < 32; d++){
                float v = Fs[m*64 + db + d];
                float4 w0 = *(const float4*)&Wd[d*128 + cg];
                float4 w1 = *(const float4*)&Wd[d*128 + cg + 4];
                float4 u0 = *(const float4*)&Wb[d*128 + cg];
                float4 u1 = *(const float4*)&Wb[d*128 + cg + 4];
                a[0] += v*w0.x; a[1] += v*w0.y; a[2] += v*w0.z; a[3] += v*w0.w;
                a[4] += v*w1.x; a[5] += v*w1.y; a[6] += v*w1.z; a[7] += v*w1.w;
                cc[0] += v*u0.x; cc[1] += v*u0.y; cc[2] += v*u0.z; cc[3] += v*u0.w;
                cc[4] += v*u1.x; cc[5] += v*u1.y; cc[6] += v*u1.z; cc[7] += v*u1.w;
            }
        }
        int node = base + m;
        float4* pa = (float4*)(g_A + (size_t)node*128 + cg);
        float4* pc = (float4*)(g_C + (size_t)node*128 + cg);
        pa[0] = make_float4(a[0],a[1],a[2],a[3]);
        pa[1] = make_float4(a[4],a[5],a[6],a[7]);
        pc[0] = make_float4(cc[0],cc[1],cc[2],cc[3]);
        pc[1] = make_float4(cc[4],cc[5],cc[6],cc[7]);
    }
}

// ---------------- kNN d=64: cached-top4 select from g_d2 ---------------------
__global__ void k_select(){
    int warp = threadIdx.x >> 5, lane = threadIdx.x & 31;
    int node = blockIdx.x*8 + warp;
    const float* row = g_d2 + (size_t)node*NN;
    float v[16];
    #pragma unroll
    for (int u4 = 0; u4 < 4; u4++){
        float4 x = *(const float4*)(row + lane*16 + u4*4);
        v[u4*4+0] = x.x; v[u4*4+1] = x.y; v[u4*4+2] = x.z; v[u4*4+3] = x.w;
    }
    sel16<1>(v, lane, g_idx + (size_t)node*KNB);
}

// ---------------- conv1 edge layer-2: D^T = W^T @ h^T (tf32, no smem) --------
__global__ void k_edge64(const float* __restrict__ bias){
    int t = threadIdx.x, warp = t >> 5, lane = t & 31;
    int node = blockIdx.x*8 + warp;
    int b = node / NN;
    int r = lane >> 2, q = lane & 3;

    int j0 = b*NN + __ldg(g_idx + (size_t)node*KNB + r);
    int j1 = b*NN + __ldg(g_idx + (size_t)node*KNB + 8 + r);
    const float* Ai = g_A + (size_t)node*64;
    const float* C0 = g_C + (size_t)j0*64;
    const float* C1 = g_C + (size_t)j1*64;

    float acc[4][2][4];
    #pragma unroll
    for (int mt = 0; mt < 4; mt++)
        #pragma unroll
        for (int n = 0; n < 2; n++)
            #pragma unroll
            for (int i = 0; i < 4; i++) acc[mt][n][i] = 0.f;

    #pragma unroll
    for (int kb = 0; kb < 8; kb++){
        int c0 = kb*8 + q;
        float ai0 = __ldg(Ai + c0), ai1 = __ldg(Ai + c0 + 4);
        unsigned b0h[2], b0l[2], b1h[2], b1l[2];
        splt(leaky(ai0 + __ldg(C0 + c0)),     b0h[0], b0l[0]);
        splt(leaky(ai1 + __ldg(C0 + c0 + 4)), b0h[1], b0l[1]);
        splt(leaky(ai0 + __ldg(C1 + c0)),     b1h[0], b1l[0]);
        splt(leaky(ai1 + __ldg(C1 + c0 + 4)), b1h[1], b1l[1]);
        #pragma unroll
        for (int mt = 0; mt < 4; mt++){
            uint4 H = __ldg(&g_w1Ah[(mt*8 + kb)*32 + lane]);
            uint4 L = __ldg(&g_w1Al[(mt*8 + kb)*32 + lane]);
            mma8(acc[mt][0], (const unsigned*)&H, b0h);
            mma8(acc[mt][0], (const unsigned*)&H, b0l);
            mma8(acc[mt][0], (const unsigned*)&L, b0h);
            mma8(acc[mt][1], (const unsigned*)&H, b1h);
            mma8(acc[mt][1], (const unsigned*)&H, b1l);
            mma8(acc[mt][1], (const unsigned*)&L, b1h);
        }
    }

    float ssum = 0.f;
    #pragma unroll
    for (int mt = 0; mt < 4; mt++){
        float m0 = fmaxf(fmaxf(acc[mt][0][0], acc[mt][0][1]),
                         fmaxf(acc[mt][1][0], acc[mt][1][1]));
        float m1 = fmaxf(fmaxf(acc[mt][0][2], acc[mt][0][3]),
                         fmaxf(acc[mt][1][2], acc[mt][1][3]));
        m0 = fmaxf(m0, __shfl_xor_sync(0xffffffffu, m0, 1));
        m0 = fmaxf(m0, __shfl_xor_sync(0xffffffffu, m0, 2));
        m1 = fmaxf(m1, __shfl_xor_sync(0xffffffffu, m1, 1));
        m1 = fmaxf(m1, __shfl_xor_sync(0xffffffffu, m1, 2));
        if (q == 0){
            int ch = mt*16 + r;
            float v0 = leaky(m0 + __ldg(bias + ch));
            float v1 = leaky(m1 + __ldg(bias + ch + 8));
            g_x1[(size_t)node*64 + ch]     = v0;
            g_x1[(size_t)node*64 + ch + 8] = v1;
            ssum += v0*v0 + v1*v1;
        }
    }
    ssum += __shfl_xor_sync(0xffffffffu, ssum, 4);
    ssum += __shfl_xor_sync(0xffffffffu, ssum, 8);
    ssum += __shfl_xor_sync(0xffffffffu, ssum, 16);
    if (lane == 0) g_sq[node] = ssum;
}

// ---------------- conv2 edge layer-2: D^T = W^T @ h^T (bf16, no smem) --------
__global__ void k_edge128(const float* __restrict__ bias){
    int t = threadIdx.x, warp = t >> 5, lane = t & 31;
    int node = blockIdx.x*8 + warp;
    int b = node / NN;
    int r = lane >> 2, q = lane & 3;

    int j0 = b*NN + __ldg(g_idx + (size_t)node*KNB + r);
    int j1 = b*NN + __ldg(g_idx + (size_t)node*KNB + 8 + r);
    const float* Ai = g_A + (size_t)node*128;
    const float* C0 = g_C + (size_t)j0*128;
    const float* C1 = g_C + (size_t)j1*128;

    float acc[4][2][4];
    #pragma unroll
    for (int mt = 0; mt < 4; mt++)
        #pragma unroll
        for (int n = 0; n < 2; n++)
            #pragma unroll
            for (int i = 0; i < 4; i++) acc[mt][n][i] = 0.f;

    #pragma unroll
    for (int kb = 0; kb < 8; kb++){
        int c0 = kb*16 + 2*q;
        float2 ai0 = *(const float2*)(Ai + c0);
        float2 ai1 = *(const float2*)(Ai + c0 + 8);
        float2 ca0 = *(const float2*)(C0 + c0);
        float2 ca1 = *(const float2*)(C0 + c0 + 8);
        float2 cb0 = *(const float2*)(C1 + c0);
        float2 cb1 = *(const float2*)(C1 + c0 + 8);
        unsigned b0h[2], b0l[2], b1h[2], b1l[2];
        split2(leaky(ai0.x + ca0.x), leaky(ai0.y + ca0.y), b0h[0], b0l[0]);
        split2(leaky(ai1.x + ca1.x), leaky(ai1.y + ca1.y), b0h[1], b0l[1]);
        split2(leaky(ai0.x + cb0.x), leaky(ai0.y + cb0.y), b1h[0], b1l[0]);
        split2(leaky(ai1.x + cb1.x), leaky(ai1.y + cb1.y), b1h[1], b1l[1]);
        #pragma unroll
        for (int mt = 0; mt < 4; mt++){
            uint4 H = __ldg(&g_w2Ah[(mt*8 + kb)*32 + lane]);
            uint4 L = __ldg(&g_w2Al[(mt*8 + kb)*32 + lane]);
            mma16(acc[mt][0], (const unsigned*)&H, b0h);
            mma16(acc[mt][0], (const unsigned*)&H, b0l);
            mma16(acc[mt][0], (const unsigned*)&L, b0h);
            mma16(acc[mt][1], (const unsigned*)&H, b1h);
            mma16(acc[mt][1], (const unsigned*)&H, b1l);
            mma16(acc[mt][1], (const unsigned*)&L, b1h);
        }
    }

    #pragma unroll
    for (int mt = 0; mt < 4; mt++){
        float m0 = fmaxf(fmaxf(acc[mt][0][0], acc[mt][0][1]),
                         fmaxf(acc[mt][1][0], acc[mt][1][1]));
        float m1 = fmaxf(fmaxf(acc[mt][0][2], acc[mt][0][3]),
                         fmaxf(acc[mt][1][2], acc[mt][1][3]));
        m0 = fmaxf(m0, __shfl_xor_sync(0xffffffffu, m0, 1));
        m0 = fmaxf(m0, __shfl_xor_sync(0xffffffffu, m0, 2));
        m1 = fmaxf(m1, __shfl_xor_sync(0xffffffffu, m1, 1));
        m1 = fmaxf(m1, __shfl_xor_sync(0xffffffffu, m1, 2));
        if (q == 0){
            int ch = mt*16 + r;
            g_x2[(size_t)node*64 + ch]     = leaky(m0 + __ldg(bias + ch));
            g_x2[(size_t)node*64 + ch + 8] = leaky(m1 + __ldg(bias + ch + 8));
        }
    }
}

__device__ __forceinline__ float featval(int node, int d){
    if (d < 5)   return g_xx[node*5 + d];
    if (d < 69)  return g_x1[(size_t)node*64 + d - 5];
    if (d < 133) return g_x2[(size_t)node*64 + d - 69];
    return 0.f;
}

// ---------------- lin1: [BN x 144] @ [144 x 512] + leaky (bf16) --------------
__global__ void k_lin1(const float* __restrict__ bl1){
    __shared__ unsigned CSh[64*76];
    __shared__ unsigned CSl[64*76];
    int t = threadIdx.x, lane = t & 31, w = t >> 5;
    int base = blockIdx.x*64;
    for (int i = t; i < 64*72; i += 256){
        int m = i / 72, p = i - m*72;
        int node = base + m;
        float v0 = featval(node, 2*p);
        float v1 = featval(node, 2*p + 1);
        unsigned h, l;
        split2(v0, v1, h, l);
        CSh[m*76 + p] = h;
        CSl[m*76 + p] = l;
    }
    __syncthreads();

    int r = lane >> 2, q = lane & 3;
    int n0 = w*64;
    for (int np = 0; np < 2; np++){
        float acc[4][4][4];
        #pragma unroll
        for (int mt = 0; mt < 4; mt++)
            #pragma unroll
            for (int nt = 0; nt < 4; nt++)
                #pragma unroll
                for (int i = 0; i < 4; i++) acc[mt][nt][i] = 0.f;

        for (int kb = 0; kb < 9; kb++){
            unsigned ah[4][4], al[4][4];
            #pragma unroll
            for (int mt = 0; mt < 4; mt++){
                int rb = mt*16;
                ah[mt][0] = CSh[(rb+r)*76 + kb*8 + q];       al[mt][0] = CSl[(rb+r)*76 + kb*8 + q];
                ah[mt][1] = CSh[(rb+r+8)*76 + kb*8 + q];     al[mt][1] = CSl[(rb+r+8)*76 + kb*8 + q];
                ah[mt][2] = CSh[(rb+r)*76 + kb*8 + 4 + q];   al[mt][2] = CSl[(rb+r)*76 + kb*8 + 4 + q];
                ah[mt][3] = CSh[(rb+r+8)*76 + kb*8 + 4 + q]; al[mt][3] = CSl[(rb+r+8)*76 + kb*8 + 4 + q];
            }
            #pragma unroll
            for (int nt = 0; nt < 4; nt++){
                uint4 wv = __ldg(&g_wl1pb[(kb*64 + w*8 + np*4 + nt)*32 + lane]);
                unsigned bh[2] = {wv.x, wv.y};
                unsigned bl[2] = {wv.z, wv.w};
                #pragma unroll
                for (int mt = 0; mt < 4; mt++){
                    mma16(acc[mt][nt], ah[mt], bh);
                    mma16(acc[mt][nt], ah[mt], bl);
                    mma16(acc[mt][nt], al[mt], bh);
                }
            }
        }
        #pragma unroll
        for (int mt = 0; mt < 4; mt++){
            #pragma unroll
            for (int nt = 0; nt < 4; nt++){
                int node = base + mt*16 + r;
                int col = n0 + (np*4 + nt)*8 + q*2;
                float b0 = __ldg(bl1 + col), b1 = __ldg(bl1 + col + 1);
                float2 u0, u1;
                u0.x = leaky(acc[mt][nt][0] + b0); u0.y = leaky(acc[mt][nt][1] + b1);
                u1.x = leaky(acc[mt][nt][2] + b0); u1.y = leaky(acc[mt][nt][3] + b1);
                *(float2*)(g_hs + (size_t)node*512 + col)     = u0;
                *(float2*)(g_hs + (size_t)(node+8)*512 + col) = u1;
            }
        }
    }
}

// ---------------- lin2: [BN x 512] @ [512 x 256] + max-pool (bf16) -----------
__global__ void k_lin2(const float* __restrict__ bl2){
    __shared__ unsigned Ash[64*36];
    __shared__ unsigned Asl[64*36];
    int t = threadIdx.x, lane = t & 31, w = t >> 5;
    int base = blockIdx.x*64;
    int g = base / NN;
    int r = lane >> 2, q = lane & 3;
    int n0 = w*32;

    float acc[4][4][4];
    #pragma unroll
    for (int mt = 0; mt < 4; mt++)
        #pragma unroll
        for (int nt = 0; nt < 4; nt++)
            #pragma unroll
            for (int i = 0; i < 4; i++) acc[mt][nt][i] = 0.f;

    for (int kc = 0; kc < 512; kc += 64){
        __syncthreads();
        for (int i = t; i < 1024; i += 256){
            int m = i >> 4, sub = i & 15;
            float4 v = *(const float4*)(g_hs + (size_t)(base + m)*512 + kc + sub*4);
            unsigned h0, l0, h1, l1;
            split2(v.x, v.y, h0, l0);
            split2(v.z, v.w, h1, l1);
            Ash[m*36 + sub*2]     = h0;
            Ash[m*36 + sub*2 + 1] = h1;
            Asl[m*36 + sub*2]     = l0;
            Asl[m*36 + sub*2 + 1] = l1;
        }
        __syncthreads();
        #pragma unroll
        for (int kb = 0; kb < 4; kb++){
            unsigned ah[4][4], al[4][4];
            #pragma unroll
            for (int mt = 0; mt < 4; mt++){
                int rb = mt*16;
                ah[mt][0] = Ash[(rb+r)*36 + kb*8 + q];       al[mt][0] = Asl[(rb+r)*36 + kb*8 + q];
                ah[mt][1] = Ash[(rb+r+8)*36 + kb*8 + q];     al[mt][1] = Asl[(rb+r+8)*36 + kb*8 + q];
                ah[mt][2] = Ash[(rb+r)*36 + kb*8 + 4 + q];   al[mt][2] = Asl[(rb+r)*36 + kb*8 + 4 + q];
                ah[mt][3] = Ash[(rb+r+8)*36 + kb*8 + 4 + q]; al[mt][3] = Asl[(rb+r+8)*36 + kb*8 + 4 + q];
            }
            int kbg = (kc >> 4) + kb;
            #pragma unroll
            for (int nt = 0; nt < 4; nt++){
                uint4 wv = __ldg(&g_wl2pb[(kbg*32 + w*4 + nt)*32 + lane]);
                unsigned bh[2] = {wv.x, wv.y};
                unsigned bl[2] = {wv.z, wv.w};
                #pragma unroll
                for (int mt = 0; mt < 4; mt++){
                    mma16(acc[mt][nt], ah[mt], bh);
                    mma16(acc[mt][nt], ah[mt], bl);
                    mma16(acc[mt][nt], al[mt], bh);
                }
            }
        }
    }

    #pragma unroll
    for (int nt = 0; nt < 4; nt++){
        float m0 = -3.4e38f, m1 = -3.4e38f;
        #pragma unroll
        for (int mt = 0; mt < 4; mt++){
            m0 = fmaxf(m0, fmaxf(acc[mt][nt][0], acc[mt][nt][2]));
            m1 = fmaxf(m1, fmaxf(acc[mt][nt][1], acc[mt][nt][3]));
        }
        #pragma unroll
        for (int off = 4; off < 32; off <<= 1){
            m0 = fmaxf(m0, __shfl_xor_sync(0xffffffffu, m0, off));
            m1 = fmaxf(m1, __shfl_xor_sync(0xffffffffu, m1, off));
        }
        if (lane < 4){
            int col = n0 + nt*8 + lane*2;
            atomicMaxFloat(&g_pool[g*256 + col],     m0 + __ldg(bl2 + col));
            atomicMaxFloat(&g_pool[g*256 + col + 1], m1 + __ldg(bl2 + col + 1));
        }
    }
}

// ---------------- head: leaky -> 256x128 -> leaky -> 128x3 -------------------
__global__ void k_head(const float* __restrict__ wm1, const float* __restrict__ bm1,
                       const float* __restrict__ wm2, const float* __restrict__ bm2,
                       float* __restrict__ out){
    __shared__ float gs[256];
    __shared__ float ms[128];
    int b = blockIdx.x, t = threadIdx.x;
    for (int c = t; c < 256; c += 128) gs[c] = leaky(g_pool[b*256 + c]);
    __syncthreads();
    float acc = bm1[t];
    #pragma unroll 8
    for (int d = 0; d < 256; d++) acc += gs[d]*wm1[d*128 + t];
    ms[t] = leaky(acc);
    __syncthreads();
    if (t < 3){
        float o = bm2[t];
        #pragma unroll 8
        for (int d = 0; d < 128; d++) o += ms[d]*wm2[d*3 + t];
        out[b*3 + t] = o;
    }
}

// -----------------------------------------------------------------------------
extern "C" void kernel_launch(void* const* d_in, const int* in_sizes, int n_in,
                              void* d_out, int out_size){
    const float* x   = (const float*)d_in[0];
    const float* pos = (const float*)d_in[1];
    const float* tq  = (const float*)d_in[2];
    const float* w1a = (const float*)d_in[4];
    const float* b1a = (const float*)d_in[5];
    const float* w1b = (const float*)d_in[6];
    const float* b1b = (const float*)d_in[7];
    const float* w2a = (const float*)d_in[8];
    const float* b2a = (const float*)d_in[9];
    const float* w2b = (const float*)d_in[10];
    const float* b2b = (const float*)d_in[11];
    const float* wl1 = (const float*)d_in[12];
    const float* bl1 = (const float*)d_in[13];
    const float* wl2 = (const float*)d_in[14];
    const float* bl2 = (const float*)d_in[15];
    const float* wm1 = (const float*)d_in[16];
    const float* bm1 = (const float*)d_in[17];
    const float* wm2 = (const float*)d_in[18];
    const float* bm2 = (const float*)d_in[19];
    float* out = (float*)d_out;

    // prep (weights, pool) + build (xx, sq5) — independent, one launch
    k_prepbuild<<<208 + BN/256, 256>>>(w1b, w2b, wl1, wl2, x, pos, tq);

    // conv1: kNN5 || convA1 (independent given xx), then edge
    k_knn5A1<<<8192 + (BN*64)/256, 256>>>(w1a, b1a);
    k_edge64<<<BN/8, 256>>>(b1b);        // also emits g_sq

    // conv2: symmetric d2-GEMM || convA2, then select+edge
    k_d2A2<<<1280 + BN/16, 256>>>(w2a, b2a);
    k_select<<<BN/8, 256>>>();
    k_edge128<<<BN/8, 256>>>(b2b);

    // lin1 -> g_hs, lin2 + fused pool, head
    k_lin1<<<BN/64, 256>>>(bl1);
    k_lin2<<<BN/64, 256>>>(bl2);
    k_head<<<BATCH, 128>>>(wm1, bm1, wm2, bm2, out);
}

// round 15
// speedup vs baseline: 1.0301x; 1.0017x over previous
#include <cuda_runtime.h>
#include <cuda_bf16.h>
#include <cstdint>

#define BATCH 128
#define NN    512
#define KNB   16
#define BN    (BATCH*NN)
#define NEGS  0.01f

// ---------------- scratch (device globals; no allocation allowed) -------------
__device__ float g_xx[BN*5];
__device__ float g_x1[BN*64];
__device__ float g_x2[BN*64];
__device__ int   g_idx[BN*KNB];
__device__ float g_A[(size_t)BN*128];
__device__ float g_C[(size_t)BN*128];
__device__ float g_pool[BATCH*256];
__device__ float g_sq[BN];
__device__ float g_sq5[BN];
__device__ float g_d2[(size_t)BN*NN];   // pairwise distances (conv2 kNN)
__device__ float g_hs[(size_t)BN*512];  // lin1 -> lin2 buffer

// W^T A-operand fragment tables for edge kernels (indexed (mt*8+kb)*32+lane)
__device__ uint4 g_w1Ah[1024], g_w1Al[1024];   // conv1 W2 (64x64), tf32 split
__device__ uint4 g_w2Ah[1024], g_w2Al[1024];   // conv2 W2 (128x64), bf16 split
// bf16 split fragment-packed B-operand weights for lin kernels
__device__ uint4  g_wl1pb[9*64*32];      // 144x512 (rows >=133 zero)
__device__ uint4  g_wl2pb[32*32*32];     // 512x256

__device__ __forceinline__ float leaky(float v){ return v > 0.f ? v : NEGS*v; }

__device__ __forceinline__ void atomicMaxFloat(float* addr, float value){
    if (value >= 0.f) atomicMax((int*)addr, __float_as_int(value));
    else              atomicMin((unsigned int*)addr, __float_as_uint(value));
}

__device__ __forceinline__ unsigned f2tf(float x){
    unsigned u; asm("cvt.rna.tf32.f32 %0, %1;" : "=r"(u) : "f"(x)); return u;
}
__device__ __forceinline__ void splt(float x, unsigned &h, unsigned &l){
    h = f2tf(x);
    l = f2tf(x - __uint_as_float(h));
}
__device__ __forceinline__ void mma8(float* c, const unsigned* a, const unsigned* b){
    asm("mma.sync.aligned.m16n8k8.row.col.f32.tf32.tf32.f32 "
        "{%0,%1,%2,%3}, {%4,%5,%6,%7}, {%8,%9}, {%0,%1,%2,%3};"
        : "+f"(c[0]), "+f"(c[1]), "+f"(c[2]), "+f"(c[3])
        : "r"(a[0]), "r"(a[1]), "r"(a[2]), "r"(a[3]), "r"(b[0]), "r"(b[1]));
}
__device__ __forceinline__ void mma16(float* c, const unsigned* a, const unsigned* b){
    asm("mma.sync.aligned.m16n8k16.row.col.f32.bf16.bf16.f32 "
        "{%0,%1,%2,%3}, {%4,%5,%6,%7}, {%8,%9}, {%0,%1,%2,%3};"
        : "+f"(c[0]), "+f"(c[1]), "+f"(c[2]), "+f"(c[3])
        : "r"(a[0]), "r"(a[1]), "r"(a[2]), "r"(a[3]), "r"(b[0]), "r"(b[1]));
}
__device__ __forceinline__ unsigned packbf(float v0, float v1){
    unsigned d; asm("cvt.rn.bf16x2.f32 %0, %1, %2;" : "=r"(d) : "f"(v1), "f"(v0)); return d;
}
__device__ __forceinline__ float bflo(unsigned p){ return __uint_as_float(p << 16); }
__device__ __forceinline__ float bfhi(unsigned p){ return __uint_as_float(p & 0xffff0000u); }
__device__ __forceinline__ void split2(float v0, float v1, unsigned &h, unsigned &l){
    h = packbf(v0, v1);
    l = packbf(v0 - bflo(h), v1 - bfhi(h));
}

// sortable-u32 transform
__device__ __forceinline__ unsigned fsort(float f){
    unsigned b = __float_as_uint(f);
    return b ^ (((int)b >> 31) | 0x80000000u);
}

// index mappings for sel16 slot u on lane:
// MODE 0: j = u*32 + lane   (knn5)
// MODE 1: j = lane*16 + u   (select from contiguous row)
template<int MODE>
__device__ __forceinline__ int sel_j(int lane, int u){
    if (MODE == 0) return u*32 + lane;
    return lane*16 + u;
}
template<int MODE>
__device__ __forceinline__ int sel_u(int j){
    if (MODE == 0) return j >> 5;
    return j & 15;
}

// warp-cooperative exact top-16-of-512 with lower-index tiebreak.
template<int MODE>
__device__ __forceinline__ void sel16(const float* v, int lane, int* out){
    const unsigned long long INF = ~0ull;
    unsigned long long s0 = INF, s1 = INF, s2 = INF, s3 = INF;
    #pragma unroll
    for (int u = 0; u < 16; u++){
        int j = sel_j<MODE>(lane, u);
        unsigned long long k = ((unsigned long long)fsort(v[u]) << 32) | (unsigned)j;
        if (k < s3){
            s3 = k;
            if (s3 < s2){ unsigned long long t = s2; s2 = s3; s3 = t; }
            if (s2 < s1){ unsigned long long t = s1; s1 = s2; s2 = t; }
            if (s1 < s0){ unsigned long long t = s0; s0 = s1; s1 = t; }
        }
    }
    unsigned mask = 0;
    int mine = 0;
    #pragma unroll 1
    for (int r = 0; r < KNB; r++){
        unsigned long long m = s0;
        #pragma unroll
        for (int off = 16; off; off >>= 1){
            unsigned long long o = __shfl_xor_sync(0xffffffffu, m, off);
            if (o < m) m = o;
        }
        if (lane == r) mine = (int)(unsigned)(m & 0xffffffffu);
        if (s0 == m){
            int j = (int)(unsigned)(m & 0xffffffffu);
            mask |= 1u << sel_u<MODE>(j);
            s0 = s1; s1 = s2; s2 = s3; s3 = INF;
            if (s0 == INF && mask != 0xffffu){
                #pragma unroll
                for (int u2 = 0; u2 < 16; u2++){
                    if (!((mask >> u2) & 1u)){
                        int j2 = sel_j<MODE>(lane, u2);
                        unsigned long long k = ((unsigned long long)fsort(v[u2]) << 32) | (unsigned)j2;
                        if (k < s3){
                            s3 = k;
                            if (s3 < s2){ unsigned long long t = s2; s2 = s3; s3 = t; }
                            if (s2 < s1){ unsigned long long t = s1; s1 = s2; s2 = t; }
                            if (s1 < s0){ unsigned long long t = s0; s0 = s1; s1 = t; }
                        }
                    }
                }
            }
        }
    }
    if (lane < KNB) out[lane] = mine;
}

// ---------------- fused prep (weight packing + pool init) + build ------------
__global__ void k_prepbuild(const float* __restrict__ w1b, const float* __restrict__ w2b,
                            const float* __restrict__ wl1, const float* __restrict__ wl2,
                            const float* __restrict__ x, const float* __restrict__ pos,
                            const float* __restrict__ tq){
    if (blockIdx.x < 208){
        int i = blockIdx.x*256 + threadIdx.x;
        if (i < BATCH*256) g_pool[i] = __int_as_float(0xff800000); // -inf
        if (i < 1024){
            int lane = i & 31, tmp = i >> 5;
            int kb = tmp & 7, mt = tmp >> 3;
            int r = lane >> 2, q = lane & 3;
            int R = mt*16 + r, k0 = kb*8 + q;
            uint4 H, L;
            splt(w1b[k0*64 + R],       H.x, L.x);
            splt(w1b[k0*64 + R + 8],   H.y, L.y);
            splt(w1b[(k0+4)*64 + R],   H.z, L.z);
            splt(w1b[(k0+4)*64 + R+8], H.w, L.w);
            g_w1Ah[i] = H; g_w1Al[i] = L;
        } else if (i < 2048){
            int rel = i - 1024;
            int lane = rel & 31, tmp = rel >> 5;
            int kb = tmp & 7, mt = tmp >> 3;
            int r = lane >> 2, q = lane & 3;
            int R = mt*16 + r, c0 = kb*16 + 2*q;
            uint4 H, L;
            split2(w2b[c0*64 + R],       w2b[(c0+1)*64 + R],     H.x, L.x);
            split2(w2b[c0*64 + R + 8],   w2b[(c0+1)*64 + R + 8], H.y, L.y);
            split2(w2b[(c0+8)*64 + R],   w2b[(c0+9)*64 + R],     H.z, L.z);
            split2(w2b[(c0+8)*64 + R+8], w2b[(c0+9)*64 + R + 8], H.w, L.w);
            g_w2Ah[rel] = H; g_w2Al[rel] = L;
        } else if (i < 53248){
            const float* W; uint4* dst; int ncb, ncols, nrows, rel;
            if (i < 20480){ rel = i - 2048;  W = wl1; dst = g_wl1pb; ncb = 64; ncols = 512; nrows = 133; }
            else          { rel = i - 20480; W = wl2; dst = g_wl2pb; ncb = 32; ncols = 256; nrows = 512; }
            int lane = rel & 31, tmp = rel >> 5;
            int cb = tmp % ncb, kb = tmp / ncb;
            int r = lane >> 2, q = lane & 3, col = cb*8 + r;
            int k0 = kb*16 + 2*q;
            float v00 = (k0     < nrows) ? W[(k0    )*ncols + col] : 0.f;
            float v01 = (k0 + 1 < nrows) ? W[(k0 + 1)*ncols + col] : 0.f;
            float v10 = (k0 + 8 < nrows) ? W[(k0 + 8)*ncols + col] : 0.f;
            float v11 = (k0 + 9 < nrows) ? W[(k0 + 9)*ncols + col] : 0.f;
            unsigned h0, l0, h1, l1;
            split2(v00, v01, h0, l0);
            split2(v10, v11, h1, l1);
            dst[rel] = make_uint4(h0, h1, l0, l1);
        }
    } else {
        int i = (blockIdx.x - 208)*256 + threadIdx.x;
        if (i < BN){
            float tv = tq[i], xv = x[i];
            float p0 = pos[i*3+0], p1 = pos[i*3+1], p2 = pos[i*3+2];
            g_xx[i*5+0] = tv;
            g_xx[i*5+1] = xv;
            g_xx[i*5+2] = p0;
            g_xx[i*5+3] = p1;
            g_xx[i*5+4] = p2;
            g_sq5[i] = tv*tv + xv*xv + p0*p0 + p1*p1 + p2*p2;
        }
    }
}

// ---------------- fused kNN d=5 + conv1 layer-1 ------------------------------
__global__ void k_knn5A1(const float* __restrict__ W, const float* __restrict__ bias){
    __shared__ float tile[128*8];
    if (blockIdx.x < 8192){
        int b  = blockIdx.x >> 6;
        int q0 = (blockIdx.x & 63) * 8;
        int warp = threadIdx.x >> 5, lane = threadIdx.x & 31;
        int qi = q0 + warp;
        int node = b*NN + qi;
        const float* Fb = g_xx + (size_t)b*NN*5;

        float f0, f1, f2, f3, f4;
        { const float* fq = Fb + qi*5; f0=fq[0]; f1=fq[1]; f2=fq[2]; f3=fq[3]; f4=fq[4]; }
        float sqi = g_sq5[node];

        float d2loc[16];
        for (int t4 = 0; t4 < 4; t4++){
            __syncthreads();
            for (int idx = threadIdx.x; idx < 1024; idx += 256){
                int rrow = idx >> 3, c = idx & 7;
                int grow = t4*128 + rrow;
                float v = 0.f;
                if (c < 5)       v = Fb[grow*5 + c];
                else if (c == 5) v = g_sq5[b*NN + grow];
                tile[idx] = v;
            }
            __syncthreads();
            #pragma unroll
            for (int u = 0; u < 4; u++){
                int jj = u*32 + lane;
                const float* tr = &tile[jj*8];
                float4 p  = *(const float4*)tr;
                float2 p2 = *(const float2*)(tr + 4);
                float dot = f0*p.x + f1*p.y + f2*p.z + f3*p.w + f4*p2.x;
                d2loc[t4*4 + u] = sqi + p2.y - 2.f*dot;
            }
        }
        sel16<0>(d2loc, lane, g_idx + (size_t)node*KNB);
    } else {
        int t = (blockIdx.x - 8192)*256 + threadIdx.x;
        if (t >= BN*64) return;
        int i = t >> 6, c = t & 63;
        const float* f = g_xx + (size_t)i*5;
        float a = bias[c], cc = 0.f;
        #pragma unroll
        for (int d = 0; d < 5; d++){
            float v  = f[d];
            float wt = W[d*64 + c];
            float wb = W[(5 + d)*64 + c];
            a  += v*(wt - wb);
            cc += v*wb;
        }
        g_A[(size_t)i*64 + c] = a;
        g_C[(size_t)i*64 + c] = cc;
    }
}

// ------- SYMMETRIC d2-GEMM (split-tf32, upper triangle), standalone ----------
// 10 upper-triangle 128x128 tiles per graph:
//   tt: 0..3 -> (0, tt) ; 4..6 -> (1, tt-3) ; 7..8 -> (2, tt-5) ; 9 -> (3,3)
// Off-diagonal tiles also write the mirrored block via smem transpose.
__global__ void k_d2sym(){
    __shared__ float SU[9216];     // As[128*36] | Bs[128*36]; Tb aliases
    int t = threadIdx.x;
    float* As = SU;
    float* Bs = SU + 4608;
    int blk = blockIdx.x;
    int b = blk / 10;
    int tt = blk - b*10;
    int ti, tj;
    if (tt < 4)      { ti = 0; tj = tt; }
    else if (tt < 7) { ti = 1; tj = tt - 3; }
    else if (tt < 9) { ti = 2; tj = tt - 5; }
    else             { ti = 3; tj = 3; }
    int i0 = ti*128, j0 = tj*128;
    const float* Fb = g_x1 + (size_t)b*NN*64;
    int lane = t & 31, w = t >> 5;
    int wx = w & 1, wy = w >> 1;
    int r = lane >> 2, q = lane & 3;

    float acc[2][8][4];
    #pragma unroll
    for (int mt = 0; mt < 2; mt++)
        #pragma unroll
        for (int nt = 0; nt < 8; nt++)
            #pragma unroll
            for (int i = 0; i < 4; i++) acc[mt][nt][i] = 0.f;

    for (int kc = 0; kc < 64; kc += 32){
        __syncthreads();
        for (int i = t; i < 128*8; i += 256){
            int m = i >> 3, kq = (i & 7)*4;
            *(float4*)&As[m*36 + kq] = *(const float4*)(Fb + (i0+m)*64 + kc + kq);
            *(float4*)&Bs[m*36 + kq] = *(const float4*)(Fb + (j0+m)*64 + kc + kq);
        }
        __syncthreads();
        #pragma unroll
        for (int k0 = 0; k0 < 32; k0 += 8){
            unsigned ah[2][4], al[2][4];
            #pragma unroll
            for (int mt = 0; mt < 2; mt++){
                int row = wy*32 + mt*16;
                splt(As[(row+r)*36 + k0 + q],       ah[mt][0], al[mt][0]);
                splt(As[(row+r+8)*36 + k0 + q],     ah[mt][1], al[mt][1]);
                splt(As[(row+r)*36 + k0 + q + 4],   ah[mt][2], al[mt][2]);
                splt(As[(row+r+8)*36 + k0 + q + 4], ah[mt][3], al[mt][3]);
            }
            #pragma unroll
            for (int nt = 0; nt < 8; nt++){
                int col = wx*64 + nt*8;
                unsigned bh[2], bl[2];
                splt(Bs[(col+r)*36 + k0 + q],     bh[0], bl[0]);
                splt(Bs[(col+r)*36 + k0 + q + 4], bh[1], bl[1]);
                #pragma unroll
                for (int mt = 0; mt < 2; mt++){
                    mma8(acc[mt][nt], ah[mt], bh);
                    mma8(acc[mt][nt], ah[mt], bl);
                    mma8(acc[mt][nt], al[mt], bh);
                }
            }
        }
    }

    // direct write (rows i0-block, cols j0-block)
    float si0[2], si1[2];
    #pragma unroll
    for (int mt = 0; mt < 2; mt++){
        int rowb = i0 + wy*32 + mt*16;
        si0[mt] = g_sq[b*NN + rowb + r];
        si1[mt] = g_sq[b*NN + rowb + r + 8];
        #pragma unroll
        for (int nt = 0; nt < 8; nt++){
            int colb = j0 + wx*64 + nt*8 + 2*q;
            float sj0 = g_sq[b*NN + colb], sj1 = g_sq[b*NN + colb + 1];
            float2 v0, v1;
            v0.x = si0[mt] + sj0 - 2.f*acc[mt][nt][0];
            v0.y = si0[mt] + sj1 - 2.f*acc[mt][nt][1];
            v1.x = si1[mt] + sj0 - 2.f*acc[mt][nt][2];
            v1.y = si1[mt] + sj1 - 2.f*acc[mt][nt][3];
            *(float2*)(g_d2 + (size_t)(b*NN + i0 + wy*32 + mt*16 + r)*NN + colb)     = v0;
            *(float2*)(g_d2 + (size_t)(b*NN + i0 + wy*32 + mt*16 + r + 8)*NN + colb) = v1;
        }
    }

    // mirrored write for off-diagonal tiles: stage 64 cols x 128 rows, twice.
    // Tb stride 132 floats: 132 % 4 == 0 keeps float4 reads 16B-aligned;
    // 132 % 32 == 4 keeps the read phase conflict-free.
    if (i0 != j0){
        float* Tb = SU;        // [64][132] = 8448 floats < 9216
        for (int h = 0; h < 2; h++){
            __syncthreads();
            if (wx == h){
                #pragma unroll
                for (int mt = 0; mt < 2; mt++){
                    int rowl = wy*32 + mt*16;
                    #pragma unroll
                    for (int nt = 0; nt < 8; nt++){
                        int coll = nt*8 + 2*q;          // 0..63 within half
                        int colb = j0 + h*64 + coll;
                        float sj0 = g_sq[b*NN + colb], sj1 = g_sq[b*NN + colb + 1];
                        Tb[(coll    )*132 + rowl + r]     = si0[mt] + sj0 - 2.f*acc[mt][nt][0];
                        Tb[(coll + 1)*132 + rowl + r]     = si0[mt] + sj1 - 2.f*acc[mt][nt][1];
                        Tb[(coll    )*132 + rowl + r + 8] = si1[mt] + sj0 - 2.f*acc[mt][nt][2];
                        Tb[(coll + 1)*132 + rowl + r + 8] = si1[mt] + sj1 - 2.f*acc[mt][nt][3];
                    }
                }
            }
            __syncthreads();
            for (int i = t; i < 64*32; i += 256){
                int row = i >> 5, c4 = (i & 31)*4;
                float4 v = *(const float4*)&Tb[row*132 + c4];
                *(float4*)(g_d2 + (size_t)(b*NN + j0 + h*64 + row)*NN + i0 + c4) = v;
            }
        }
    }
}

// ---------------- conv2 layer-1 (d=64, H=128), standalone --------------------
__global__ void __launch_bounds__(256) k_convA2(const float* __restrict__ W,
                                                const float* __restrict__ bias){
    __shared__ float Wd[32*128];
    __shared__ float Wb[32*128];
    __shared__ float Fs[16*64];
    int t = threadIdx.x;
    int base = blockIdx.x*16;

    for (int idx = t; idx < 1024; idx += 256)
        Fs[idx] = g_x1[(size_t)base*64 + idx];

    int m  = t >> 4;
    int cg = (t & 15)*8;
    float a[8], cc[8];
    float4 bb0 = *(const float4*)(bias + cg);
    float4 bb1 = *(const float4*)(bias + cg + 4);
    a[0]=bb0.x; a[1]=bb0.y; a[2]=bb0.z; a[3]=bb0.w;
    a[4]=bb1.x; a[5]=bb1.y; a[6]=bb1.z; a[7]=bb1.w;
    #pragma unroll
    for (int q = 0; q < 8; q++) cc[q] = 0.f;

    for (int db = 0; db < 64; db += 32){
        __syncthreads();
        for (int idx = t; idx < 4096; idx += 256){
            int d = idx >> 7, c = idx & 127;
            float wt = W[(db + d)*128 + c];
            float wb = W[(64 + db + d)*128 + c];
            Wd[idx] = wt - wb;
            Wb[idx] = wb;
        }
        __syncthreads();
        #pragma unroll 4
        for (int d = 0; d < 32; d++){
            float v = Fs[m*64 + db + d];
            float4 w0 = *(const float4*)&Wd[d*128 + cg];
            float4 w1 = *(const float4*)&Wd[d*128 + cg + 4];
            float4 u0 = *(const float4*)&Wb[d*128 + cg];
            float4 u1 = *(const float4*)&Wb[d*128 + cg + 4];
            a[0] += v*w0.x; a[1] += v*w0.y; a[2] += v*w0.z; a[3] += v*w0.w;
            a[4] += v*w1.x; a[5] += v*w1.y; a[6] += v*w1.z; a[7] += v*w1.w;
            cc[0] += v*u0.x; cc[1] += v*u0.y; cc[2] += v*u0.z; cc[3] += v*u0.w;
            cc[4] += v*u1.x; cc[5] += v*u1.y; cc[6] += v*u1.z; cc[7] += v*u1.w;
        }
    }
    int node = base + m;
    float4* pa = (float4*)(g_A + (size_t)node*128 + cg);
    float4* pc = (float4*)(g_C + (size_t)node*128 + cg);
    pa[0] = make_float4(a[0],a[1],a[2],a[3]);
    pa[1] = make_float4(a[4],a[5],a[6],a[7]);
    pc[0] = make_float4(cc[0],cc[1],cc[2],cc[3]);
    pc[1] = make_float4(cc[4],cc[5],cc[6],cc[7]);
}

// ---------------- kNN d=64: cached-top4 select from g_d2 ---------------------
__global__ void k_select(){
    int warp = threadIdx.x >> 5, lane = threadIdx.x & 31;
    int node = blockIdx.x*8 + warp;
    const float* row = g_d2 + (size_t)node*NN;
    float v[16];
    #pragma unroll
    for (int u4 = 0; u4 < 4; u4++){
        float4 x = *(const float4*)(row + lane*16 + u4*4);
        v[u4*4+0] = x.x; v[u4*4+1] = x.y; v[u4*4+2] = x.z; v[u4*4+3] = x.w;
    }
    sel16<1>(v, lane, g_idx + (size_t)node*KNB);
}

// ---------------- conv1 edge layer-2: D^T = W^T @ h^T (tf32, no smem) --------
__global__ void k_edge64(const float* __restrict__ bias){
    int t = threadIdx.x, warp = t >> 5, lane = t & 31;
    int node = blockIdx.x*8 + warp;
    int b = node / NN;
    int r = lane >> 2, q = lane & 3;

    int j0 = b*NN + __ldg(g_idx + (size_t)node*KNB + r);
    int j1 = b*NN + __ldg(g_idx + (size_t)node*KNB + 8 + r);
    const float* Ai = g_A + (size_t)node*64;
    const float* C0 = g_C + (size_t)j0*64;
    const float* C1 = g_C + (size_t)j1*64;

    float acc[4][2][4];
    #pragma unroll
    for (int mt = 0; mt < 4; mt++)
        #pragma unroll
        for (int n = 0; n < 2; n++)
            #pragma unroll
            for (int i = 0; i < 4; i++) acc[mt][n][i] = 0.f;

    #pragma unroll
    for (int kb = 0; kb < 8; kb++){
        int c0 = kb*8 + q;
        float ai0 = __ldg(Ai + c0), ai1 = __ldg(Ai + c0 + 4);
        unsigned b0h[2], b0l[2], b1h[2], b1l[2];
        splt(leaky(ai0 + __ldg(C0 + c0)),     b0h[0], b0l[0]);
        splt(leaky(ai1 + __ldg(C0 + c0 + 4)), b0h[1], b0l[1]);
        splt(leaky(ai0 + __ldg(C1 + c0)),     b1h[0], b1l[0]);
        splt(leaky(ai1 + __ldg(C1 + c0 + 4)), b1h[1], b1l[1]);
        #pragma unroll
        for (int mt = 0; mt < 4; mt++){
            uint4 H = __ldg(&g_w1Ah[(mt*8 + kb)*32 + lane]);
            uint4 L = __ldg(&g_w1Al[(mt*8 + kb)*32 + lane]);
            mma8(acc[mt][0], (const unsigned*)&H, b0h);
            mma8(acc[mt][0], (const unsigned*)&H, b0l);
            mma8(acc[mt][0], (const unsigned*)&L, b0h);
            mma8(acc[mt][1], (const unsigned*)&H, b1h);
            mma8(acc[mt][1], (const unsigned*)&H, b1l);
            mma8(acc[mt][1], (const unsigned*)&L, b1h);
        }
    }

    float ssum = 0.f;
    #pragma unroll
    for (int mt = 0; mt < 4; mt++){
        float m0 = fmaxf(fmaxf(acc[mt][0][0], acc[mt][0][1]),
                         fmaxf(acc[mt][1][0], acc[mt][1][1]));
        float m1 = fmaxf(fmaxf(acc[mt][0][2], acc[mt][0][3]),
                         fmaxf(acc[mt][1][2], acc[mt][1][3]));
        m0 = fmaxf(m0, __shfl_xor_sync(0xffffffffu, m0, 1));
        m0 = fmaxf(m0, __shfl_xor_sync(0xffffffffu, m0, 2));
        m1 = fmaxf(m1, __shfl_xor_sync(0xffffffffu, m1, 1));
        m1 = fmaxf(m1, __shfl_xor_sync(0xffffffffu, m1, 2));
        if (q == 0){
            int ch = mt*16 + r;
            float v0 = leaky(m0 + __ldg(bias + ch));
            float v1 = leaky(m1 + __ldg(bias + ch + 8));
            g_x1[(size_t)node*64 + ch]     = v0;
            g_x1[(size_t)node*64 + ch + 8] = v1;
            ssum += v0*v0 + v1*v1;
        }
    }
    ssum += __shfl_xor_sync(0xffffffffu, ssum, 4);
    ssum += __shfl_xor_sync(0xffffffffu, ssum, 8);
    ssum += __shfl_xor_sync(0xffffffffu, ssum, 16);
    if (lane == 0) g_sq[node] = ssum;
}

// ---------------- conv2 edge layer-2: D^T = W^T @ h^T (bf16, no smem) --------
__global__ void k_edge128(const float* __restrict__ bias){
    int t = threadIdx.x, warp = t >> 5, lane = t & 31;
    int node = blockIdx.x*8 + warp;
    int b = node / NN;
    int r = lane >> 2, q = lane & 3;

    int j0 = b*NN + __ldg(g_idx + (size_t)node*KNB + r);
    int j1 = b*NN + __ldg(g_idx + (size_t)node*KNB + 8 + r);
    const float* Ai = g_A + (size_t)node*128;
    const float* C0 = g_C + (size_t)j0*128;
    const float* C1 = g_C + (size_t)j1*128;

    float acc[4][2][4];
    #pragma unroll
    for (int mt = 0; mt < 4; mt++)
        #pragma unroll
        for (int n = 0; n < 2; n++)
            #pragma unroll
            for (int i = 0; i < 4; i++) acc[mt][n][i] = 0.f;

    #pragma unroll
    for (int kb = 0; kb < 8; kb++){
        int c0 = kb*16 + 2*q;
        float2 ai0 = *(const float2*)(Ai + c0);
        float2 ai1 = *(const float2*)(Ai + c0 + 8);
        float2 ca0 = *(const float2*)(C0 + c0);
        float2 ca1 = *(const float2*)(C0 + c0 + 8);
        float2 cb0 = *(const float2*)(C1 + c0);
        float2 cb1 = *(const float2*)(C1 + c0 + 8);
        unsigned b0h[2], b0l[2], b1h[2], b1l[2];
        split2(leaky(ai0.x + ca0.x), leaky(ai0.y + ca0.y), b0h[0], b0l[0]);
        split2(leaky(ai1.x + ca1.x), leaky(ai1.y + ca1.y), b0h[1], b0l[1]);
        split2(leaky(ai0.x + cb0.x), leaky(ai0.y + cb0.y), b1h[0], b1l[0]);
        split2(leaky(ai1.x + cb1.x), leaky(ai1.y + cb1.y), b1h[1], b1l[1]);
        #pragma unroll
        for (int mt = 0; mt < 4; mt++){
            uint4 H = __ldg(&g_w2Ah[(mt*8 + kb)*32 + lane]);
            uint4 L = __ldg(&g_w2Al[(mt*8 + kb)*32 + lane]);
            mma16(acc[mt][0], (const unsigned*)&H, b0h);
            mma16(acc[mt][0], (const unsigned*)&H, b0l);
            mma16(acc[mt][0], (const unsigned*)&L, b0h);
            mma16(acc[mt][1], (const unsigned*)&H, b1h);
            mma16(acc[mt][1], (const unsigned*)&H, b1l);
            mma16(acc[mt][1], (const unsigned*)&L, b1h);
        }
    }

    #pragma unroll
    for (int mt = 0; mt < 4; mt++){
        float m0 = fmaxf(fmaxf(acc[mt][0][0], acc[mt][0][1]),
                         fmaxf(acc[mt][1][0], acc[mt][1][1]));
        float m1 = fmaxf(fmaxf(acc[mt][0][2], acc[mt][0][3]),
                         fmaxf(acc[mt][1][2], acc[mt][1][3]));
        m0 = fmaxf(m0, __shfl_xor_sync(0xffffffffu, m0, 1));
        m0 = fmaxf(m0, __shfl_xor_sync(0xffffffffu, m0, 2));
        m1 = fmaxf(m1, __shfl_xor_sync(0xffffffffu, m1, 1));
        m1 = fmaxf(m1, __shfl_xor_sync(0xffffffffu, m1, 2));
        if (q == 0){
            int ch = mt*16 + r;
            g_x2[(size_t)node*64 + ch]     = leaky(m0 + __ldg(bias + ch));
            g_x2[(size_t)node*64 + ch + 8] = leaky(m1 + __ldg(bias + ch + 8));
        }
    }
}

__device__ __forceinline__ float featval(int node, int d){
    if (d < 5)   return g_xx[node*5 + d];
    if (d < 69)  return g_x1[(size_t)node*64 + d - 5];
    if (d < 133) return g_x2[(size_t)node*64 + d - 69];
    return 0.f;
}

// ---------------- lin1: [BN x 144] @ [144 x 512] + leaky (bf16) --------------
__global__ void k_lin1(const float* __restrict__ bl1){
    __shared__ unsigned CSh[64*76];
    __shared__ unsigned CSl[64*76];
    int t = threadIdx.x, lane = t & 31, w = t >> 5;
    int base = blockIdx.x*64;
    for (int i = t; i < 64*72; i += 256){
        int m = i / 72, p = i - m*72;
        int node = base + m;
        float v0 = featval(node, 2*p);
        float v1 = featval(node, 2*p + 1);
        unsigned h, l;
        split2(v0, v1, h, l);
        CSh[m*76 + p] = h;
        CSl[m*76 + p] = l;
    }
    __syncthreads();

    int r = lane >> 2, q = lane & 3;
    int n0 = w*64;
    for (int np = 0; np < 2; np++){
        float acc[4][4][4];
        #pragma unroll
        for (int mt = 0; mt < 4; mt++)
            #pragma unroll
            for (int nt = 0; nt < 4; nt++)
                #pragma unroll
                for (int i = 0; i < 4; i++) acc[mt][nt][i] = 0.f;

        for (int kb = 0; kb < 9; kb++){
            unsigned ah[4][4], al[4][4];
            #pragma unroll
            for (int mt = 0; mt < 4; mt++){
                int rb = mt*16;
                ah[mt][0] = CSh[(rb+r)*76 + kb*8 + q];       al[mt][0] = CSl[(rb+r)*76 + kb*8 + q];
                ah[mt][1] = CSh[(rb+r+8)*76 + kb*8 + q];     al[mt][1] = CSl[(rb+r+8)*76 + kb*8 + q];
                ah[mt][2] = CSh[(rb+r)*76 + kb*8 + 4 + q];   al[mt][2] = CSl[(rb+r)*76 + kb*8 + 4 + q];
                ah[mt][3] = CSh[(rb+r+8)*76 + kb*8 + 4 + q]; al[mt][3] = CSl[(rb+r+8)*76 + kb*8 + 4 + q];
            }
            #pragma unroll
            for (int nt = 0; nt < 4; nt++){
                uint4 wv = __ldg(&g_wl1pb[(kb*64 + w*8 + np*4 + nt)*32 + lane]);
                unsigned bh[2] = {wv.x, wv.y};
                unsigned bl[2] = {wv.z, wv.w};
                #pragma unroll
                for (int mt = 0; mt < 4; mt++){
                    mma16(acc[mt][nt], ah[mt], bh);
                    mma16(acc[mt][nt], ah[mt], bl);
                    mma16(acc[mt][nt], al[mt], bh);
                }
            }
        }
        #pragma unroll
        for (int mt = 0; mt < 4; mt++){
            #pragma unroll
            for (int nt = 0; nt < 4; nt++){
                int node = base + mt*16 + r;
                int col = n0 + (np*4 + nt)*8 + q*2;
                float b0 = __ldg(bl1 + col), b1 = __ldg(bl1 + col + 1);
                float2 u0, u1;
                u0.x = leaky(acc[mt][nt][0] + b0); u0.y = leaky(acc[mt][nt][1] + b1);
                u1.x = leaky(acc[mt][nt][2] + b0); u1.y = leaky(acc[mt][nt][3] + b1);
                *(float2*)(g_hs + (size_t)node*512 + col)     = u0;
                *(float2*)(g_hs + (size_t)(node+8)*512 + col) = u1;
            }
        }
    }
}

// ---------------- lin2: [BN x 512] @ [512 x 256] + max-pool (bf16) -----------
__global__ void k_lin2(const float* __restrict__ bl2){
    __shared__ unsigned Ash[64*36];
    __shared__ unsigned Asl[64*36];
    int t = threadIdx.x, lane = t & 31, w = t >> 5;
    int base = blockIdx.x*64;
    int g = base / NN;
    int r = lane >> 2, q = lane & 3;
    int n0 = w*32;

    float acc[4][4][4];
    #pragma unroll
    for (int mt = 0; mt < 4; mt++)
        #pragma unroll
        for (int nt = 0; nt < 4; nt++)
            #pragma unroll
            for (int i = 0; i < 4; i++) acc[mt][nt][i] = 0.f;

    for (int kc = 0; kc < 512; kc += 64){
        __syncthreads();
        for (int i = t; i < 1024; i += 256){
            int m = i >> 4, sub = i & 15;
            float4 v = *(const float4*)(g_hs + (size_t)(base + m)*512 + kc + sub*4);
            unsigned h0, l0, h1, l1;
            split2(v.x, v.y, h0, l0);
            split2(v.z, v.w, h1, l1);
            Ash[m*36 + sub*2]     = h0;
            Ash[m*36 + sub*2 + 1] = h1;
            Asl[m*36 + sub*2]     = l0;
            Asl[m*36 + sub*2 + 1] = l1;
        }
        __syncthreads();
        #pragma unroll
        for (int kb = 0; kb < 4; kb++){
            unsigned ah[4][4], al[4][4];
            #pragma unroll
            for (int mt = 0; mt < 4; mt++){
                int rb = mt*16;
                ah[mt][0] = Ash[(rb+r)*36 + kb*8 + q];       al[mt][0] = Asl[(rb+r)*36 + kb*8 + q];
                ah[mt][1] = Ash[(rb+r+8)*36 + kb*8 + q];     al[mt][1] = Asl[(rb+r+8)*36 + kb*8 + q];
                ah[mt][2] = Ash[(rb+r)*36 + kb*8 + 4 + q];   al[mt][2] = Asl[(rb+r)*36 + kb*8 + 4 + q];
                ah[mt][3] = Ash[(rb+r+8)*36 + kb*8 + 4 + q]; al[mt][3] = Asl[(rb+r+8)*36 + kb*8 + 4 + q];
            }
            int kbg = (kc >> 4) + kb;
            #pragma unroll
            for (int nt = 0; nt < 4; nt++){
                uint4 wv = __ldg(&g_wl2pb[(kbg*32 + w*4 + nt)*32 + lane]);
                unsigned bh[2] = {wv.x, wv.y};
                unsigned bl[2] = {wv.z, wv.w};
                #pragma unroll
                for (int mt = 0; mt < 4; mt++){
                    mma16(acc[mt][nt], ah[mt], bh);
                    mma16(acc[mt][nt], ah[mt], bl);
                    mma16(acc[mt][nt], al[mt], bh);
                }
            }
        }
    }

    #pragma unroll
    for (int nt = 0; nt < 4; nt++){
        float m0 = -3.4e38f, m1 = -3.4e38f;
        #pragma unroll
        for (int mt = 0; mt < 4; mt++){
            m0 = fmaxf(m0, fmaxf(acc[mt][nt][0], acc[mt][nt][2]));
            m1 = fmaxf(m1, fmaxf(acc[mt][nt][1], acc[mt][nt][3]));
        }
        #pragma unroll
        for (int off = 4; off < 32; off <<= 1){
            m0 = fmaxf(m0, __shfl_xor_sync(0xffffffffu, m0, off));
            m1 = fmaxf(m1, __shfl_xor_sync(0xffffffffu, m1, off));
        }
        if (lane < 4){
            int col = n0 + nt*8 + lane*2;
            atomicMaxFloat(&g_pool[g*256 + col],     m0 + __ldg(bl2 + col));
            atomicMaxFloat(&g_pool[g*256 + col + 1], m1 + __ldg(bl2 + col + 1));
        }
    }
}

// ---------------- head: leaky -> 256x128 -> leaky -> 128x3 -------------------
__global__ void k_head(const float* __restrict__ wm1, const float* __restrict__ bm1,
                       const float* __restrict__ wm2, const float* __restrict__ bm2,
                       float* __restrict__ out){
    __shared__ float gs[256];
    __shared__ float ms[128];
    int b = blockIdx.x, t = threadIdx.x;
    for (int c = t; c < 256; c += 128) gs[c] = leaky(g_pool[b*256 + c]);
    __syncthreads();
    float acc = bm1[t];
    #pragma unroll 8
    for (int d = 0; d < 256; d++) acc += gs[d]*wm1[d*128 + t];
    ms[t] = leaky(acc);
    __syncthreads();
    if (t < 3){
        float o = bm2[t];
        #pragma unroll 8
        for (int d = 0; d < 128; d++) o += ms[d]*wm2[d*3 + t];
        out[b*3 + t] = o;
    }
}

// -----------------------------------------------------------------------------
extern "C" void kernel_launch(void* const* d_in, const int* in_sizes, int n_in,
                              void* d_out, int out_size){
    const float* x   = (const float*)d_in[0];
    const float* pos = (const float*)d_in[1];
    const float* tq  = (const float*)d_in[2];
    const float* w1a = (const float*)d_in[4];
    const float* b1a = (const float*)d_in[5];
    const float* w1b = (const float*)d_in[6];
    const float* b1b = (const float*)d_in[7];
    const float* w2a = (const float*)d_in[8];
    const float* b2a = (const float*)d_in[9];
    const float* w2b = (const float*)d_in[10];
    const float* b2b = (const float*)d_in[11];
    const float* wl1 = (const float*)d_in[12];
    const float* bl1 = (const float*)d_in[13];
    const float* wl2 = (const float*)d_in[14];
    const float* bl2 = (const float*)d_in[15];
    const float* wm1 = (const float*)d_in[16];
    const float* bm1 = (const float*)d_in[17];
    const float* wm2 = (const float*)d_in[18];
    const float* bm2 = (const float*)d_in[19];
    float* out = (float*)d_out;

    // prep (weights, pool) + build (xx, sq5) — independent, one launch
    k_prepbuild<<<208 + BN/256, 256>>>(w1b, w2b, wl1, wl2, x, pos, tq);

    // conv1: kNN5 || convA1 (independent given xx), then edge
    k_knn5A1<<<8192 + (BN*64)/256, 256>>>(w1a, b1a);
    k_edge64<<<BN/8, 256>>>(b1b);        // also emits g_sq

    // conv2: symmetric d2-GEMM, conv2 L1 (own kernel/regs), select, edge
    k_d2sym<<<BATCH*10, 256>>>();
    k_convA2<<<BN/16, 256>>>(w2a, b2a);
    k_select<<<BN/8, 256>>>();
    k_edge128<<<BN/8, 256>>>(b2b);

    // lin1 -> g_hs, lin2 + fused pool, head
    k_lin1<<<BN/64, 256>>>(bl1);
    k_lin2<<<BN/64, 256>>>(bl2);
    k_head<<<BATCH, 128>>>(wm1, bm1, wm2, bm2, out);
}

// round 16
// speedup vs baseline: 1.0390x; 1.0086x over previous
#include <cuda_runtime.h>
#include <cuda_bf16.h>
#include <cstdint>

#define BATCH 128
#define NN    512
#define KNB   16
#define BN    (BATCH*NN)
#define NEGS  0.01f

// ---------------- scratch (device globals; no allocation allowed) -------------
__device__ float g_xx[BN*5];
__device__ float g_x1[BN*64];
__device__ float g_x2[BN*64];
__device__ int   g_idx[BN*KNB];
__device__ float g_A[(size_t)BN*128];
__device__ float g_C[(size_t)BN*128];
__device__ float g_pool[BATCH*256];
__device__ float g_sq[BN];
__device__ float g_sq5[BN];
__device__ float g_d2[(size_t)BN*NN];   // pairwise distances (conv2 kNN)
__device__ float g_hs[(size_t)BN*512];  // lin1 -> lin2 buffer

// W^T A-operand fragment tables for edge kernels (indexed (mt*8+kb)*32+lane)
__device__ uint4 g_w1Ah[1024], g_w1Al[1024];   // conv1 W2 (64x64), tf32 split
__device__ uint4 g_w2Ah[1024], g_w2Al[1024];   // conv2 W2 (128x64), bf16 split
// bf16 split fragment-packed B-operand weights for lin kernels
__device__ uint4  g_wl1pb[9*64*32];      // 144x512 (rows >=133 zero)
__device__ uint4  g_wl2pb[32*32*32];     // 512x256

__device__ __forceinline__ float leaky(float v){ return v > 0.f ? v : NEGS*v; }

__device__ __forceinline__ void atomicMaxFloat(float* addr, float value){
    if (value >= 0.f) atomicMax((int*)addr, __float_as_int(value));
    else              atomicMin((unsigned int*)addr, __float_as_uint(value));
}

__device__ __forceinline__ unsigned f2tf(float x){
    unsigned u; asm("cvt.rna.tf32.f32 %0, %1;" : "=r"(u) : "f"(x)); return u;
}
__device__ __forceinline__ void splt(float x, unsigned &h, unsigned &l){
    h = f2tf(x);
    l = f2tf(x - __uint_as_float(h));
}
__device__ __forceinline__ void mma8(float* c, const unsigned* a, const unsigned* b){
    asm("mma.sync.aligned.m16n8k8.row.col.f32.tf32.tf32.f32 "
        "{%0,%1,%2,%3}, {%4,%5,%6,%7}, {%8,%9}, {%0,%1,%2,%3};"
        : "+f"(c[0]), "+f"(c[1]), "+f"(c[2]), "+f"(c[3])
        : "r"(a[0]), "r"(a[1]), "r"(a[2]), "r"(a[3]), "r"(b[0]), "r"(b[1]));
}
__device__ __forceinline__ void mma16(float* c, const unsigned* a, const unsigned* b){
    asm("mma.sync.aligned.m16n8k16.row.col.f32.bf16.bf16.f32 "
        "{%0,%1,%2,%3}, {%4,%5,%6,%7}, {%8,%9}, {%0,%1,%2,%3};"
        : "+f"(c[0]), "+f"(c[1]), "+f"(c[2]), "+f"(c[3])
        : "r"(a[0]), "r"(a[1]), "r"(a[2]), "r"(a[3]), "r"(b[0]), "r"(b[1]));
}
__device__ __forceinline__ unsigned packbf(float v0, float v1){
    unsigned d; asm("cvt.rn.bf16x2.f32 %0, %1, %2;" : "=r"(d) : "f"(v1), "f"(v0)); return d;
}
__device__ __forceinline__ float bflo(unsigned p){ return __uint_as_float(p << 16); }
__device__ __forceinline__ float bfhi(unsigned p){ return __uint_as_float(p & 0xffff0000u); }
__device__ __forceinline__ void split2(float v0, float v1, unsigned &h, unsigned &l){
    h = packbf(v0, v1);
    l = packbf(v0 - bflo(h), v1 - bfhi(h));
}

// sortable-u32 transform
__device__ __forceinline__ unsigned fsort(float f){
    unsigned b = __float_as_uint(f);
    return b ^ (((int)b >> 31) | 0x80000000u);
}

// index mappings for sel16 slot u on lane:
// MODE 0: j = u*32 + lane   (knn5)
// MODE 1: j = lane*16 + u   (select from contiguous row)
template<int MODE>
__device__ __forceinline__ int sel_j(int lane, int u){
    if (MODE == 0) return u*32 + lane;
    return lane*16 + u;
}
template<int MODE>
__device__ __forceinline__ int sel_u(int j){
    if (MODE == 0) return j >> 5;
    return j & 15;
}

// warp-cooperative exact top-16-of-512 with lower-index tiebreak.
template<int MODE>
__device__ __forceinline__ void sel16(const float* v, int lane, int* out){
    const unsigned long long INF = ~0ull;
    unsigned long long s0 = INF, s1 = INF, s2 = INF, s3 = INF;
    #pragma unroll
    for (int u = 0; u < 16; u++){
        int j = sel_j<MODE>(lane, u);
        unsigned long long k = ((unsigned long long)fsort(v[u]) << 32) | (unsigned)j;
        if (k < s3){
            s3 = k;
            if (s3 < s2){ unsigned long long t = s2; s2 = s3; s3 = t; }
            if (s2 < s1){ unsigned long long t = s1; s1 = s2; s2 = t; }
            if (s1 < s0){ unsigned long long t = s0; s0 = s1; s1 = t; }
        }
    }
    unsigned mask = 0;
    int mine = 0;
    #pragma unroll 1
    for (int r = 0; r < KNB; r++){
        unsigned long long m = s0;
        #pragma unroll
        for (int off = 16; off; off >>= 1){
            unsigned long long o = __shfl_xor_sync(0xffffffffu, m, off);
            if (o < m) m = o;
        }
        if (lane == r) mine = (int)(unsigned)(m & 0xffffffffu);
        if (s0 == m){
            int j = (int)(unsigned)(m & 0xffffffffu);
            mask |= 1u << sel_u<MODE>(j);
            s0 = s1; s1 = s2; s2 = s3; s3 = INF;
            if (s0 == INF && mask != 0xffffu){
                #pragma unroll
                for (int u2 = 0; u2 < 16; u2++){
                    if (!((mask >> u2) & 1u)){
                        int j2 = sel_j<MODE>(lane, u2);
                        unsigned long long k = ((unsigned long long)fsort(v[u2]) << 32) | (unsigned)j2;
                        if (k < s3){
                            s3 = k;
                            if (s3 < s2){ unsigned long long t = s2; s2 = s3; s3 = t; }
                            if (s2 < s1){ unsigned long long t = s1; s1 = s2; s2 = t; }
                            if (s1 < s0){ unsigned long long t = s0; s0 = s1; s1 = t; }
                        }
                    }
                }
            }
        }
    }
    if (lane < KNB) out[lane] = mine;
}

// ---------------- fused prep (weight packing + pool init) + build ------------
__global__ void k_prepbuild(const float* __restrict__ w1b, const float* __restrict__ w2b,
                            const float* __restrict__ wl1, const float* __restrict__ wl2,
                            const float* __restrict__ x, const float* __restrict__ pos,
                            const float* __restrict__ tq){
    if (blockIdx.x < 208){
        int i = blockIdx.x*256 + threadIdx.x;
        if (i < BATCH*256) g_pool[i] = __int_as_float(0xff800000); // -inf
        if (i < 1024){
            int lane = i & 31, tmp = i >> 5;
            int kb = tmp & 7, mt = tmp >> 3;
            int r = lane >> 2, q = lane & 3;
            int R = mt*16 + r, k0 = kb*8 + q;
            uint4 H, L;
            splt(w1b[k0*64 + R],       H.x, L.x);
            splt(w1b[k0*64 + R + 8],   H.y, L.y);
            splt(w1b[(k0+4)*64 + R],   H.z, L.z);
            splt(w1b[(k0+4)*64 + R+8], H.w, L.w);
            g_w1Ah[i] = H; g_w1Al[i] = L;
        } else if (i < 2048){
            int rel = i - 1024;
            int lane = rel & 31, tmp = rel >> 5;
            int kb = tmp & 7, mt = tmp >> 3;
            int r = lane >> 2, q = lane & 3;
            int R = mt*16 + r, c0 = kb*16 + 2*q;
            uint4 H, L;
            split2(w2b[c0*64 + R],       w2b[(c0+1)*64 + R],     H.x, L.x);
            split2(w2b[c0*64 + R + 8],   w2b[(c0+1)*64 + R + 8], H.y, L.y);
            split2(w2b[(c0+8)*64 + R],   w2b[(c0+9)*64 + R],     H.z, L.z);
            split2(w2b[(c0+8)*64 + R+8], w2b[(c0+9)*64 + R + 8], H.w, L.w);
            g_w2Ah[rel] = H; g_w2Al[rel] = L;
        } else if (i < 53248){
            const float* W; uint4* dst; int ncb, ncols, nrows, rel;
            if (i < 20480){ rel = i - 2048;  W = wl1; dst = g_wl1pb; ncb = 64; ncols = 512; nrows = 133; }
            else          { rel = i - 20480; W = wl2; dst = g_wl2pb; ncb = 32; ncols = 256; nrows = 512; }
            int lane = rel & 31, tmp = rel >> 5;
            int cb = tmp % ncb, kb = tmp / ncb;
            int r = lane >> 2, q = lane & 3, col = cb*8 + r;
            int k0 = kb*16 + 2*q;
            float v00 = (k0     < nrows) ? W[(k0    )*ncols + col] : 0.f;
            float v01 = (k0 + 1 < nrows) ? W[(k0 + 1)*ncols + col] : 0.f;
            float v10 = (k0 + 8 < nrows) ? W[(k0 + 8)*ncols + col] : 0.f;
            float v11 = (k0 + 9 < nrows) ? W[(k0 + 9)*ncols + col] : 0.f;
            unsigned h0, l0, h1, l1;
            split2(v00, v01, h0, l0);
            split2(v10, v11, h1, l1);
            dst[rel] = make_uint4(h0, h1, l0, l1);
        }
    } else {
        int i = (blockIdx.x - 208)*256 + threadIdx.x;
        if (i < BN){
            float tv = tq[i], xv = x[i];
            float p0 = pos[i*3+0], p1 = pos[i*3+1], p2 = pos[i*3+2];
            g_xx[i*5+0] = tv;
            g_xx[i*5+1] = xv;
            g_xx[i*5+2] = p0;
            g_xx[i*5+3] = p1;
            g_xx[i*5+4] = p2;
            g_sq5[i] = tv*tv + xv*xv + p0*p0 + p1*p1 + p2*p2;
        }
    }
}

// ---------------- fused kNN d=5 + conv1 layer-1 ------------------------------
__global__ void k_knn5A1(const float* __restrict__ W, const float* __restrict__ bias){
    __shared__ float tile[128*8];
    if (blockIdx.x < 8192){
        int b  = blockIdx.x >> 6;
        int q0 = (blockIdx.x & 63) * 8;
        int warp = threadIdx.x >> 5, lane = threadIdx.x & 31;
        int qi = q0 + warp;
        int node = b*NN + qi;
        const float* Fb = g_xx + (size_t)b*NN*5;

        float f0, f1, f2, f3, f4;
        { const float* fq = Fb + qi*5; f0=fq[0]; f1=fq[1]; f2=fq[2]; f3=fq[3]; f4=fq[4]; }
        float sqi = g_sq5[node];

        float d2loc[16];
        for (int t4 = 0; t4 < 4; t4++){
            __syncthreads();
            for (int idx = threadIdx.x; idx < 1024; idx += 256){
                int rrow = idx >> 3, c = idx & 7;
                int grow = t4*128 + rrow;
                float v = 0.f;
                if (c < 5)       v = Fb[grow*5 + c];
                else if (c == 5) v = g_sq5[b*NN + grow];
                tile[idx] = v;
            }
            __syncthreads();
            #pragma unroll
            for (int u = 0; u < 4; u++){
                int jj = u*32 + lane;
                const float* tr = &tile[jj*8];
                float4 p  = *(const float4*)tr;
                float2 p2 = *(const float2*)(tr + 4);
                float dot = f0*p.x + f1*p.y + f2*p.z + f3*p.w + f4*p2.x;
                d2loc[t4*4 + u] = sqi + p2.y - 2.f*dot;
            }
        }
        sel16<0>(d2loc, lane, g_idx + (size_t)node*KNB);
    } else {
        int t = (blockIdx.x - 8192)*256 + threadIdx.x;
        if (t >= BN*64) return;
        int i = t >> 6, c = t & 63;
        const float* f = g_xx + (size_t)i*5;
        float a = bias[c], cc = 0.f;
        #pragma unroll
        for (int d = 0; d < 5; d++){
            float v  = f[d];
            float wt = W[d*64 + c];
            float wb = W[(5 + d)*64 + c];
            a  += v*(wt - wb);
            cc += v*wb;
        }
        g_A[(size_t)i*64 + c] = a;
        g_C[(size_t)i*64 + c] = cc;
    }
}

// ------- SYMMETRIC d2-GEMM (split-tf32, upper triangle), standalone ----------
// 10 upper-triangle 128x128 tiles per graph:
//   tt: 0..3 -> (0, tt) ; 4..6 -> (1, tt-3) ; 7..8 -> (2, tt-5) ; 9 -> (3,3)
// Off-diagonal tiles also write the mirrored block via smem transpose.
__global__ void k_d2sym(){
    __shared__ float SU[9216];     // As[128*36] | Bs[128*36]; Tb aliases
    int t = threadIdx.x;
    float* As = SU;
    float* Bs = SU + 4608;
    int blk = blockIdx.x;
    int b = blk / 10;
    int tt = blk - b*10;
    int ti, tj;
    if (tt < 4)      { ti = 0; tj = tt; }
    else if (tt < 7) { ti = 1; tj = tt - 3; }
    else if (tt < 9) { ti = 2; tj = tt - 5; }
    else             { ti = 3; tj = 3; }
    int i0 = ti*128, j0 = tj*128;
    const float* Fb = g_x1 + (size_t)b*NN*64;
    int lane = t & 31, w = t >> 5;
    int wx = w & 1, wy = w >> 1;
    int r = lane >> 2, q = lane & 3;

    float acc[2][8][4];
    #pragma unroll
    for (int mt = 0; mt < 2; mt++)
        #pragma unroll
        for (int nt = 0; nt < 8; nt++)
            #pragma unroll
            for (int i = 0; i < 4; i++) acc[mt][nt][i] = 0.f;

    for (int kc = 0; kc < 64; kc += 32){
        __syncthreads();
        for (int i = t; i < 128*8; i += 256){
            int m = i >> 3, kq = (i & 7)*4;
            *(float4*)&As[m*36 + kq] = *(const float4*)(Fb + (i0+m)*64 + kc + kq);
            *(float4*)&Bs[m*36 + kq] = *(const float4*)(Fb + (j0+m)*64 + kc + kq);
        }
        __syncthreads();
        #pragma unroll
        for (int k0 = 0; k0 < 32; k0 += 8){
            unsigned ah[2][4], al[2][4];
            #pragma unroll
            for (int mt = 0; mt < 2; mt++){
                int row = wy*32 + mt*16;
                splt(As[(row+r)*36 + k0 + q],       ah[mt][0], al[mt][0]);
                splt(As[(row+r+8)*36 + k0 + q],     ah[mt][1], al[mt][1]);
                splt(As[(row+r)*36 + k0 + q + 4],   ah[mt][2], al[mt][2]);
                splt(As[(row+r+8)*36 + k0 + q + 4], ah[mt][3], al[mt][3]);
            }
            #pragma unroll
            for (int nt = 0; nt < 8; nt++){
                int col = wx*64 + nt*8;
                unsigned bh[2], bl[2];
                splt(Bs[(col+r)*36 + k0 + q],     bh[0], bl[0]);
                splt(Bs[(col+r)*36 + k0 + q + 4], bh[1], bl[1]);
                #pragma unroll
                for (int mt = 0; mt < 2; mt++){
                    mma8(acc[mt][nt], ah[mt], bh);
                    mma8(acc[mt][nt], ah[mt], bl);
                    mma8(acc[mt][nt], al[mt], bh);
                }
            }
        }
    }

    // direct write (rows i0-block, cols j0-block)
    float si0[2], si1[2];
    #pragma unroll
    for (int mt = 0; mt < 2; mt++){
        int rowb = i0 + wy*32 + mt*16;
        si0[mt] = g_sq[b*NN + rowb + r];
        si1[mt] = g_sq[b*NN + rowb + r + 8];
        #pragma unroll
        for (int nt = 0; nt < 8; nt++){
            int colb = j0 + wx*64 + nt*8 + 2*q;
            float sj0 = g_sq[b*NN + colb], sj1 = g_sq[b*NN + colb + 1];
            float2 v0, v1;
            v0.x = si0[mt] + sj0 - 2.f*acc[mt][nt][0];
            v0.y = si0[mt] + sj1 - 2.f*acc[mt][nt][1];
            v1.x = si1[mt] + sj0 - 2.f*acc[mt][nt][2];
            v1.y = si1[mt] + sj1 - 2.f*acc[mt][nt][3];
            *(float2*)(g_d2 + (size_t)(b*NN + i0 + wy*32 + mt*16 + r)*NN + colb)     = v0;
            *(float2*)(g_d2 + (size_t)(b*NN + i0 + wy*32 + mt*16 + r + 8)*NN + colb) = v1;
        }
    }

    // mirrored write for off-diagonal tiles: stage 64 cols x 128 rows, twice.
    // Tb stride 132 floats: 132 % 4 == 0 keeps float4 reads 16B-aligned;
    // 132 % 32 == 4 keeps the read phase conflict-free.
    if (i0 != j0){
        float* Tb = SU;        // [64][132] = 8448 floats < 9216
        for (int h = 0; h < 2; h++){
            __syncthreads();
            if (wx == h){
                #pragma unroll
                for (int mt = 0; mt < 2; mt++){
                    int rowl = wy*32 + mt*16;
                    #pragma unroll
                    for (int nt = 0; nt < 8; nt++){
                        int coll = nt*8 + 2*q;          // 0..63 within half
                        int colb = j0 + h*64 + coll;
                        float sj0 = g_sq[b*NN + colb], sj1 = g_sq[b*NN + colb + 1];
                        Tb[(coll    )*132 + rowl + r]     = si0[mt] + sj0 - 2.f*acc[mt][nt][0];
                        Tb[(coll + 1)*132 + rowl + r]     = si0[mt] + sj1 - 2.f*acc[mt][nt][1];
                        Tb[(coll    )*132 + rowl + r + 8] = si1[mt] + sj0 - 2.f*acc[mt][nt][2];
                        Tb[(coll + 1)*132 + rowl + r + 8] = si1[mt] + sj1 - 2.f*acc[mt][nt][3];
                    }
                }
            }
            __syncthreads();
            for (int i = t; i < 64*32; i += 256){
                int row = i >> 5, c4 = (i & 31)*4;
                float4 v = *(const float4*)&Tb[row*132 + c4];
                *(float4*)(g_d2 + (size_t)(b*NN + j0 + h*64 + row)*NN + i0 + c4) = v;
            }
        }
    }
}

// ---- fused kNN d=64 select (from g_d2) + conv2 layer-1 (independent) --------
// blocks [0, 8192): select ; blocks [8192, 12288): convA2
__global__ void __launch_bounds__(256) k_selA2(const float* __restrict__ W,
                                               const float* __restrict__ bias){
    __shared__ float SU[9216];     // used only by convA2 branch
    int t = threadIdx.x;
    if (blockIdx.x < 8192){
        int warp = t >> 5, lane = t & 31;
        int node = blockIdx.x*8 + warp;
        const float* row = g_d2 + (size_t)node*NN;
        float v[16];
        #pragma unroll
        for (int u4 = 0; u4 < 4; u4++){
            float4 x = *(const float4*)(row + lane*16 + u4*4);
            v[u4*4+0] = x.x; v[u4*4+1] = x.y; v[u4*4+2] = x.z; v[u4*4+3] = x.w;
        }
        sel16<1>(v, lane, g_idx + (size_t)node*KNB);
    } else {
        float* Wd = SU;            // [32*128]
        float* Wb = SU + 4096;     // [32*128]
        float* Fs = SU + 8192;     // [16*64]
        int base = (blockIdx.x - 8192)*16;

        for (int idx = t; idx < 1024; idx += 256)
            Fs[idx] = g_x1[(size_t)base*64 + idx];

        int m  = t >> 4;
        int cg = (t & 15)*8;
        float a[8], cc[8];
        float4 bb0 = *(const float4*)(bias + cg);
        float4 bb1 = *(const float4*)(bias + cg + 4);
        a[0]=bb0.x; a[1]=bb0.y; a[2]=bb0.z; a[3]=bb0.w;
        a[4]=bb1.x; a[5]=bb1.y; a[6]=bb1.z; a[7]=bb1.w;
        #pragma unroll
        for (int q = 0; q < 8; q++) cc[q] = 0.f;

        for (int db = 0; db < 64; db += 32){
            __syncthreads();
            for (int idx = t; idx < 4096; idx += 256){
                int d = idx >> 7, c = idx & 127;
                float wt = W[(db + d)*128 + c];
                float wb = W[(64 + db + d)*128 + c];
                Wd[idx] = wt - wb;
                Wb[idx] = wb;
            }
            __syncthreads();
            #pragma unroll 4
            for (int d = 0; d < 32; d++){
                float v = Fs[m*64 + db + d];
                float4 w0 = *(const float4*)&Wd[d*128 + cg];
                float4 w1 = *(const float4*)&Wd[d*128 + cg + 4];
                float4 u0 = *(const float4*)&Wb[d*128 + cg];
                float4 u1 = *(const float4*)&Wb[d*128 + cg + 4];
                a[0] += v*w0.x; a[1] += v*w0.y; a[2] += v*w0.z; a[3] += v*w0.w;
                a[4] += v*w1.x; a[5] += v*w1.y; a[6] += v*w1.z; a[7] += v*w1.w;
                cc[0] += v*u0.x; cc[1] += v*u0.y; cc[2] += v*u0.z; cc[3] += v*u0.w;
                cc[4] += v*u1.x; cc[5] += v*u1.y; cc[6] += v*u1.z; cc[7] += v*u1.w;
            }
        }
        int node = base + m;
        float4* pa = (float4*)(g_A + (size_t)node*128 + cg);
        float4* pc = (float4*)(g_C + (size_t)node*128 + cg);
        pa[0] = make_float4(a[0],a[1],a[2],a[3]);
        pa[1] = make_float4(a[4],a[5],a[6],a[7]);
        pc[0] = make_float4(cc[0],cc[1],cc[2],cc[3]);
        pc[1] = make_float4(cc[4],cc[5],cc[6],cc[7]);
    }
}

// ---------------- conv1 edge layer-2: D^T = W^T @ h^T (tf32, no smem) --------
__global__ void k_edge64(const float* __restrict__ bias){
    int t = threadIdx.x, warp = t >> 5, lane = t & 31;
    int node = blockIdx.x*8 + warp;
    int b = node / NN;
    int r = lane >> 2, q = lane & 3;

    int j0 = b*NN + __ldg(g_idx + (size_t)node*KNB + r);
    int j1 = b*NN + __ldg(g_idx + (size_t)node*KNB + 8 + r);
    const float* Ai = g_A + (size_t)node*64;
    const float* C0 = g_C + (size_t)j0*64;
    const float* C1 = g_C + (size_t)j1*64;

    float acc[4][2][4];
    #pragma unroll
    for (int mt = 0; mt < 4; mt++)
        #pragma unroll
        for (int n = 0; n < 2; n++)
            #pragma unroll
            for (int i = 0; i < 4; i++) acc[mt][n][i] = 0.f;

    #pragma unroll
    for (int kb = 0; kb < 8; kb++){
        int c0 = kb*8 + q;
        float ai0 = __ldg(Ai + c0), ai1 = __ldg(Ai + c0 + 4);
        unsigned b0h[2], b0l[2], b1h[2], b1l[2];
        splt(leaky(ai0 + __ldg(C0 + c0)),     b0h[0], b0l[0]);
        splt(leaky(ai1 + __ldg(C0 + c0 + 4)), b0h[1], b0l[1]);
        splt(leaky(ai0 + __ldg(C1 + c0)),     b1h[0], b1l[0]);
        splt(leaky(ai1 + __ldg(C1 + c0 + 4)), b1h[1], b1l[1]);
        #pragma unroll
        for (int mt = 0; mt < 4; mt++){
            uint4 H = __ldg(&g_w1Ah[(mt*8 + kb)*32 + lane]);
            uint4 L = __ldg(&g_w1Al[(mt*8 + kb)*32 + lane]);
            mma8(acc[mt][0], (const unsigned*)&H, b0h);
            mma8(acc[mt][0], (const unsigned*)&H, b0l);
            mma8(acc[mt][0], (const unsigned*)&L, b0h);
            mma8(acc[mt][1], (const unsigned*)&H, b1h);
            mma8(acc[mt][1], (const unsigned*)&H, b1l);
            mma8(acc[mt][1], (const unsigned*)&L, b1h);
        }
    }

    float ssum = 0.f;
    #pragma unroll
    for (int mt = 0; mt < 4; mt++){
        float m0 = fmaxf(fmaxf(acc[mt][0][0], acc[mt][0][1]),
                         fmaxf(acc[mt][1][0], acc[mt][1][1]));
        float m1 = fmaxf(fmaxf(acc[mt][0][2], acc[mt][0][3]),
                         fmaxf(acc[mt][1][2], acc[mt][1][3]));
        m0 = fmaxf(m0, __shfl_xor_sync(0xffffffffu, m0, 1));
        m0 = fmaxf(m0, __shfl_xor_sync(0xffffffffu, m0, 2));
        m1 = fmaxf(m1, __shfl_xor_sync(0xffffffffu, m1, 1));
        m1 = fmaxf(m1, __shfl_xor_sync(0xffffffffu, m1, 2));
        if (q == 0){
            int ch = mt*16 + r;
            float v0 = leaky(m0 + __ldg(bias + ch));
            float v1 = leaky(m1 + __ldg(bias + ch + 8));
            g_x1[(size_t)node*64 + ch]     = v0;
            g_x1[(size_t)node*64 + ch + 8] = v1;
            ssum += v0*v0 + v1*v1;
        }
    }
    ssum += __shfl_xor_sync(0xffffffffu, ssum, 4);
    ssum += __shfl_xor_sync(0xffffffffu, ssum, 8);
    ssum += __shfl_xor_sync(0xffffffffu, ssum, 16);
    if (lane == 0) g_sq[node] = ssum;
}

// ---------------- conv2 edge layer-2: D^T = W^T @ h^T (bf16, no smem) --------
__global__ void k_edge128(const float* __restrict__ bias){
    int t = threadIdx.x, warp = t >> 5, lane = t & 31;
    int node = blockIdx.x*8 + warp;
    int b = node / NN;
    int r = lane >> 2, q = lane & 3;

    int j0 = b*NN + __ldg(g_idx + (size_t)node*KNB + r);
    int j1 = b*NN + __ldg(g_idx + (size_t)node*KNB + 8 + r);
    const float* Ai = g_A + (size_t)node*128;
    const float* C0 = g_C + (size_t)j0*128;
    const float* C1 = g_C + (size_t)j1*128;

    float acc[4][2][4];
    #pragma unroll
    for (int mt = 0; mt < 4; mt++)
        #pragma unroll
        for (int n = 0; n < 2; n++)
            #pragma unroll
            for (int i = 0; i < 4; i++) acc[mt][n][i] = 0.f;

    #pragma unroll
    for (int kb = 0; kb < 8; kb++){
        int c0 = kb*16 + 2*q;
        float2 ai0 = *(const float2*)(Ai + c0);
        float2 ai1 = *(const float2*)(Ai + c0 + 8);
        float2 ca0 = *(const float2*)(C0 + c0);
        float2 ca1 = *(const float2*)(C0 + c0 + 8);
        float2 cb0 = *(const float2*)(C1 + c0);
        float2 cb1 = *(const float2*)(C1 + c0 + 8);
        unsigned b0h[2], b0l[2], b1h[2], b1l[2];
        split2(leaky(ai0.x + ca0.x), leaky(ai0.y + ca0.y), b0h[0], b0l[0]);
        split2(leaky(ai1.x + ca1.x), leaky(ai1.y + ca1.y), b0h[1], b0l[1]);
        split2(leaky(ai0.x + cb0.x), leaky(ai0.y + cb0.y), b1h[0], b1l[0]);
        split2(leaky(ai1.x + cb1.x), leaky(ai1.y + cb1.y), b1h[1], b1l[1]);
        #pragma unroll
        for (int mt = 0; mt < 4; mt++){
            uint4 H = __ldg(&g_w2Ah[(mt*8 + kb)*32 + lane]);
            uint4 L = __ldg(&g_w2Al[(mt*8 + kb)*32 + lane]);
            mma16(acc[mt][0], (const unsigned*)&H, b0h);
            mma16(acc[mt][0], (const unsigned*)&H, b0l);
            mma16(acc[mt][0], (const unsigned*)&L, b0h);
            mma16(acc[mt][1], (const unsigned*)&H, b1h);
            mma16(acc[mt][1], (const unsigned*)&H, b1l);
            mma16(acc[mt][1], (const unsigned*)&L, b1h);
        }
    }

    #pragma unroll
    for (int mt = 0; mt < 4; mt++){
        float m0 = fmaxf(fmaxf(acc[mt][0][0], acc[mt][0][1]),
                         fmaxf(acc[mt][1][0], acc[mt][1][1]));
        float m1 = fmaxf(fmaxf(acc[mt][0][2], acc[mt][0][3]),
                         fmaxf(acc[mt][1][2], acc[mt][1][3]));
        m0 = fmaxf(m0, __shfl_xor_sync(0xffffffffu, m0, 1));
        m0 = fmaxf(m0, __shfl_xor_sync(0xffffffffu, m0, 2));
        m1 = fmaxf(m1, __shfl_xor_sync(0xffffffffu, m1, 1));
        m1 = fmaxf(m1, __shfl_xor_sync(0xffffffffu, m1, 2));
        if (q == 0){
            int ch = mt*16 + r;
            g_x2[(size_t)node*64 + ch]     = leaky(m0 + __ldg(bias + ch));
            g_x2[(size_t)node*64 + ch + 8] = leaky(m1 + __ldg(bias + ch + 8));
        }
    }
}

__device__ __forceinline__ float featval(int node, int d){
    if (d < 5)   return g_xx[node*5 + d];
    if (d < 69)  return g_x1[(size_t)node*64 + d - 5];
    if (d < 133) return g_x2[(size_t)node*64 + d - 69];
    return 0.f;
}

// ---------------- lin1: [BN x 144] @ [144 x 512] + leaky (bf16) --------------
__global__ void k_lin1(const float* __restrict__ bl1){
    __shared__ unsigned CSh[64*76];
    __shared__ unsigned CSl[64*76];
    int t = threadIdx.x, lane = t & 31, w = t >> 5;
    int base = blockIdx.x*64;
    for (int i = t; i < 64*72; i += 256){
        int m = i / 72, p = i - m*72;
        int node = base + m;
        float v0 = featval(node, 2*p);
        float v1 = featval(node, 2*p + 1);
        unsigned h, l;
        split2(v0, v1, h, l);
        CSh[m*76 + p] = h;
        CSl[m*76 + p] = l;
    }
    __syncthreads();

    int r = lane >> 2, q = lane & 3;
    int n0 = w*64;
    for (int np = 0; np < 2; np++){
        float acc[4][4][4];
        #pragma unroll
        for (int mt = 0; mt < 4; mt++)
            #pragma unroll
            for (int nt = 0; nt < 4; nt++)
                #pragma unroll
                for (int i = 0; i < 4; i++) acc[mt][nt][i] = 0.f;

        for (int kb = 0; kb < 9; kb++){
            unsigned ah[4][4], al[4][4];
            #pragma unroll
            for (int mt = 0; mt < 4; mt++){
                int rb = mt*16;
                ah[mt][0] = CSh[(rb+r)*76 + kb*8 + q];       al[mt][0] = CSl[(rb+r)*76 + kb*8 + q];
                ah[mt][1] = CSh[(rb+r+8)*76 + kb*8 + q];     al[mt][1] = CSl[(rb+r+8)*76 + kb*8 + q];
                ah[mt][2] = CSh[(rb+r)*76 + kb*8 + 4 + q];   al[mt][2] = CSl[(rb+r)*76 + kb*8 + 4 + q];
                ah[mt][3] = CSh[(rb+r+8)*76 + kb*8 + 4 + q]; al[mt][3] = CSl[(rb+r+8)*76 + kb*8 + 4 + q];
            }
            #pragma unroll
            for (int nt = 0; nt < 4; nt++){
                uint4 wv = __ldg(&g_wl1pb[(kb*64 + w*8 + np*4 + nt)*32 + lane]);
                unsigned bh[2] = {wv.x, wv.y};
                unsigned bl[2] = {wv.z, wv.w};
                #pragma unroll
                for (int mt = 0; mt < 4; mt++){
                    mma16(acc[mt][nt], ah[mt], bh);
                    mma16(acc[mt][nt], ah[mt], bl);
                    mma16(acc[mt][nt], al[mt], bh);
                }
            }
        }
        #pragma unroll
        for (int mt = 0; mt < 4; mt++){
            #pragma unroll
            for (int nt = 0; nt < 4; nt++){
                int node = base + mt*16 + r;
                int col = n0 + (np*4 + nt)*8 + q*2;
                float b0 = __ldg(bl1 + col), b1 = __ldg(bl1 + col + 1);
                float2 u0, u1;
                u0.x = leaky(acc[mt][nt][0] + b0); u0.y = leaky(acc[mt][nt][1] + b1);
                u1.x = leaky(acc[mt][nt][2] + b0); u1.y = leaky(acc[mt][nt][3] + b1);
                *(float2*)(g_hs + (size_t)node*512 + col)     = u0;
                *(float2*)(g_hs + (size_t)(node+8)*512 + col) = u1;
            }
        }
    }
}

// ---------------- lin2: [BN x 512] @ [512 x 256] + max-pool (bf16) -----------
__global__ void k_lin2(const float* __restrict__ bl2){
    __shared__ unsigned Ash[64*36];
    __shared__ unsigned Asl[64*36];
    int t = threadIdx.x, lane = t & 31, w = t >> 5;
    int base = blockIdx.x*64;
    int g = base / NN;
    int r = lane >> 2, q = lane & 3;
    int n0 = w*32;

    float acc[4][4][4];
    #pragma unroll
    for (int mt = 0; mt < 4; mt++)
        #pragma unroll
        for (int nt = 0; nt < 4; nt++)
            #pragma unroll
            for (int i = 0; i < 4; i++) acc[mt][nt][i] = 0.f;

    for (int kc = 0; kc < 512; kc += 64){
        __syncthreads();
        for (int i = t; i < 1024; i += 256){
            int m = i >> 4, sub = i & 15;
            float4 v = *(const float4*)(g_hs + (size_t)(base + m)*512 + kc + sub*4);
            unsigned h0, l0, h1, l1;
            split2(v.x, v.y, h0, l0);
            split2(v.z, v.w, h1, l1);
            Ash[m*36 + sub*2]     = h0;
            Ash[m*36 + sub*2 + 1] = h1;
            Asl[m*36 + sub*2]     = l0;
            Asl[m*36 + sub*2 + 1] = l1;
        }
        __syncthreads();
        #pragma unroll
        for (int kb = 0; kb < 4; kb++){
            unsigned ah[4][4], al[4][4];
            #pragma unroll
            for (int mt = 0; mt < 4; mt++){
                int rb = mt*16;
                ah[mt][0] = Ash[(rb+r)*36 + kb*8 + q];       al[mt][0] = Asl[(rb+r)*36 + kb*8 + q];
                ah[mt][1] = Ash[(rb+r+8)*36 + kb*8 + q];     al[mt][1] = Asl[(rb+r+8)*36 + kb*8 + q];
                ah[mt][2] = Ash[(rb+r)*36 + kb*8 + 4 + q];   al[mt][2] = Asl[(rb+r)*36 + kb*8 + 4 + q];
                ah[mt][3] = Ash[(rb+r+8)*36 + kb*8 + 4 + q]; al[mt][3] = Asl[(rb+r+8)*36 + kb*8 + 4 + q];
            }
            int kbg = (kc >> 4) + kb;
            #pragma unroll
            for (int nt = 0; nt < 4; nt++){
                uint4 wv = __ldg(&g_wl2pb[(kbg*32 + w*4 + nt)*32 + lane]);
                unsigned bh[2] = {wv.x, wv.y};
                unsigned bl[2] = {wv.z, wv.w};
                #pragma unroll
                for (int mt = 0; mt < 4; mt++){
                    mma16(acc[mt][nt], ah[mt], bh);
                    mma16(acc[mt][nt], ah[mt], bl);
                    mma16(acc[mt][nt], al[mt], bh);
                }
            }
        }
    }

    #pragma unroll
    for (int nt = 0; nt < 4; nt++){
        float m0 = -3.4e38f, m1 = -3.4e38f;
        #pragma unroll
        for (int mt = 0; mt < 4; mt++){
            m0 = fmaxf(m0, fmaxf(acc[mt][nt][0], acc[mt][nt][2]));
            m1 = fmaxf(m1, fmaxf(acc[mt][nt][1], acc[mt][nt][3]));
        }
        #pragma unroll
        for (int off = 4; off < 32; off <<= 1){
            m0 = fmaxf(m0, __shfl_xor_sync(0xffffffffu, m0, off));
            m1 = fmaxf(m1, __shfl_xor_sync(0xffffffffu, m1, off));
        }
        if (lane < 4){
            int col = n0 + nt*8 + lane*2;
            atomicMaxFloat(&g_pool[g*256 + col],     m0 + __ldg(bl2 + col));
            atomicMaxFloat(&g_pool[g*256 + col + 1], m1 + __ldg(bl2 + col + 1));
        }
    }
}

// ---------------- head: leaky -> 256x128 -> leaky -> 128x3 -------------------
__global__ void k_head(const float* __restrict__ wm1, const float* __restrict__ bm1,
                       const float* __restrict__ wm2, const float* __restrict__ bm2,
                       float* __restrict__ out){
    __shared__ float gs[256];
    __shared__ float ms[128];
    int b = blockIdx.x, t = threadIdx.x;
    for (int c = t; c < 256; c += 128) gs[c] = leaky(g_pool[b*256 + c]);
    __syncthreads();
    float acc = bm1[t];
    #pragma unroll 8
    for (int d = 0; d < 256; d++) acc += gs[d]*wm1[d*128 + t];
    ms[t] = leaky(acc);
    __syncthreads();
    if (t < 3){
        float o = bm2[t];
        #pragma unroll 8
        for (int d = 0; d < 128; d++) o += ms[d]*wm2[d*3 + t];
        out[b*3 + t] = o;
    }
}

// -----------------------------------------------------------------------------
extern "C" void kernel_launch(void* const* d_in, const int* in_sizes, int n_in,
                              void* d_out, int out_size){
    const float* x   = (const float*)d_in[0];
    const float* pos = (const float*)d_in[1];
    const float* tq  = (const float*)d_in[2];
    const float* w1a = (const float*)d_in[4];
    const float* b1a = (const float*)d_in[5];
    const float* w1b = (const float*)d_in[6];
    const float* b1b = (const float*)d_in[7];
    const float* w2a = (const float*)d_in[8];
    const float* b2a = (const float*)d_in[9];
    const float* w2b = (const float*)d_in[10];
    const float* b2b = (const float*)d_in[11];
    const float* wl1 = (const float*)d_in[12];
    const float* bl1 = (const float*)d_in[13];
    const float* wl2 = (const float*)d_in[14];
    const float* bl2 = (const float*)d_in[15];
    const float* wm1 = (const float*)d_in[16];
    const float* bm1 = (const float*)d_in[17];
    const float* wm2 = (const float*)d_in[18];
    const float* bm2 = (const float*)d_in[19];
    float* out = (float*)d_out;

    // prep (weights, pool) + build (xx, sq5) — independent, one launch
    k_prepbuild<<<208 + BN/256, 256>>>(w1b, w2b, wl1, wl2, x, pos, tq);

    // conv1: kNN5 || convA1 (independent given xx), then edge
    k_knn5A1<<<8192 + (BN*64)/256, 256>>>(w1a, b1a);
    k_edge64<<<BN/8, 256>>>(b1b);        // also emits g_sq

    // conv2: symmetric d2-GEMM, then (select || conv2 L1), then edge
    k_d2sym<<<BATCH*10, 256>>>();
    k_selA2<<<8192 + BN/16, 256>>>(w2a, b2a);
    k_edge128<<<BN/8, 256>>>(b2b);

    // lin1 -> g_hs, lin2 + fused pool, head
    k_lin1<<<BN/64, 256>>>(bl1);
    k_lin2<<<BN/64, 256>>>(bl2);
    k_head<<<BATCH, 128>>>(wm1, bm1, wm2, bm2, out);
}

// round 17
// speedup vs baseline: 1.1538x; 1.1105x over previous
#include <cuda_runtime.h>
#include <cuda_bf16.h>
#include <cstdint>

#define BATCH 128
#define NN    512
#define KNB   16
#define BN    (BATCH*NN)
#define NEGS  0.01f

// ---------------- scratch (device globals; no allocation allowed) -------------
__device__ float g_xx[BN*5];
__device__ float g_x1[BN*64];
__device__ float g_x2[BN*64];
__device__ int   g_idx[BN*KNB];
__device__ float g_A[(size_t)BN*128];
__device__ float g_C[(size_t)BN*128];
__device__ float g_pool[BATCH*256];
__device__ float g_sq[BN];
__device__ float g_sq5[BN];
__device__ float g_d2[(size_t)BN*NN];   // pairwise distances (conv2 kNN)
__device__ float g_hs[(size_t)BN*512];  // lin1 -> lin2 buffer

// W^T A-operand fragment tables for edge kernels (indexed (mt*8+kb)*32+lane)
__device__ uint4 g_w1Ah[1024], g_w1Al[1024];   // conv1 W2 (64x64), tf32 split
__device__ uint4 g_w2Ah[1024];                 // conv2 W2 (128x64), bf16 hi only
// bf16 split fragment-packed B-operand weights for lin kernels
__device__ uint4  g_wl1pb[9*64*32];      // 144x512 (rows >=133 zero)
__device__ uint4  g_wl2pb[32*32*32];     // 512x256

__device__ __forceinline__ float leaky(float v){ return v > 0.f ? v : NEGS*v; }

__device__ __forceinline__ void atomicMaxFloat(float* addr, float value){
    if (value >= 0.f) atomicMax((int*)addr, __float_as_int(value));
    else              atomicMin((unsigned int*)addr, __float_as_uint(value));
}

__device__ __forceinline__ unsigned f2tf(float x){
    unsigned u; asm("cvt.rna.tf32.f32 %0, %1;" : "=r"(u) : "f"(x)); return u;
}
__device__ __forceinline__ void splt(float x, unsigned &h, unsigned &l){
    h = f2tf(x);
    l = f2tf(x - __uint_as_float(h));
}
__device__ __forceinline__ void mma8(float* c, const unsigned* a, const unsigned* b){
    asm("mma.sync.aligned.m16n8k8.row.col.f32.tf32.tf32.f32 "
        "{%0,%1,%2,%3}, {%4,%5,%6,%7}, {%8,%9}, {%0,%1,%2,%3};"
        : "+f"(c[0]), "+f"(c[1]), "+f"(c[2]), "+f"(c[3])
        : "r"(a[0]), "r"(a[1]), "r"(a[2]), "r"(a[3]), "r"(b[0]), "r"(b[1]));
}
__device__ __forceinline__ void mma16(float* c, const unsigned* a, const unsigned* b){
    asm("mma.sync.aligned.m16n8k16.row.col.f32.bf16.bf16.f32 "
        "{%0,%1,%2,%3}, {%4,%5,%6,%7}, {%8,%9}, {%0,%1,%2,%3};"
        : "+f"(c[0]), "+f"(c[1]), "+f"(c[2]), "+f"(c[3])
        : "r"(a[0]), "r"(a[1]), "r"(a[2]), "r"(a[3]), "r"(b[0]), "r"(b[1]));
}
__device__ __forceinline__ unsigned packbf(float v0, float v1){
    unsigned d; asm("cvt.rn.bf16x2.f32 %0, %1, %2;" : "=r"(d) : "f"(v1), "f"(v0)); return d;
}
__device__ __forceinline__ float bflo(unsigned p){ return __uint_as_float(p << 16); }
__device__ __forceinline__ float bfhi(unsigned p){ return __uint_as_float(p & 0xffff0000u); }
__device__ __forceinline__ void split2(float v0, float v1, unsigned &h, unsigned &l){
    h = packbf(v0, v1);
    l = packbf(v0 - bflo(h), v1 - bfhi(h));
}

// sortable-u32 transform
__device__ __forceinline__ unsigned fsort(float f){
    unsigned b = __float_as_uint(f);
    return b ^ (((int)b >> 31) | 0x80000000u);
}

// index mappings for sel16 slot u on lane:
// MODE 0: j = u*32 + lane   (knn5)
// MODE 1: j = lane*16 + u   (select from contiguous row)
template<int MODE>
__device__ __forceinline__ int sel_j(int lane, int u){
    if (MODE == 0) return u*32 + lane;
    return lane*16 + u;
}
template<int MODE>
__device__ __forceinline__ int sel_u(int j){
    if (MODE == 0) return j >> 5;
    return j & 15;
}

// warp-cooperative exact top-16-of-512 with lower-index tiebreak.
template<int MODE>
__device__ __forceinline__ void sel16(const float* v, int lane, int* out){
    const unsigned long long INF = ~0ull;
    unsigned long long s0 = INF, s1 = INF, s2 = INF, s3 = INF;
    #pragma unroll
    for (int u = 0; u < 16; u++){
        int j = sel_j<MODE>(lane, u);
        unsigned long long k = ((unsigned long long)fsort(v[u]) << 32) | (unsigned)j;
        if (k < s3){
            s3 = k;
            if (s3 < s2){ unsigned long long t = s2; s2 = s3; s3 = t; }
            if (s2 < s1){ unsigned long long t = s1; s1 = s2; s2 = t; }
            if (s1 < s0){ unsigned long long t = s0; s0 = s1; s1 = t; }
        }
    }
    unsigned mask = 0;
    int mine = 0;
    #pragma unroll 1
    for (int r = 0; r < KNB; r++){
        unsigned long long m = s0;
        #pragma unroll
        for (int off = 16; off; off >>= 1){
            unsigned long long o = __shfl_xor_sync(0xffffffffu, m, off);
            if (o < m) m = o;
        }
        if (lane == r) mine = (int)(unsigned)(m & 0xffffffffu);
        if (s0 == m){
            int j = (int)(unsigned)(m & 0xffffffffu);
            mask |= 1u << sel_u<MODE>(j);
            s0 = s1; s1 = s2; s2 = s3; s3 = INF;
            if (s0 == INF && mask != 0xffffu){
                #pragma unroll
                for (int u2 = 0; u2 < 16; u2++){
                    if (!((mask >> u2) & 1u)){
                        int j2 = sel_j<MODE>(lane, u2);
                        unsigned long long k = ((unsigned long long)fsort(v[u2]) << 32) | (unsigned)j2;
                        if (k < s3){
                            s3 = k;
                            if (s3 < s2){ unsigned long long t = s2; s2 = s3; s3 = t; }
                            if (s2 < s1){ unsigned long long t = s1; s1 = s2; s2 = t; }
                            if (s1 < s0){ unsigned long long t = s0; s0 = s1; s1 = t; }
                        }
                    }
                }
            }
        }
    }
    if (lane < KNB) out[lane] = mine;
}

// ---------------- fused prep (weight packing + pool init) + build ------------
__global__ void k_prepbuild(const float* __restrict__ w1b, const float* __restrict__ w2b,
                            const float* __restrict__ wl1, const float* __restrict__ wl2,
                            const float* __restrict__ x, const float* __restrict__ pos,
                            const float* __restrict__ tq){
    if (blockIdx.x < 208){
        int i = blockIdx.x*256 + threadIdx.x;
        if (i < BATCH*256) g_pool[i] = __int_as_float(0xff800000); // -inf
        if (i < 1024){
            int lane = i & 31, tmp = i >> 5;
            int kb = tmp & 7, mt = tmp >> 3;
            int r = lane >> 2, q = lane & 3;
            int R = mt*16 + r, k0 = kb*8 + q;
            uint4 H, L;
            splt(w1b[k0*64 + R],       H.x, L.x);
            splt(w1b[k0*64 + R + 8],   H.y, L.y);
            splt(w1b[(k0+4)*64 + R],   H.z, L.z);
            splt(w1b[(k0+4)*64 + R+8], H.w, L.w);
            g_w1Ah[i] = H; g_w1Al[i] = L;
        } else if (i < 2048){
            int rel = i - 1024;
            int lane = rel & 31, tmp = rel >> 5;
            int kb = tmp & 7, mt = tmp >> 3;
            int r = lane >> 2, q = lane & 3;
            int R = mt*16 + r, c0 = kb*16 + 2*q;
            uint4 H; unsigned dummy;
            split2(w2b[c0*64 + R],       w2b[(c0+1)*64 + R],     H.x, dummy);
            split2(w2b[c0*64 + R + 8],   w2b[(c0+1)*64 + R + 8], H.y, dummy);
            split2(w2b[(c0+8)*64 + R],   w2b[(c0+9)*64 + R],     H.z, dummy);
            split2(w2b[(c0+8)*64 + R+8], w2b[(c0+9)*64 + R + 8], H.w, dummy);
            g_w2Ah[rel] = H;
        } else if (i < 53248){
            const float* W; uint4* dst; int ncb, ncols, nrows, rel;
            if (i < 20480){ rel = i - 2048;  W = wl1; dst = g_wl1pb; ncb = 64; ncols = 512; nrows = 133; }
            else          { rel = i - 20480; W = wl2; dst = g_wl2pb; ncb = 32; ncols = 256; nrows = 512; }
            int lane = rel & 31, tmp = rel >> 5;
            int cb = tmp % ncb, kb = tmp / ncb;
            int r = lane >> 2, q = lane & 3, col = cb*8 + r;
            int k0 = kb*16 + 2*q;
            float v00 = (k0     < nrows) ? W[(k0    )*ncols + col] : 0.f;
            float v01 = (k0 + 1 < nrows) ? W[(k0 + 1)*ncols + col] : 0.f;
            float v10 = (k0 + 8 < nrows) ? W[(k0 + 8)*ncols + col] : 0.f;
            float v11 = (k0 + 9 < nrows) ? W[(k0 + 9)*ncols + col] : 0.f;
            unsigned h0, l0, h1, l1;
            split2(v00, v01, h0, l0);
            split2(v10, v11, h1, l1);
            dst[rel] = make_uint4(h0, h1, l0, l1);
        }
    } else {
        int i = (blockIdx.x - 208)*256 + threadIdx.x;
        if (i < BN){
            float tv = tq[i], xv = x[i];
            float p0 = pos[i*3+0], p1 = pos[i*3+1], p2 = pos[i*3+2];
            g_xx[i*5+0] = tv;
            g_xx[i*5+1] = xv;
            g_xx[i*5+2] = p0;
            g_xx[i*5+3] = p1;
            g_xx[i*5+4] = p2;
            g_sq5[i] = tv*tv + xv*xv + p0*p0 + p1*p1 + p2*p2;
        }
    }
}

// ---------------- fused kNN d=5 + conv1 layer-1 ------------------------------
__global__ void k_knn5A1(const float* __restrict__ W, const float* __restrict__ bias){
    __shared__ float tile[128*8];
    if (blockIdx.x < 8192){
        int b  = blockIdx.x >> 6;
        int q0 = (blockIdx.x & 63) * 8;
        int warp = threadIdx.x >> 5, lane = threadIdx.x & 31;
        int qi = q0 + warp;
        int node = b*NN + qi;
        const float* Fb = g_xx + (size_t)b*NN*5;

        float f0, f1, f2, f3, f4;
        { const float* fq = Fb + qi*5; f0=fq[0]; f1=fq[1]; f2=fq[2]; f3=fq[3]; f4=fq[4]; }
        float sqi = g_sq5[node];

        float d2loc[16];
        for (int t4 = 0; t4 < 4; t4++){
            __syncthreads();
            for (int idx = threadIdx.x; idx < 1024; idx += 256){
                int rrow = idx >> 3, c = idx & 7;
                int grow = t4*128 + rrow;
                float v = 0.f;
                if (c < 5)       v = Fb[grow*5 + c];
                else if (c == 5) v = g_sq5[b*NN + grow];
                tile[idx] = v;
            }
            __syncthreads();
            #pragma unroll
            for (int u = 0; u < 4; u++){
                int jj = u*32 + lane;
                const float* tr = &tile[jj*8];
                float4 p  = *(const float4*)tr;
                float2 p2 = *(const float2*)(tr + 4);
                float dot = f0*p.x + f1*p.y + f2*p.z + f3*p.w + f4*p2.x;
                d2loc[t4*4 + u] = sqi + p2.y - 2.f*dot;
            }
        }
        sel16<0>(d2loc, lane, g_idx + (size_t)node*KNB);
    } else {
        int t = (blockIdx.x - 8192)*256 + threadIdx.x;
        if (t >= BN*64) return;
        int i = t >> 6, c = t & 63;
        const float* f = g_xx + (size_t)i*5;
        float a = bias[c], cc = 0.f;
        #pragma unroll
        for (int d = 0; d < 5; d++){
            float v  = f[d];
            float wt = W[d*64 + c];
            float wb = W[(5 + d)*64 + c];
            a  += v*(wt - wb);
            cc += v*wb;
        }
        g_A[(size_t)i*64 + c] = a;
        g_C[(size_t)i*64 + c] = cc;
    }
}

// ------- SYMMETRIC d2-GEMM (split-tf32, upper triangle), standalone ----------
__global__ void k_d2sym(){
    __shared__ float SU[9216];     // As[128*36] | Bs[128*36]; Tb aliases
    int t = threadIdx.x;
    float* As = SU;
    float* Bs = SU + 4608;
    int blk = blockIdx.x;
    int b = blk / 10;
    int tt = blk - b*10;
    int ti, tj;
    if (tt < 4)      { ti = 0; tj = tt; }
    else if (tt < 7) { ti = 1; tj = tt - 3; }
    else if (tt < 9) { ti = 2; tj = tt - 5; }
    else             { ti = 3; tj = 3; }
    int i0 = ti*128, j0 = tj*128;
    const float* Fb = g_x1 + (size_t)b*NN*64;
    int lane = t & 31, w = t >> 5;
    int wx = w & 1, wy = w >> 1;
    int r = lane >> 2, q = lane & 3;

    float acc[2][8][4];
    #pragma unroll
    for (int mt = 0; mt < 2; mt++)
        #pragma unroll
        for (int nt = 0; nt < 8; nt++)
            #pragma unroll
            for (int i = 0; i < 4; i++) acc[mt][nt][i] = 0.f;

    for (int kc = 0; kc < 64; kc += 32){
        __syncthreads();
        for (int i = t; i < 128*8; i += 256){
            int m = i >> 3, kq = (i & 7)*4;
            *(float4*)&As[m*36 + kq] = *(const float4*)(Fb + (i0+m)*64 + kc + kq);
            *(float4*)&Bs[m*36 + kq] = *(const float4*)(Fb + (j0+m)*64 + kc + kq);
        }
        __syncthreads();
        #pragma unroll
        for (int k0 = 0; k0 < 32; k0 += 8){
            unsigned ah[2][4], al[2][4];
            #pragma unroll
            for (int mt = 0; mt < 2; mt++){
                int row = wy*32 + mt*16;
                splt(As[(row+r)*36 + k0 + q],       ah[mt][0], al[mt][0]);
                splt(As[(row+r+8)*36 + k0 + q],     ah[mt][1], al[mt][1]);
                splt(As[(row+r)*36 + k0 + q + 4],   ah[mt][2], al[mt][2]);
                splt(As[(row+r+8)*36 + k0 + q + 4], ah[mt][3], al[mt][3]);
            }
            #pragma unroll
            for (int nt = 0; nt < 8; nt++){
                int col = wx*64 + nt*8;
                unsigned bh[2], bl[2];
                splt(Bs[(col+r)*36 + k0 + q],     bh[0], bl[0]);
                splt(Bs[(col+r)*36 + k0 + q + 4], bh[1], bl[1]);
                #pragma unroll
                for (int mt = 0; mt < 2; mt++){
                    mma8(acc[mt][nt], ah[mt], bh);
                    mma8(acc[mt][nt], ah[mt], bl);
                    mma8(acc[mt][nt], al[mt], bh);
                }
            }
        }
    }

    float si0[2], si1[2];
    #pragma unroll
    for (int mt = 0; mt < 2; mt++){
        int rowb = i0 + wy*32 + mt*16;
        si0[mt] = g_sq[b*NN + rowb + r];
        si1[mt] = g_sq[b*NN + rowb + r + 8];
        #pragma unroll
        for (int nt = 0; nt < 8; nt++){
            int colb = j0 + wx*64 + nt*8 + 2*q;
            float sj0 = g_sq[b*NN + colb], sj1 = g_sq[b*NN + colb + 1];
            float2 v0, v1;
            v0.x = si0[mt] + sj0 - 2.f*acc[mt][nt][0];
            v0.y = si0[mt] + sj1 - 2.f*acc[mt][nt][1];
            v1.x = si1[mt] + sj0 - 2.f*acc[mt][nt][2];
            v1.y = si1[mt] + sj1 - 2.f*acc[mt][nt][3];
            *(float2*)(g_d2 + (size_t)(b*NN + i0 + wy*32 + mt*16 + r)*NN + colb)     = v0;
            *(float2*)(g_d2 + (size_t)(b*NN + i0 + wy*32 + mt*16 + r + 8)*NN + colb) = v1;
        }
    }

    if (i0 != j0){
        float* Tb = SU;        // [64][132] = 8448 floats < 9216
        for (int h = 0; h < 2; h++){
            __syncthreads();
            if (wx == h){
                #pragma unroll
                for (int mt = 0; mt < 2; mt++){
                    int rowl = wy*32 + mt*16;
                    #pragma unroll
                    for (int nt = 0; nt < 8; nt++){
                        int coll = nt*8 + 2*q;
                        int colb = j0 + h*64 + coll;
                        float sj0 = g_sq[b*NN + colb], sj1 = g_sq[b*NN + colb + 1];
                        Tb[(coll    )*132 + rowl + r]     = si0[mt] + sj0 - 2.f*acc[mt][nt][0];
                        Tb[(coll + 1)*132 + rowl + r]     = si0[mt] + sj1 - 2.f*acc[mt][nt][1];
                        Tb[(coll    )*132 + rowl + r + 8] = si1[mt] + sj0 - 2.f*acc[mt][nt][2];
                        Tb[(coll + 1)*132 + rowl + r + 8] = si1[mt] + sj1 - 2.f*acc[mt][nt][3];
                    }
                }
            }
            __syncthreads();
            for (int i = t; i < 64*32; i += 256){
                int row = i >> 5, c4 = (i & 31)*4;
                float4 v = *(const float4*)&Tb[row*132 + c4];
                *(float4*)(g_d2 + (size_t)(b*NN + j0 + h*64 + row)*NN + i0 + c4) = v;
            }
        }
    }
}

// ---- fused kNN d=64 select (from g_d2) + conv2 layer-1 (independent) --------
__global__ void __launch_bounds__(256) k_selA2(const float* __restrict__ W,
                                               const float* __restrict__ bias){
    __shared__ float SU[9216];     // used only by convA2 branch
    int t = threadIdx.x;
    if (blockIdx.x < 8192){
        int warp = t >> 5, lane = t & 31;
        int node = blockIdx.x*8 + warp;
        const float* row = g_d2 + (size_t)node*NN;
        float v[16];
        #pragma unroll
        for (int u4 = 0; u4 < 4; u4++){
            float4 x = *(const float4*)(row + lane*16 + u4*4);
            v[u4*4+0] = x.x; v[u4*4+1] = x.y; v[u4*4+2] = x.z; v[u4*4+3] = x.w;
        }
        sel16<1>(v, lane, g_idx + (size_t)node*KNB);
    } else {
        float* Wd = SU;            // [32*128]
        float* Wb = SU + 4096;     // [32*128]
        float* Fs = SU + 8192;     // [16*64]
        int base = (blockIdx.x - 8192)*16;

        for (int idx = t; idx < 1024; idx += 256)
            Fs[idx] = g_x1[(size_t)base*64 + idx];

        int m  = t >> 4;
        int cg = (t & 15)*8;
        float a[8], cc[8];
        float4 bb0 = *(const float4*)(bias + cg);
        float4 bb1 = *(const float4*)(bias + cg + 4);
        a[0]=bb0.x; a[1]=bb0.y; a[2]=bb0.z; a[3]=bb0.w;
        a[4]=bb1.x; a[5]=bb1.y; a[6]=bb1.z; a[7]=bb1.w;
        #pragma unroll
        for (int q = 0; q < 8; q++) cc[q] = 0.f;

        for (int db = 0; db < 64; db += 32){
            __syncthreads();
            for (int idx = t; idx < 4096; idx += 256){
                int d = idx >> 7, c = idx & 127;
                float wt = W[(db + d)*128 + c];
                float wb = W[(64 + db + d)*128 + c];
                Wd[idx] = wt - wb;
                Wb[idx] = wb;
            }
            __syncthreads();
            #pragma unroll 4
            for (int d = 0; d < 32; d++){
                float v = Fs[m*64 + db + d];
                float4 w0 = *(const float4*)&Wd[d*128 + cg];
                float4 w1 = *(const float4*)&Wd[d*128 + cg + 4];
                float4 u0 = *(const float4*)&Wb[d*128 + cg];
                float4 u1 = *(const float4*)&Wb[d*128 + cg + 4];
                a[0] += v*w0.x; a[1] += v*w0.y; a[2] += v*w0.z; a[3] += v*w0.w;
                a[4] += v*w1.x; a[5] += v*w1.y; a[6] += v*w1.z; a[7] += v*w1.w;
                cc[0] += v*u0.x; cc[1] += v*u0.y; cc[2] += v*u0.z; cc[3] += v*u0.w;
                cc[4] += v*u1.x; cc[5] += v*u1.y; cc[6] += v*u1.z; cc[7] += v*u1.w;
            }
        }
        int node = base + m;
        float4* pa = (float4*)(g_A + (size_t)node*128 + cg);
        float4* pc = (float4*)(g_C + (size_t)node*128 + cg);
        pa[0] = make_float4(a[0],a[1],a[2],a[3]);
        pa[1] = make_float4(a[4],a[5],a[6],a[7]);
        pc[0] = make_float4(cc[0],cc[1],cc[2],cc[3]);
        pc[1] = make_float4(cc[4],cc[5],cc[6],cc[7]);
    }
}

// ---------------- conv1 edge layer-2: D^T = W^T @ h^T (tf32, exact) ----------
__global__ void k_edge64(const float* __restrict__ bias){
    int t = threadIdx.x, warp = t >> 5, lane = t & 31;
    int node = blockIdx.x*8 + warp;
    int b = node / NN;
    int r = lane >> 2, q = lane & 3;

    int j0 = b*NN + __ldg(g_idx + (size_t)node*KNB + r);
    int j1 = b*NN + __ldg(g_idx + (size_t)node*KNB + 8 + r);
    const float* Ai = g_A + (size_t)node*64;
    const float* C0 = g_C + (size_t)j0*64;
    const float* C1 = g_C + (size_t)j1*64;

    float acc[4][2][4];
    #pragma unroll
    for (int mt = 0; mt < 4; mt++)
        #pragma unroll
        for (int n = 0; n < 2; n++)
            #pragma unroll
            for (int i = 0; i < 4; i++) acc[mt][n][i] = 0.f;

    #pragma unroll
    for (int kb = 0; kb < 8; kb++){
        int c0 = kb*8 + q;
        float ai0 = __ldg(Ai + c0), ai1 = __ldg(Ai + c0 + 4);
        unsigned b0h[2], b0l[2], b1h[2], b1l[2];
        splt(leaky(ai0 + __ldg(C0 + c0)),     b0h[0], b0l[0]);
        splt(leaky(ai1 + __ldg(C0 + c0 + 4)), b0h[1], b0l[1]);
        splt(leaky(ai0 + __ldg(C1 + c0)),     b1h[0], b1l[0]);
        splt(leaky(ai1 + __ldg(C1 + c0 + 4)), b1h[1], b1l[1]);
        #pragma unroll
        for (int mt = 0; mt < 4; mt++){
            uint4 H = __ldg(&g_w1Ah[(mt*8 + kb)*32 + lane]);
            uint4 L = __ldg(&g_w1Al[(mt*8 + kb)*32 + lane]);
            mma8(acc[mt][0], (const unsigned*)&H, b0h);
            mma8(acc[mt][0], (const unsigned*)&H, b0l);
            mma8(acc[mt][0], (const unsigned*)&L, b0h);
            mma8(acc[mt][1], (const unsigned*)&H, b1h);
            mma8(acc[mt][1], (const unsigned*)&H, b1l);
            mma8(acc[mt][1], (const unsigned*)&L, b1h);
        }
    }

    float ssum = 0.f;
    #pragma unroll
    for (int mt = 0; mt < 4; mt++){
        float m0 = fmaxf(fmaxf(acc[mt][0][0], acc[mt][0][1]),
                         fmaxf(acc[mt][1][0], acc[mt][1][1]));
        float m1 = fmaxf(fmaxf(acc[mt][0][2], acc[mt][0][3]),
                         fmaxf(acc[mt][1][2], acc[mt][1][3]));
        m0 = fmaxf(m0, __shfl_xor_sync(0xffffffffu, m0, 1));
        m0 = fmaxf(m0, __shfl_xor_sync(0xffffffffu, m0, 2));
        m1 = fmaxf(m1, __shfl_xor_sync(0xffffffffu, m1, 1));
        m1 = fmaxf(m1, __shfl_xor_sync(0xffffffffu, m1, 2));
        if (q == 0){
            int ch = mt*16 + r;
            float v0 = leaky(m0 + __ldg(bias + ch));
            float v1 = leaky(m1 + __ldg(bias + ch + 8));
            g_x1[(size_t)node*64 + ch]     = v0;
            g_x1[(size_t)node*64 + ch + 8] = v1;
            ssum += v0*v0 + v1*v1;
        }
    }
    ssum += __shfl_xor_sync(0xffffffffu, ssum, 4);
    ssum += __shfl_xor_sync(0xffffffffu, ssum, 8);
    ssum += __shfl_xor_sync(0xffffffffu, ssum, 16);
    if (lane == 0) g_sq[node] = ssum;
}

// ------- conv2 edge layer-2 (bf16, 2-term: W-hi x (b-hi + b-lo)) -------------
__global__ void k_edge128(const float* __restrict__ bias){
    int t = threadIdx.x, warp = t >> 5, lane = t & 31;
    int node = blockIdx.x*8 + warp;
    int b = node / NN;
    int r = lane >> 2, q = lane & 3;

    int j0 = b*NN + __ldg(g_idx + (size_t)node*KNB + r);
    int j1 = b*NN + __ldg(g_idx + (size_t)node*KNB + 8 + r);
    const float* Ai = g_A + (size_t)node*128;
    const float* C0 = g_C + (size_t)j0*128;
    const float* C1 = g_C + (size_t)j1*128;

    float acc[4][2][4];
    #pragma unroll
    for (int mt = 0; mt < 4; mt++)
        #pragma unroll
        for (int n = 0; n < 2; n++)
            #pragma unroll
            for (int i = 0; i < 4; i++) acc[mt][n][i] = 0.f;

    #pragma unroll
    for (int kb = 0; kb < 8; kb++){
        int c0 = kb*16 + 2*q;
        float2 ai0 = *(const float2*)(Ai + c0);
        float2 ai1 = *(const float2*)(Ai + c0 + 8);
        float2 ca0 = *(const float2*)(C0 + c0);
        float2 ca1 = *(const float2*)(C0 + c0 + 8);
        float2 cb0 = *(const float2*)(C1 + c0);
        float2 cb1 = *(const float2*)(C1 + c0 + 8);
        unsigned b0h[2], b0l[2], b1h[2], b1l[2];
        split2(leaky(ai0.x + ca0.x), leaky(ai0.y + ca0.y), b0h[0], b0l[0]);
        split2(leaky(ai1.x + ca1.x), leaky(ai1.y + ca1.y), b0h[1], b0l[1]);
        split2(leaky(ai0.x + cb0.x), leaky(ai0.y + cb0.y), b1h[0], b1l[0]);
        split2(leaky(ai1.x + cb1.x), leaky(ai1.y + cb1.y), b1h[1], b1l[1]);
        #pragma unroll
        for (int mt = 0; mt < 4; mt++){
            uint4 H = __ldg(&g_w2Ah[(mt*8 + kb)*32 + lane]);
            mma16(acc[mt][0], (const unsigned*)&H, b0h);
            mma16(acc[mt][0], (const unsigned*)&H, b0l);
            mma16(acc[mt][1], (const unsigned*)&H, b1h);
            mma16(acc[mt][1], (const unsigned*)&H, b1l);
        }
    }

    #pragma unroll
    for (int mt = 0; mt < 4; mt++){
        float m0 = fmaxf(fmaxf(acc[mt][0][0], acc[mt][0][1]),
                         fmaxf(acc[mt][1][0], acc[mt][1][1]));
        float m1 = fmaxf(fmaxf(acc[mt][0][2], acc[mt][0][3]),
                         fmaxf(acc[mt][1][2], acc[mt][1][3]));
        m0 = fmaxf(m0, __shfl_xor_sync(0xffffffffu, m0, 1));
        m0 = fmaxf(m0, __shfl_xor_sync(0xffffffffu, m0, 2));
        m1 = fmaxf(m1, __shfl_xor_sync(0xffffffffu, m1, 1));
        m1 = fmaxf(m1, __shfl_xor_sync(0xffffffffu, m1, 2));
        if (q == 0){
            int ch = mt*16 + r;
            g_x2[(size_t)node*64 + ch]     = leaky(m0 + __ldg(bias + ch));
            g_x2[(size_t)node*64 + ch + 8] = leaky(m1 + __ldg(bias + ch + 8));
        }
    }
}

__device__ __forceinline__ float featval(int node, int d){
    if (d < 5)   return g_xx[node*5 + d];
    if (d < 69)  return g_x1[(size_t)node*64 + d - 5];
    if (d < 133) return g_x2[(size_t)node*64 + d - 69];
    return 0.f;
}

// ------- lin1 (bf16, 2-term: a-hi x (B-hi + B-lo)) + leaky -------------------
__global__ void k_lin1(const float* __restrict__ bl1){
    __shared__ unsigned CSh[64*76];
    int t = threadIdx.x, lane = t & 31, w = t >> 5;
    int base = blockIdx.x*64;
    for (int i = t; i < 64*72; i += 256){
        int m = i / 72, p = i - m*72;
        int node = base + m;
        float v0 = featval(node, 2*p);
        float v1 = featval(node, 2*p + 1);
        CSh[m*76 + p] = packbf(v0, v1);
    }
    __syncthreads();

    int r = lane >> 2, q = lane & 3;
    int n0 = w*64;
    for (int np = 0; np < 2; np++){
        float acc[4][4][4];
        #pragma unroll
        for (int mt = 0; mt < 4; mt++)
            #pragma unroll
            for (int nt = 0; nt < 4; nt++)
                #pragma unroll
                for (int i = 0; i < 4; i++) acc[mt][nt][i] = 0.f;

        for (int kb = 0; kb < 9; kb++){
            unsigned ah[4][4];
            #pragma unroll
            for (int mt = 0; mt < 4; mt++){
                int rb = mt*16;
                ah[mt][0] = CSh[(rb+r)*76 + kb*8 + q];
                ah[mt][1] = CSh[(rb+r+8)*76 + kb*8 + q];
                ah[mt][2] = CSh[(rb+r)*76 + kb*8 + 4 + q];
                ah[mt][3] = CSh[(rb+r+8)*76 + kb*8 + 4 + q];
            }
            #pragma unroll
            for (int nt = 0; nt < 4; nt++){
                uint4 wv = __ldg(&g_wl1pb[(kb*64 + w*8 + np*4 + nt)*32 + lane]);
                unsigned bh[2] = {wv.x, wv.y};
                unsigned bl[2] = {wv.z, wv.w};
                #pragma unroll
                for (int mt = 0; mt < 4; mt++){
                    mma16(acc[mt][nt], ah[mt], bh);
                    mma16(acc[mt][nt], ah[mt], bl);
                }
            }
        }
        #pragma unroll
        for (int mt = 0; mt < 4; mt++){
            #pragma unroll
            for (int nt = 0; nt < 4; nt++){
                int node = base + mt*16 + r;
                int col = n0 + (np*4 + nt)*8 + q*2;
                float b0 = __ldg(bl1 + col), b1 = __ldg(bl1 + col + 1);
                float2 u0, u1;
                u0.x = leaky(acc[mt][nt][0] + b0); u0.y = leaky(acc[mt][nt][1] + b1);
                u1.x = leaky(acc[mt][nt][2] + b0); u1.y = leaky(acc[mt][nt][3] + b1);
                *(float2*)(g_hs + (size_t)node*512 + col)     = u0;
                *(float2*)(g_hs + (size_t)(node+8)*512 + col) = u1;
            }
        }
    }
}

// ------- lin2 (bf16, 2-term) + max-pool --------------------------------------
__global__ void k_lin2(const float* __restrict__ bl2){
    __shared__ unsigned Ash[64*36];
    int t = threadIdx.x, lane = t & 31, w = t >> 5;
    int base = blockIdx.x*64;
    int g = base / NN;
    int r = lane >> 2, q = lane & 3;
    int n0 = w*32;

    float acc[4][4][4];
    #pragma unroll
    for (int mt = 0; mt < 4; mt++)
        #pragma unroll
        for (int nt = 0; nt < 4; nt++)
            #pragma unroll
            for (int i = 0; i < 4; i++) acc[mt][nt][i] = 0.f;

    for (int kc = 0; kc < 512; kc += 64){
        __syncthreads();
        for (int i = t; i < 1024; i += 256){
            int m = i >> 4, sub = i & 15;
            float4 v = *(const float4*)(g_hs + (size_t)(base + m)*512 + kc + sub*4);
            Ash[m*36 + sub*2]     = packbf(v.x, v.y);
            Ash[m*36 + sub*2 + 1] = packbf(v.z, v.w);
        }
        __syncthreads();
        #pragma unroll
        for (int kb = 0; kb < 4; kb++){
            unsigned ah[4][4];
            #pragma unroll
            for (int mt = 0; mt < 4; mt++){
                int rb = mt*16;
                ah[mt][0] = Ash[(rb+r)*36 + kb*8 + q];
                ah[mt][1] = Ash[(rb+r+8)*36 + kb*8 + q];
                ah[mt][2] = Ash[(rb+r)*36 + kb*8 + 4 + q];
                ah[mt][3] = Ash[(rb+r+8)*36 + kb*8 + 4 + q];
            }
            int kbg = (kc >> 4) + kb;
            #pragma unroll
            for (int nt = 0; nt < 4; nt++){
                uint4 wv = __ldg(&g_wl2pb[(kbg*32 + w*4 + nt)*32 + lane]);
                unsigned bh[2] = {wv.x, wv.y};
                unsigned bl[2] = {wv.z, wv.w};
                #pragma unroll
                for (int mt = 0; mt < 4; mt++){
                    mma16(acc[mt][nt], ah[mt], bh);
                    mma16(acc[mt][nt], ah[mt], bl);
                }
            }
        }
    }

    #pragma unroll
    for (int nt = 0; nt < 4; nt++){
        float m0 = -3.4e38f, m1 = -3.4e38f;
        #pragma unroll
        for (int mt = 0; mt < 4; mt++){
            m0 = fmaxf(m0, fmaxf(acc[mt][nt][0], acc[mt][nt][2]));
            m1 = fmaxf(m1, fmaxf(acc[mt][nt][1], acc[mt][nt][3]));
        }
        #pragma unroll
        for (int off = 4; off < 32; off <<= 1){
            m0 = fmaxf(m0, __shfl_xor_sync(0xffffffffu, m0, off));
            m1 = fmaxf(m1, __shfl_xor_sync(0xffffffffu, m1, off));
        }
        if (lane < 4){
            int col = n0 + nt*8 + lane*2;
            atomicMaxFloat(&g_pool[g*256 + col],     m0 + __ldg(bl2 + col));
            atomicMaxFloat(&g_pool[g*256 + col + 1], m1 + __ldg(bl2 + col + 1));
        }
    }
}

// ---------------- head: leaky -> 256x128 -> leaky -> 128x3 -------------------
__global__ void k_head(const float* __restrict__ wm1, const float* __restrict__ bm1,
                       const float* __restrict__ wm2, const float* __restrict__ bm2,
                       float* __restrict__ out){
    __shared__ float gs[256];
    __shared__ float ms[128];
    int b = blockIdx.x, t = threadIdx.x;
    for (int c = t; c < 256; c += 128) gs[c] = leaky(g_pool[b*256 + c]);
    __syncthreads();
    float acc = bm1[t];
    #pragma unroll 8
    for (int d = 0; d < 256; d++) acc += gs[d]*wm1[d*128 + t];
    ms[t] = leaky(acc);
    __syncthreads();
    if (t < 3){
        float o = bm2[t];
        #pragma unroll 8
        for (int d = 0; d < 128; d++) o += ms[d]*wm2[d*3 + t];
        out[b*3 + t] = o;
    }
}

// -----------------------------------------------------------------------------
extern "C" void kernel_launch(void* const* d_in, const int* in_sizes, int n_in,
                              void* d_out, int out_size){
    const float* x   = (const float*)d_in[0];
    const float* pos = (const float*)d_in[1];
    const float* tq  = (const float*)d_in[2];
    const float* w1a = (const float*)d_in[4];
    const float* b1a = (const float*)d_in[5];
    const float* w1b = (const float*)d_in[6];
    const float* b1b = (const float*)d_in[7];
    const float* w2a = (const float*)d_in[8];
    const float* b2a = (const float*)d_in[9];
    const float* w2b = (const float*)d_in[10];
    const float* b2b = (const float*)d_in[11];
    const float* wl1 = (const float*)d_in[12];
    const float* bl1 = (const float*)d_in[13];
    const float* wl2 = (const float*)d_in[14];
    const float* bl2 = (const float*)d_in[15];
    const float* wm1 = (const float*)d_in[16];
    const float* bm1 = (const float*)d_in[17];
    const float* wm2 = (const float*)d_in[18];
    const float* bm2 = (const float*)d_in[19];
    float* out = (float*)d_out;

    // prep (weights, pool) + build (xx, sq5) — independent, one launch
    k_prepbuild<<<208 + BN/256, 256>>>(w1b, w2b, wl1, wl2, x, pos, tq);

    // conv1: kNN5 || convA1 (independent given xx), then edge
    k_knn5A1<<<8192 + (BN*64)/256, 256>>>(w1a, b1a);
    k_edge64<<<BN/8, 256>>>(b1b);        // also emits g_sq

    // conv2: symmetric d2-GEMM, then (select || conv2 L1), then edge
    k_d2sym<<<BATCH*10, 256>>>();
    k_selA2<<<8192 + BN/16, 256>>>(w2a, b2a);
    k_edge128<<<BN/8, 256>>>(b2b);

    // lin1 -> g_hs, lin2 + fused pool, head
    k_lin1<<<BN/64, 256>>>(bl1);
    k_lin2<<<BN/64, 256>>>(bl2);
    k_head<<<BATCH, 128>>>(wm1, bm1, wm2, bm2, out);
}